// round 13
// baseline (speedup 1.0000x reference)
#include <cuda_runtime.h>
#include <cuda_bf16.h>
#include <math.h>

// ---------------- problem constants ----------------
#define L_TOK 10000
#define LP    10048
#define NC    157
#define Q     64
#define DM    512
#define DI    1024
#define DS    64
#define NH    16
#define HD    64
#define DXBC  1152
#define DPROJ 2192
#define NB    3

// ---------------- scratch ----------------
__device__ __align__(16) float g_hcur [(size_t)NB*LP*DM];
__device__ __align__(16) float g_zx   [(size_t)NB*LP*DPROJ];
__device__ __align__(16) float g_xs   [(size_t)NB*LP*DI];
__device__ __align__(16) float g_Bm   [(size_t)NB*LP*DS];
__device__ __align__(16) float g_Cm   [(size_t)NB*LP*DS];
__device__ __align__(16) float g_dtv  [(size_t)NB*LP*NH];
__device__ __align__(16) float g_cum  [(size_t)NB*NH*LP];
__device__ __align__(16) float g_y    [(size_t)NB*LP*DI];
__device__ __align__(16) float g_schunk[(size_t)NB*NH*NC*DS*HD];
__device__ __align__(16) float g_sbef  [(size_t)NB*NH*NC*DS*HD];
__device__ __align__(16) float g_hn   [(size_t)NB*L_TOK*DM];
__device__ __align__(16) float g_s1   [(size_t)NB*L_TOK*128];
__device__ float g_scoreb[NB*L_TOK];
__device__ float g_wts   [NB*L_TOK];
__device__ float g_pooled[DM];

// split-bf16 (uint2 = {hi bf16x2, lo bf16x2}) for W-side + fc1/attn A-side
__device__ __align__(16) uint2 g_xS   [(size_t)L_TOK*512];
__device__ __align__(16) uint2 g_fc1wS[(size_t)DM*512];
__device__ __align__(16) uint2 g_ipwS [(size_t)6*DPROJ*256];
__device__ __align__(16) uint2 g_opwS [(size_t)6*DM*512];
__device__ __align__(16) uint2 g_aw1S [(size_t)128*256];
__device__ __align__(16) uint2 g_hnS  [(size_t)NB*L_TOK*256];
// plain-bf16 packed (unsigned = bf16x2) activation buffers
__device__ __align__(16) unsigned g_hcurB[(size_t)NB*LP*256];
__device__ __align__(16) unsigned g_yB   [(size_t)NB*LP*512];

// ---------------- helpers ----------------
__device__ __forceinline__ float bsum(float v) {
    __shared__ float sh[32];
    int lane = threadIdx.x & 31, w = threadIdx.x >> 5;
    #pragma unroll
    for (int o = 16; o > 0; o >>= 1) v += __shfl_xor_sync(0xffffffffu, v, o);
    if (lane == 0) sh[w] = v;
    __syncthreads();
    int nw = blockDim.x >> 5;
    v = (threadIdx.x < nw) ? sh[threadIdx.x] : 0.f;
    if (w == 0) {
        #pragma unroll
        for (int o = 16; o > 0; o >>= 1) v += __shfl_xor_sync(0xffffffffu, v, o);
        if (threadIdx.x == 0) sh[0] = v;
    }
    __syncthreads();
    float r = sh[0];
    __syncthreads();
    return r;
}

__device__ __forceinline__ unsigned pack_bf16(float f0, float f1) {
    unsigned r;
    asm("cvt.rn.bf16x2.f32 %0, %1, %2;" : "=r"(r) : "f"(f1), "f"(f0));
    return r;
}

__device__ __forceinline__ uint2 split_bf16_pair(float f0, float f1) {
    unsigned hp, lp;
    asm("cvt.rn.bf16x2.f32 %0, %1, %2;" : "=r"(hp) : "f"(f1), "f"(f0));
    __nv_bfloat162 h = *reinterpret_cast<__nv_bfloat162*>(&hp);
    float r0 = f0 - __bfloat162float(h.x);
    float r1 = f1 - __bfloat162float(h.y);
    asm("cvt.rn.bf16x2.f32 %0, %1, %2;" : "=r"(lp) : "f"(r1), "f"(r0));
    uint2 q; q.x = hp; q.y = lp;
    return q;
}

__global__ void k_split(const float* __restrict__ in, uint2* __restrict__ out, long long npairs) {
    long long i = (long long)blockIdx.x * 256 + threadIdx.x;
    if (i >= npairs) return;
    float2 v = ((const float2*)in)[i];
    out[i] = split_bf16_pair(v.x, v.y);
}

// merged split of x, fc1_w, in_proj_w (single launch)
#define NPX ((long long)L_TOK * 512)
#define NPF ((long long)DM * 512)
#define NPI ((long long)6 * DPROJ * 256)
__global__ void k_split_all(const float* __restrict__ x, const float* __restrict__ fw,
                            const float* __restrict__ iw) {
    long long i = (long long)blockIdx.x * 256 + threadIdx.x;
    const float* src; uint2* dst; long long off;
    if (i < NPX) { src = x; dst = g_xS; off = i; }
    else if (i < NPX + NPF) { src = fw; dst = g_fc1wS; off = i - NPX; }
    else if (i < NPX + NPF + NPI) { src = iw; dst = g_ipwS; off = i - NPX - NPF; }
    else return;
    float2 v = ((const float2*)src)[off];
    dst[off] = split_bf16_pair(v.x, v.y);
}

__device__ __forceinline__ void mma16(float c[4], const unsigned a[4], const unsigned b[2]) {
    asm volatile(
        "mma.sync.aligned.m16n8k16.row.col.f32.bf16.bf16.f32 "
        "{%0,%1,%2,%3},{%4,%5,%6,%7},{%8,%9},{%0,%1,%2,%3};"
        : "+f"(c[0]), "+f"(c[1]), "+f"(c[2]), "+f"(c[3])
        : "r"(a[0]), "r"(a[1]), "r"(a[2]), "r"(a[3]), "r"(b[0]), "r"(b[1]));
}

__device__ __forceinline__ void cp8(unsigned dst, const void* src, bool pred) {
    int sz = pred ? 8 : 0;
    asm volatile("cp.async.ca.shared.global [%0], [%1], 8, %2;" :: "r"(dst), "l"(src), "r"(sz));
}
__device__ __forceinline__ void cp4(unsigned dst, const void* src, bool pred) {
    int sz = pred ? 4 : 0;
    asm volatile("cp.async.ca.shared.global [%0], [%1], 4, %2;" :: "r"(dst), "l"(src), "r"(sz));
}

// ---------------- tgemm: 3xBF16 split both sides (fc1, attn1) — R8-proven ----------------
// op: 0=store, 1=C+=, 2=relu(v+bias) (+bf16 aux), 3=tanh(v+bias)
#define STAGES 4
#define S4 130
#define TG_SMEM (STAGES * 4 * S4 * 16 * 2)

__global__ __launch_bounds__(256, 2) void tgemm(
    const uint2* __restrict__ A, long long sA,
    const uint2* __restrict__ W, long long sW,
    const float* __restrict__ bias,
    float* __restrict__ C, long long sC,
    unsigned* __restrict__ Caux,
    int M, int N, int Kp, int op, int joff)
{
    extern __shared__ uint4 sm4[];
    uint4* As = sm4;
    uint4* Ws = sm4 + STAGES * 4 * S4;

    int z = blockIdx.z;
    A += (long long)z * sA;
    C += (long long)z * sC;
    W += (long long)(2 * z + joff) * sW;
    if (Caux) Caux += (long long)z * (sC >> 1);

    int tid = threadIdx.x;
    int warp = tid >> 5, lane = tid & 31;
    int wm = warp & 3, wn = warp >> 2;
    int g = lane >> 2, tig = lane & 3;
    int row0 = blockIdx.y * 128, col0 = blockIdx.x * 128;

    int ar = tid >> 1, half = tid & 1;
    bool aok = (row0 + ar) < M;
    bool wok = (col0 + ar) < N;
    const uint2* Ag = A + (long long)(row0 + ar) * Kp + half * 4;
    const uint2* Wg = W + (long long)(col0 + ar) * Kp + half * 4;
    unsigned aSm = (unsigned)__cvta_generic_to_shared(As);
    unsigned wSm = (unsigned)__cvta_generic_to_shared(Ws);

    float c[2][8][4];
    #pragma unroll
    for (int mt = 0; mt < 2; mt++)
        #pragma unroll
        for (int nt = 0; nt < 8; nt++)
            #pragma unroll
            for (int q = 0; q < 4; q++) c[mt][nt][q] = 0.f;

    int nK = Kp >> 3;

    #define ISSUE(kt, slot) do { \
        const uint2* _Ap = Ag + (kt) * 8; \
        const uint2* _Wp = Wg + (kt) * 8; \
        _Pragma("unroll") \
        for (int i = 0; i < 4; i++) { \
            unsigned off = (unsigned)((((slot) * 4 + i) * S4 + ar) * 16 + half * 8); \
            cp8(aSm + off, _Ap + i, aok); \
            cp8(wSm + off, _Wp + i, wok); \
        } \
    } while (0)

    #pragma unroll
    for (int s = 0; s < STAGES - 1; s++) {
        if (s < nK) ISSUE(s, s);
        asm volatile("cp.async.commit_group;");
    }

    for (int kt = 0; kt < nK; kt++) {
        asm volatile("cp.async.wait_group %0;" :: "n"(STAGES - 2));
        __syncthreads();

        int slot = kt & 3;
        const uint4* Ab = As + slot * 4 * S4;
        const uint4* Wb = Ws + slot * 4 * S4;

        uint4 fa[2][2];
        #pragma unroll
        for (int mt = 0; mt < 2; mt++) {
            int m0 = wm * 32 + mt * 16;
            fa[mt][0] = Ab[tig * S4 + m0 + g];
            fa[mt][1] = Ab[tig * S4 + m0 + g + 8];
        }
        unsigned ahi[2][4], alo[2][4];
        #pragma unroll
        for (int mt = 0; mt < 2; mt++) {
            ahi[mt][0] = fa[mt][0].x; ahi[mt][1] = fa[mt][1].x;
            ahi[mt][2] = fa[mt][0].z; ahi[mt][3] = fa[mt][1].z;
            alo[mt][0] = fa[mt][0].y; alo[mt][1] = fa[mt][1].y;
            alo[mt][2] = fa[mt][0].w; alo[mt][3] = fa[mt][1].w;
        }
        #pragma unroll
        for (int nt = 0; nt < 8; nt++) {
            int n0 = wn * 64 + nt * 8;
            uint4 fb = Wb[tig * S4 + n0 + g];
            unsigned bhi[2] = {fb.x, fb.z};
            unsigned blo[2] = {fb.y, fb.w};
            #pragma unroll
            for (int mt = 0; mt < 2; mt++) {
                mma16(c[mt][nt], alo[mt], bhi);
                mma16(c[mt][nt], ahi[mt], blo);
                mma16(c[mt][nt], ahi[mt], bhi);
            }
        }

        int pre = kt + STAGES - 1;
        if (pre < nK) ISSUE(pre, pre & 3);
        asm volatile("cp.async.commit_group;");
    }
    asm volatile("cp.async.wait_all;");

    #pragma unroll
    for (int mt = 0; mt < 2; mt++) {
        #pragma unroll
        for (int nt = 0; nt < 8; nt++) {
            int cc = col0 + wn * 64 + nt * 8 + 2 * tig;
            if (cc >= N) continue;
            #pragma unroll
            for (int hf = 0; hf < 2; hf++) {
                int r = row0 + wm * 32 + mt * 16 + g + hf * 8;
                if (r >= M) continue;
                float v0 = c[mt][nt][hf * 2 + 0];
                float v1 = c[mt][nt][hf * 2 + 1];
                long long ci = (long long)r * N + cc;
                if (op == 0) {
                    *(float2*)&C[ci] = make_float2(v0, v1);
                } else if (op == 1) {
                    float2 o = *(float2*)&C[ci];
                    o.x += v0; o.y += v1;
                    *(float2*)&C[ci] = o;
                    if (Caux) Caux[ci >> 1] = pack_bf16(o.x, o.y);
                } else if (op == 2) {
                    v0 = fmaxf(v0 + bias[cc], 0.f);
                    v1 = fmaxf(v1 + bias[cc + 1], 0.f);
                    *(float2*)&C[ci] = make_float2(v0, v1);
                    if (Caux) Caux[ci >> 1] = pack_bf16(v0, v1);
                } else {
                    v0 += bias[cc]; v1 += bias[cc + 1];
                    *(float2*)&C[ci] = make_float2(tanhf(v0), tanhf(v1));
                }
            }
        }
    }
    #undef ISSUE
}

// ---------------- tgemm2: bf16-A x split-W; warp grid 2m x 4n (W redundancy 4x -> 2x) ----------------
// op: 0=store, 1=C+= (+bf16 aux)
#define SA2 130
#define NSLOT 3
#define TG2_SMEM (NSLOT * 8 * SA2 * 8 + NSLOT * 8 * S4 * 16)

__global__ __launch_bounds__(256, 2) void tgemm2(
    const unsigned* __restrict__ A, long long sA,
    const uint2* __restrict__ W, long long sW,
    float* __restrict__ C, long long sC,
    unsigned* __restrict__ Caux,
    int M, int N, int Kp, int op, int joff)
{
    extern __shared__ uint4 sm4[];
    uint2* As2 = (uint2*)sm4;
    uint4* Ws = (uint4*)((char*)sm4 + NSLOT * 8 * SA2 * 8);

    int z = blockIdx.z;
    A += (long long)z * sA;
    C += (long long)z * sC;
    W += (long long)(2 * z + joff) * sW;
    if (Caux) Caux += (long long)z * (sC >> 1);

    int tid = threadIdx.x;
    int warp = tid >> 5, lane = tid & 31;
    int wm = warp & 1, wn = warp >> 1;          // 2 m-warps x 4 n-warps
    int g = lane >> 2, tig = lane & 3;
    int row0 = blockIdx.y * 128, col0 = blockIdx.x * 128;

    int ar = tid >> 1, half = tid & 1;
    bool aok = (row0 + ar) < M;
    bool wok = (col0 + ar) < N;
    const unsigned* Ag = A + (long long)(row0 + ar) * Kp + half * 4;
    const uint2* Wg = W + (long long)(col0 + ar) * Kp + half * 4;
    unsigned aSm = (unsigned)__cvta_generic_to_shared(As2);
    unsigned wSm = (unsigned)__cvta_generic_to_shared(Ws);

    float c[4][4][4];
    #pragma unroll
    for (int mt = 0; mt < 4; mt++)
        #pragma unroll
        for (int nt = 0; nt < 4; nt++)
            #pragma unroll
            for (int q = 0; q < 4; q++) c[mt][nt][q] = 0.f;

    int nG = Kp >> 4;

    #define ISSUEG(gi, s) do { \
        _Pragma("unroll") \
        for (int u = 0; u < 2; u++) { \
            const unsigned* _Ap = Ag + ((gi) * 2 + u) * 8; \
            const uint2* _Wp = Wg + ((gi) * 2 + u) * 8; \
            _Pragma("unroll") \
            for (int i = 0; i < 4; i++) { \
                cp4(aSm + (unsigned)((((s) * 8 + u * 4 + i) * SA2 + ar) * 8 + half * 4), _Ap + i, aok); \
                cp8(wSm + (unsigned)((((s) * 8 + u * 4 + i) * S4 + ar) * 16 + half * 8), _Wp + i, wok); \
            } \
        } \
    } while (0)

    ISSUEG(0, 0);
    asm volatile("cp.async.commit_group;");
    if (1 < nG) ISSUEG(1, 1);
    asm volatile("cp.async.commit_group;");

    int sc = 0, si = 2;
    for (int gi = 0; gi < nG; gi++) {
        asm volatile("cp.async.wait_group 1;");
        __syncthreads();

        #pragma unroll
        for (int u = 0; u < 2; u++) {
            const uint2* Ab = As2 + (sc * 8 + u * 4) * SA2;
            const uint4* Wb = Ws + (sc * 8 + u * 4) * S4;

            unsigned a[4][4];
            #pragma unroll
            for (int mt = 0; mt < 4; mt++) {
                int m0 = wm * 64 + mt * 16;
                uint2 q0 = Ab[tig * SA2 + m0 + g];
                uint2 q1 = Ab[tig * SA2 + m0 + g + 8];
                a[mt][0] = q0.x; a[mt][1] = q1.x;
                a[mt][2] = q0.y; a[mt][3] = q1.y;
            }
            #pragma unroll
            for (int nt = 0; nt < 4; nt++) {
                int n0 = wn * 32 + nt * 8;
                uint4 fb = Wb[tig * S4 + n0 + g];
                unsigned bhi[2] = {fb.x, fb.z};
                unsigned blo[2] = {fb.y, fb.w};
                #pragma unroll
                for (int mt = 0; mt < 4; mt++) {
                    mma16(c[mt][nt], a[mt], blo);
                    mma16(c[mt][nt], a[mt], bhi);
                }
            }
        }

        int pre = gi + 2;
        if (pre < nG) ISSUEG(pre, si);
        asm volatile("cp.async.commit_group;");
        sc++; if (sc == NSLOT) sc = 0;
        si++; if (si == NSLOT) si = 0;
    }
    asm volatile("cp.async.wait_all;");

    #pragma unroll
    for (int mt = 0; mt < 4; mt++) {
        #pragma unroll
        for (int nt = 0; nt < 4; nt++) {
            int cc = col0 + wn * 32 + nt * 8 + 2 * tig;
            if (cc >= N) continue;
            #pragma unroll
            for (int hf = 0; hf < 2; hf++) {
                int r = row0 + wm * 64 + mt * 16 + g + hf * 8;
                if (r >= M) continue;
                float v0 = c[mt][nt][hf * 2 + 0];
                float v1 = c[mt][nt][hf * 2 + 1];
                long long ci = (long long)r * N + cc;
                if (op == 0) {
                    *(float2*)&C[ci] = make_float2(v0, v1);
                } else {
                    float2 o = *(float2*)&C[ci];
                    o.x += v0; o.y += v1;
                    *(float2*)&C[ci] = o;
                    if (Caux) Caux[ci >> 1] = pack_bf16(o.x, o.y);
                }
            }
        }
    }
    #undef ISSUEG
}

// ---------------- branch prep (coalesced) + pad-row zeroing ----------------
__global__ void k_prep2() {
    long long i = (long long)blockIdx.x * 256 + threadIdx.x;
    const long long mainN = (long long)L_TOK * 128;
    if (i < mainN) {
        int t = (int)(i >> 7), q = (int)(i & 127);
        float4 v = *((const float4*)g_hcur + (long long)t * 128 + q);
        int d0 = q * 4, p = q * 2;
        *(float4*)&g_hcur[(long long)LP * DM + (long long)t * DM + (508 - d0)] =
            make_float4(v.w, v.z, v.y, v.x);
        g_hcurB[(long long)LP * 256 + (long long)t * 256 + (255 - p)] = pack_bf16(v.y, v.x);
        g_hcurB[(long long)LP * 256 + (long long)t * 256 + (254 - p)] = pack_bf16(v.w, v.z);
        int tt = (t % 100) * 100 + t / 100;
        *(float4*)&g_hcur[2LL * LP * DM + (long long)tt * DM + d0] = v;
        g_hcurB[2LL * LP * 256 + (long long)tt * 256 + p]     = pack_bf16(v.x, v.y);
        g_hcurB[2LL * LP * 256 + (long long)tt * 256 + p + 1] = pack_bf16(v.z, v.w);
        return;
    }
    long long j = i - mainN;
    if (j >= (long long)NB * (LP - L_TOK) * 128) return;
    int b = (int)(j / ((LP - L_TOK) * 128));
    int rem = (int)(j % ((LP - L_TOK) * 128));
    int t = L_TOK + rem / 128, q = rem % 128;
    *(float4*)&g_hcur[((long long)b * LP + t) * DM + q * 4] = make_float4(0.f, 0.f, 0.f, 0.f);
    g_hcurB[((long long)b * LP + t) * 256 + q * 2]     = 0u;
    g_hcurB[((long long)b * LP + t) * 256 + q * 2 + 1] = 0u;
}

// ---------------- fused conv + silu + dt + cumsum ----------------
__global__ __launch_bounds__(256) void k_convfused(
    const float* __restrict__ cw, const float* __restrict__ cb,
    const float* __restrict__ dt_bias, const float* __restrict__ A_log, int j)
{
    __shared__ float av_s[NH * 64];
    int c = blockIdx.x, b = blockIdx.y;
    int lidx = 2 * b + j;
    int tid = threadIdx.x;
    const float* zbase = g_zx + (long long)b * LP * DPROJ;
    int gt0 = c * Q;

    for (int cc = tid; cc < DXBC; cc += 256) {
        const float* col = zbase + DI + cc;
        const float* wp = cw + (long long)(lidx * DXBC + cc) * 4;
        float w0 = wp[0], w1 = wp[1], w2 = wp[2], w3 = wp[3];
        float bia = cb[lidx * DXBC + cc];
        float h3 = (gt0 - 3 >= 0) ? col[(long long)(gt0 - 3) * DPROJ] : 0.f;
        float h2 = (gt0 - 2 >= 0) ? col[(long long)(gt0 - 2) * DPROJ] : 0.f;
        float h1 = (gt0 - 1 >= 0) ? col[(long long)(gt0 - 1) * DPROJ] : 0.f;
        #pragma unroll 4
        for (int t = 0; t < Q; t++) {
            int gt = gt0 + t;
            float cur = col[(long long)gt * DPROJ];
            float a = bia + w0 * h3 + w1 * h2 + w2 * h1 + w3 * cur;
            float v = a / (1.f + __expf(-a));
            if (gt >= L_TOK) v = 0.f;
            long long tb = (long long)b * LP + gt;
            if (cc < DI)            g_xs[tb * DI + cc] = v;
            else if (cc < DI + DS)  g_Bm[tb * DS + (cc - DI)] = v;
            else                    g_Cm[tb * DS + (cc - DI - DS)] = v;
            h3 = h2; h2 = h1; h1 = cur;
        }
    }

    #pragma unroll
    for (int k = 0; k < 4; k++) {
        int idx = tid + k * 256;
        int h = idx & 15, t = idx >> 4;
        int gt = gt0 + t;
        float draw = zbase[(long long)gt * DPROJ + DI + DXBC + h];
        float xv = draw + dt_bias[lidx * NH + h];
        float sp = (xv > 20.f) ? xv : log1pf(expf(xv));
        if (gt >= L_TOK) sp = 0.f;
        g_dtv[((long long)b * LP + gt) * NH + h] = sp;
        float Ah = -expf(A_log[lidx * NH + h]);
        av_s[h * 64 + t] = sp * Ah;
    }
    __syncthreads();

    int warp = tid >> 5, lane = tid & 31;
    #pragma unroll
    for (int hh = 0; hh < 2; hh++) {
        int h = warp * 2 + hh;
        float x1 = av_s[h * 64 + lane];
        float x2 = av_s[h * 64 + 32 + lane];
        #pragma unroll
        for (int o = 1; o < 32; o <<= 1) { float yv = __shfl_up_sync(0xffffffffu, x1, o); if (lane >= o) x1 += yv; }
        #pragma unroll
        for (int o = 1; o < 32; o <<= 1) { float yv = __shfl_up_sync(0xffffffffu, x2, o); if (lane >= o) x2 += yv; }
        float tot1 = __shfl_sync(0xffffffffu, x1, 31);
        x2 += tot1;
        long long base = (long long)(b * NH + h) * LP + (long long)c * Q;
        g_cum[base + lane] = x1;
        g_cum[base + 32 + lane] = x2;
    }
}

// ---------------- intra-chunk (tensor-core) ----------------
#define SMEM_INTRA_MMA (4096 * 16 + 512)
__global__ __launch_bounds__(256) void k_intra_mma() {
    extern __shared__ uint4 smu[];
    uint4* sC  = smu;
    uint4* sB  = smu + 1024;
    uint4* sUT = smu + 2048;
    uint4* sBw = smu + 3072;
    float* scum = (float*)(smu + 4096);
    float* sdt  = scum + 64;

    int c = blockIdx.x, h = blockIdx.y, b = blockIdx.z;
    long long rowb = (long long)b * LP + (long long)c * Q;
    int tid = threadIdx.x;

    if (tid < 64) {
        scum[tid] = g_cum[(long long)(b * NH + h) * LP + (long long)c * Q + tid];
        sdt[tid]  = g_dtv[(rowb + tid) * NH + h];
    }
    __syncthreads();
    float T = scum[63];

    for (int i = tid; i < 1024; i += 256) {
        int slot = i >> 6, row = i & 63;
        int ks = slot >> 2, tg = slot & 3;
        int k0 = ks * 16 + tg * 2;
        long long rb = rowb + row;
        float2 c0 = *(const float2*)&g_Cm[rb * DS + k0];
        float2 c1 = *(const float2*)&g_Cm[rb * DS + k0 + 8];
        uint2 ch0 = split_bf16_pair(c0.x, c0.y);
        uint2 ch1 = split_bf16_pair(c1.x, c1.y);
        sC[i] = make_uint4(ch0.x, ch0.y, ch1.x, ch1.y);
        float2 b0 = *(const float2*)&g_Bm[rb * DS + k0];
        float2 b1 = *(const float2*)&g_Bm[rb * DS + k0 + 8];
        uint2 bh0 = split_bf16_pair(b0.x, b0.y);
        uint2 bh1 = split_bf16_pair(b1.x, b1.y);
        sB[i] = make_uint4(bh0.x, bh0.y, bh1.x, bh1.y);
        float u0 = sdt[k0]     * g_xs[(rowb + k0)     * DI + h * HD + row];
        float u1 = sdt[k0 + 1] * g_xs[(rowb + k0 + 1) * DI + h * HD + row];
        float u2 = sdt[k0 + 8] * g_xs[(rowb + k0 + 8) * DI + h * HD + row];
        float u3 = sdt[k0 + 9] * g_xs[(rowb + k0 + 9) * DI + h * HD + row];
        uint2 uh0 = split_bf16_pair(u0, u1);
        uint2 uh1 = split_bf16_pair(u2, u3);
        sUT[i] = make_uint4(uh0.x, uh0.y, uh1.x, uh1.y);
        float bw0 = g_Bm[(rowb + k0)     * DS + row] * __expf(T - scum[k0]);
        float bw1 = g_Bm[(rowb + k0 + 1) * DS + row] * __expf(T - scum[k0 + 1]);
        float bw2 = g_Bm[(rowb + k0 + 8) * DS + row] * __expf(T - scum[k0 + 8]);
        float bw3 = g_Bm[(rowb + k0 + 9) * DS + row] * __expf(T - scum[k0 + 9]);
        uint2 wh0 = split_bf16_pair(bw0, bw1);
        uint2 wh1 = split_bf16_pair(bw2, bw3);
        sBw[i] = make_uint4(wh0.x, wh0.y, wh1.x, wh1.y);
    }
    __syncthreads();

    int warp = tid >> 5, lane = tid & 31;
    int g = lane >> 2, tig = lane & 3;
    int r0 = (warp & 3) * 16, cbn = (warp >> 2) * 32;

    float accP[4][4];
    #pragma unroll
    for (int nt = 0; nt < 4; nt++)
        #pragma unroll
        for (int q = 0; q < 4; q++) accP[nt][q] = 0.f;
    #pragma unroll
    for (int ks = 0; ks < 4; ks++) {
        uint4 fa0 = sC[(ks * 4 + tig) * 64 + r0 + g];
        uint4 fa1 = sC[(ks * 4 + tig) * 64 + r0 + g + 8];
        unsigned ahi[4] = {fa0.x, fa1.x, fa0.z, fa1.z};
        unsigned alo[4] = {fa0.y, fa1.y, fa0.w, fa1.w};
        #pragma unroll
        for (int nt = 0; nt < 4; nt++) {
            uint4 fb = sB[(ks * 4 + tig) * 64 + cbn + nt * 8 + g];
            unsigned bhi[2] = {fb.x, fb.z}, blo[2] = {fb.y, fb.w};
            mma16(accP[nt], alo, bhi);
            mma16(accP[nt], ahi, blo);
            mma16(accP[nt], ahi, bhi);
        }
    }
    __syncthreads();

    uint2* sP2 = (uint2*)sB;
    #pragma unroll
    for (int nt = 0; nt < 4; nt++) {
        int scol = cbn + nt * 8 + 2 * tig;
        int Pp = scol >> 1;
        int ksp = Pp >> 3, tslot = Pp & 3, halfp = (Pp >> 2) & 1;
        #pragma unroll
        for (int hf = 0; hf < 2; hf++) {
            int t = r0 + g + hf * 8;
            float v0 = accP[nt][hf * 2], v1 = accP[nt][hf * 2 + 1];
            v0 = (scol     <= t) ? v0 * __expf(scum[t] - scum[scol])     : 0.f;
            v1 = (scol + 1 <= t) ? v1 * __expf(scum[t] - scum[scol + 1]) : 0.f;
            sP2[((ksp * 4 + tslot) * 64 + t) * 2 + halfp] = split_bf16_pair(v0, v1);
        }
    }
    __syncthreads();

    float accY[4][4], accS[4][4];
    #pragma unroll
    for (int nt = 0; nt < 4; nt++)
        #pragma unroll
        for (int q = 0; q < 4; q++) { accY[nt][q] = 0.f; accS[nt][q] = 0.f; }
    uint4* sP = sB;
    #pragma unroll
    for (int ks = 0; ks < 4; ks++) {
        uint4 fp0 = sP[(ks * 4 + tig) * 64 + r0 + g];
        uint4 fp1 = sP[(ks * 4 + tig) * 64 + r0 + g + 8];
        unsigned phi[4] = {fp0.x, fp1.x, fp0.z, fp1.z};
        unsigned plo[4] = {fp0.y, fp1.y, fp0.w, fp1.w};
        uint4 fw0 = sBw[(ks * 4 + tig) * 64 + r0 + g];
        uint4 fw1 = sBw[(ks * 4 + tig) * 64 + r0 + g + 8];
        unsigned whi[4] = {fw0.x, fw1.x, fw0.z, fw1.z};
        unsigned wlo[4] = {fw0.y, fw1.y, fw0.w, fw1.w};
        #pragma unroll
        for (int nt = 0; nt < 4; nt++) {
            uint4 fb = sUT[(ks * 4 + tig) * 64 + cbn + nt * 8 + g];
            unsigned bhi[2] = {fb.x, fb.z}, blo[2] = {fb.y, fb.w};
            mma16(accY[nt], plo, bhi); mma16(accY[nt], phi, blo); mma16(accY[nt], phi, bhi);
            mma16(accS[nt], wlo, bhi); mma16(accS[nt], whi, blo); mma16(accS[nt], whi, bhi);
        }
    }

    long long sbase = ((long long)(b * NH + h) * NC + c) * 4096;
    #pragma unroll
    for (int nt = 0; nt < 4; nt++) {
        int p = cbn + nt * 8 + 2 * tig;
        #pragma unroll
        for (int hf = 0; hf < 2; hf++) {
            int r = r0 + g + hf * 8;
            *(float2*)&g_y[(rowb + r) * DI + h * HD + p] =
                make_float2(accY[nt][hf * 2], accY[nt][hf * 2 + 1]);
            *(float2*)&g_schunk[sbase + r * 64 + p] =
                make_float2(accS[nt][hf * 2], accS[nt][hf * 2 + 1]);
        }
    }
}

// ---------------- chunk-state recurrence (4-way split, prefetched) ----------------
__global__ __launch_bounds__(256) void k_rec() {
    int bh = blockIdx.x;
    int qd = blockIdx.y;
    int tid = threadIdx.x;
    int off = qd * 1024 + tid;
    float S[4], v[4], nv[4];
    #pragma unroll
    for (int i = 0; i < 4; i++) S[i] = 0.f;
    const float* cumrow = g_cum + (long long)bh * LP;
    long long base = (long long)bh * NC * 4096;
    #pragma unroll
    for (int i = 0; i < 4; i++) v[i] = g_schunk[base + off + i * 256];
    for (int c = 0; c < NC; c++) {
        float e = __expf(cumrow[c * Q + 63]);
        if (c + 1 < NC) {
            long long nb = base + 4096;
            #pragma unroll
            for (int i = 0; i < 4; i++) nv[i] = g_schunk[nb + off + i * 256];
        }
        #pragma unroll
        for (int i = 0; i < 4; i++) {
            g_sbef[base + off + i * 256] = S[i];
            S[i] = e * S[i] + v[i];
            v[i] = nv[i];
        }
        base += 4096;
    }
}

// ---------------- inter-chunk (tensor-core) ----------------
__global__ __launch_bounds__(256) void k_inter_mma(const float* __restrict__ Dh, int j) {
    __shared__ uint4 sC[1024];
    __shared__ uint4 sST[1024];
    __shared__ float scum[64];

    int c = blockIdx.x, h = blockIdx.y, b = blockIdx.z;
    long long rowb = (long long)b * LP + (long long)c * Q;
    long long sbase = ((long long)(b * NH + h) * NC + c) * 4096;
    int tid = threadIdx.x;

    if (tid < 64)
        scum[tid] = g_cum[(long long)(b * NH + h) * LP + (long long)c * Q + tid];

    for (int i = tid; i < 1024; i += 256) {
        int slot = i >> 6, row = i & 63;
        int ks = slot >> 2, tg = slot & 3;
        int k0 = ks * 16 + tg * 2;
        long long rb = rowb + row;
        float2 c0 = *(const float2*)&g_Cm[rb * DS + k0];
        float2 c1 = *(const float2*)&g_Cm[rb * DS + k0 + 8];
        uint2 ch0 = split_bf16_pair(c0.x, c0.y);
        uint2 ch1 = split_bf16_pair(c1.x, c1.y);
        sC[i] = make_uint4(ch0.x, ch0.y, ch1.x, ch1.y);
        float s0 = g_sbef[sbase + (k0)     * 64 + row];
        float s1 = g_sbef[sbase + (k0 + 1) * 64 + row];
        float s2 = g_sbef[sbase + (k0 + 8) * 64 + row];
        float s3 = g_sbef[sbase + (k0 + 9) * 64 + row];
        uint2 sh0 = split_bf16_pair(s0, s1);
        uint2 sh1 = split_bf16_pair(s2, s3);
        sST[i] = make_uint4(sh0.x, sh0.y, sh1.x, sh1.y);
    }
    __syncthreads();

    int warp = tid >> 5, lane = tid & 31;
    int g = lane >> 2, tig = lane & 3;
    int r0 = (warp & 3) * 16, cbn = (warp >> 2) * 32;

    float acc[4][4];
    #pragma unroll
    for (int nt = 0; nt < 4; nt++)
        #pragma unroll
        for (int q = 0; q < 4; q++) acc[nt][q] = 0.f;
    #pragma unroll
    for (int ks = 0; ks < 4; ks++) {
        uint4 fa0 = sC[(ks * 4 + tig) * 64 + r0 + g];
        uint4 fa1 = sC[(ks * 4 + tig) * 64 + r0 + g + 8];
        unsigned ahi[4] = {fa0.x, fa1.x, fa0.z, fa1.z};
        unsigned alo[4] = {fa0.y, fa1.y, fa0.w, fa1.w};
        #pragma unroll
        for (int nt = 0; nt < 4; nt++) {
            uint4 fb = sST[(ks * 4 + tig) * 64 + cbn + nt * 8 + g];
            unsigned bhi[2] = {fb.x, fb.z}, blo[2] = {fb.y, fb.w};
            mma16(acc[nt], alo, bhi);
            mma16(acc[nt], ahi, blo);
            mma16(acc[nt], ahi, bhi);
        }
    }

    float dh = Dh[(2 * b + j) * NH + h];
    #pragma unroll
    for (int nt = 0; nt < 4; nt++) {
        int p = cbn + nt * 8 + 2 * tig;
        #pragma unroll
        for (int hf = 0; hf < 2; hf++) {
            int t = r0 + g + hf * 8;
            float e = __expf(scum[t]);
            long long ydx = (rowb + t) * DI + h * HD + p;
            float2 o = *(float2*)&g_y[ydx];
            float2 xs2 = *(const float2*)&g_xs[ydx];
            o.x += e * acc[nt][hf * 2]     + dh * xs2.x;
            o.y += e * acc[nt][hf * 2 + 1] + dh * xs2.y;
            *(float2*)&g_y[ydx] = o;
        }
    }
}

// ---------------- gate (silu(z)) + RMSNorm -> packed bf16 ----------------
__global__ __launch_bounds__(256) void k_gate(const float* __restrict__ norm_w, int j) {
    int t = blockIdx.x, b = blockIdx.y;
    int lidx = 2 * b + j;
    const float* z = g_zx + ((long long)b * LP + t) * DPROJ;
    const float* yr = g_y + ((long long)b * LP + t) * DI;
    unsigned* yo = g_yB + ((long long)b * LP + t) * 512;
    int c0 = threadIdx.x * 4;
    float4 zv4 = *(const float4*)&z[c0];
    float4 yv4 = *(const float4*)&yr[c0];
    float vals[4];
    float zv[4] = {zv4.x, zv4.y, zv4.z, zv4.w};
    float yv[4] = {yv4.x, yv4.y, yv4.z, yv4.w};
    float ss = 0.f;
    #pragma unroll
    for (int i = 0; i < 4; i++) {
        float gv = yv[i] * (zv[i] / (1.f + __expf(-zv[i])));
        vals[i] = gv;
        ss += gv * gv;
    }
    float tot = bsum(ss);
    float scale = rsqrtf(tot / (float)DI + 1e-5f);
    float4 nw4 = *(const float4*)&norm_w[lidx * DI + c0];
    float nw[4] = {nw4.x, nw4.y, nw4.z, nw4.w};
    uint2 packed;
    packed.x = pack_bf16(vals[0] * scale * nw[0], vals[1] * scale * nw[1]);
    packed.y = pack_bf16(vals[2] * scale * nw[2], vals[3] * scale * nw[3]);
    *(uint2*)&yo[c0 >> 1] = packed;
}

// ---------------- final LayerNorm: fp32 hn + split pairs ----------------
__global__ __launch_bounds__(256) void k_ln(const float* __restrict__ lnw, const float* __restrict__ lnb) {
    int g = blockIdx.x;
    int b = g / L_TOK, t = g % L_TOK;
    const float* row = g_hcur + ((long long)b * LP + t) * DM;
    int tid = threadIdx.x;
    float2 v = *(const float2*)&row[2 * tid];
    float s = bsum(v.x + v.y);
    float sq = bsum(v.x * v.x + v.y * v.y);
    float mu = s / (float)DM;
    float var = sq / (float)DM - mu * mu;
    float inv = rsqrtf(var + 1e-5f);
    float o0 = (v.x - mu) * inv * lnw[2 * tid]     + lnb[2 * tid];
    float o1 = (v.y - mu) * inv * lnw[2 * tid + 1] + lnb[2 * tid + 1];
    *(float2*)&g_hn[(long long)g * DM + 2 * tid] = make_float2(o0, o1);
    g_hnS[(long long)g * 256 + tid] = split_bf16_pair(o0, o1);
}

// ---------------- attention scalar score ----------------
__global__ void k_score(const float* __restrict__ w2, const float* __restrict__ b2) {
    int g = blockIdx.x;
    int tid = threadIdx.x;
    float v = g_s1[(long long)g * 128 + tid] * w2[tid];
    v = bsum(v);
    if (tid == 0) g_scoreb[g] = v + b2[0];
}

// ---------------- softmax (+ zero pooled) ----------------
__global__ void k_softmax() {
    const int n = NB * L_TOK;
    __shared__ float red[32];
    __shared__ float s_max, s_sum;
    int tid = threadIdx.x;
    if (tid < DM) g_pooled[tid] = 0.f;
    float m = -1e30f;
    for (int i = tid; i < n; i += 1024) m = fmaxf(m, g_scoreb[i]);
    #pragma unroll
    for (int o = 16; o > 0; o >>= 1) m = fmaxf(m, __shfl_xor_sync(0xffffffffu, m, o));
    if ((tid & 31) == 0) red[tid >> 5] = m;
    __syncthreads();
    if (tid < 32) {
        float v = red[tid];
        #pragma unroll
        for (int o = 16; o > 0; o >>= 1) v = fmaxf(v, __shfl_xor_sync(0xffffffffu, v, o));
        if (tid == 0) s_max = v;
    }
    __syncthreads();
    float m0 = s_max;
    float s = 0.f;
    for (int i = tid; i < n; i += 1024) s += expf(g_scoreb[i] - m0);
    #pragma unroll
    for (int o = 16; o > 0; o >>= 1) s += __shfl_xor_sync(0xffffffffu, s, o);
    if ((tid & 31) == 0) red[tid >> 5] = s;
    __syncthreads();
    if (tid < 32) {
        float v = red[tid];
        #pragma unroll
        for (int o = 16; o > 0; o >>= 1) v += __shfl_xor_sync(0xffffffffu, v, o);
        if (tid == 0) s_sum = v;
    }
    __syncthreads();
    float inv = 1.f / s_sum;
    for (int i = tid; i < n; i += 1024) g_wts[i] = expf(g_scoreb[i] - m0) * inv;
}

// ---------------- pooled ----------------
#define PBLK 120
__global__ __launch_bounds__(256) void k_pooled() {
    const int total = NB * L_TOK;
    int per = (total + PBLK - 1) / PBLK;
    int g0 = blockIdx.x * per;
    int g1 = g0 + per; if (g1 > total) g1 = total;
    int tid = threadIdx.x;
    float a0 = 0.f, a1 = 0.f;
    for (int g = g0; g < g1; g++) {
        float w = g_wts[g];
        float2 v = *(const float2*)&g_hn[(long long)g * DM + 2 * tid];
        a0 = fmaf(w, v.x, a0);
        a1 = fmaf(w, v.y, a1);
    }
    atomicAdd(&g_pooled[2 * tid], a0);
    atomicAdd(&g_pooled[2 * tid + 1], a1);
}

// ---------------- final classifier ----------------
__global__ void k_final(const float* __restrict__ cls_w, const float* __restrict__ cls_b,
                        float* __restrict__ out, int out_size) {
    int tid = threadIdx.x;
    int cls = tid >> 5, lane = tid & 31;
    float acc = 0.f;
    for (int d = lane; d < DM; d += 32) acc += g_pooled[d] * cls_w[cls * DM + d];
    #pragma unroll
    for (int o = 16; o > 0; o >>= 1) acc += __shfl_xor_sync(0xffffffffu, acc, o);
    __shared__ float lg[2];
    if (lane == 0) lg[cls] = acc;
    __syncthreads();
    if (tid == 0) {
        float l0 = lg[0] + cls_b[0], l1 = lg[1] + cls_b[1];
        float m = fmaxf(l0, l1);
        float e0 = expf(l0 - m), e1 = expf(l1 - m);
        float s = e0 + e1;
        out[0] = l0;
        out[1] = l1;
        if (out_size >= 4) { out[2] = e0 / s; out[3] = e1 / s; }
    }
}

// ---------------- launch ----------------
static inline void launch_split(const float* src, void* dst, long long npairs) {
    k_split<<<(int)((npairs + 255) / 256), 256>>>(src, (uint2*)dst, npairs);
}

extern "C" void kernel_launch(void* const* d_in, const int* in_sizes, int n_in,
                              void* d_out, int out_size) {
    const float* x        = (const float*)d_in[0];
    const float* fc1_w    = (const float*)d_in[1];
    const float* fc1_b    = (const float*)d_in[2];
    const float* in_proj_w= (const float*)d_in[3];
    const float* conv_w   = (const float*)d_in[4];
    const float* conv_b   = (const float*)d_in[5];
    const float* dt_bias  = (const float*)d_in[6];
    const float* A_log    = (const float*)d_in[7];
    const float* Dh       = (const float*)d_in[8];
    const float* norm_w   = (const float*)d_in[9];
    const float* out_proj_w=(const float*)d_in[10];
    const float* ln_w     = (const float*)d_in[11];
    const float* ln_b     = (const float*)d_in[12];
    const float* attn_w1  = (const float*)d_in[13];
    const float* attn_b1  = (const float*)d_in[14];
    const float* attn_w2  = (const float*)d_in[15];
    const float* attn_b2  = (const float*)d_in[16];
    const float* cls_w    = (const float*)d_in[17];
    const float* cls_b    = (const float*)d_in[18];
    float* out = (float*)d_out;

    void *p_hcur, *p_zx, *p_y, *p_s1;
    void *p_xS, *p_fc1wS, *p_ipwS, *p_opwS, *p_aw1S, *p_hcurB, *p_yB, *p_hnS;
    cudaGetSymbolAddress(&p_hcur,  g_hcur);
    cudaGetSymbolAddress(&p_zx,    g_zx);
    cudaGetSymbolAddress(&p_y,     g_y);
    cudaGetSymbolAddress(&p_s1,    g_s1);
    cudaGetSymbolAddress(&p_xS,    g_xS);
    cudaGetSymbolAddress(&p_fc1wS, g_fc1wS);
    cudaGetSymbolAddress(&p_ipwS,  g_ipwS);
    cudaGetSymbolAddress(&p_opwS,  g_opwS);
    cudaGetSymbolAddress(&p_aw1S,  g_aw1S);
    cudaGetSymbolAddress(&p_hcurB, g_hcurB);
    cudaGetSymbolAddress(&p_yB,    g_yB);
    cudaGetSymbolAddress(&p_hnS,   g_hnS);

    cudaFuncSetAttribute(tgemm,  cudaFuncAttributeMaxDynamicSharedMemorySize, TG_SMEM);
    cudaFuncSetAttribute(tgemm2, cudaFuncAttributeMaxDynamicSharedMemorySize, TG2_SMEM);
    cudaFuncSetAttribute(k_intra_mma, cudaFuncAttributeMaxDynamicSharedMemorySize, SMEM_INTRA_MMA);

    // 1: merged splits (x, fc1_w, in_proj_w)
    {
        long long tot = NPX + NPF + NPI;
        k_split_all<<<(int)((tot + 255) / 256), 256>>>(x, fc1_w, in_proj_w);
    }
    // 2: fc1 (op=2 + branch-0 bf16 aux)
    {
        dim3 grid((DM + 127) / 128, (L_TOK + 127) / 128, 1);
        tgemm<<<grid, 256, TG_SMEM>>>((const uint2*)p_xS, 0, (const uint2*)p_fc1wS, 0, fc1_b,
                                      (float*)p_hcur, 0, (unsigned*)p_hcurB, L_TOK, DM, 512, 2, 0);
    }
    // 3: branch prep + pad zero (fused)
    {
        long long tot = (long long)L_TOK * 128 + (long long)NB * (LP - L_TOK) * 128;
        k_prep2<<<(int)((tot + 255) / 256), 256>>>();
    }

    for (int j = 0; j < 2; j++) {
        // 4 (j=0): in_proj (tgemm2 2m x 4n) <- ncu window
        {
            dim3 g1((DPROJ + 127) / 128, (LP + 127) / 128, NB);
            tgemm2<<<g1, 256, TG2_SMEM>>>((const unsigned*)p_hcurB, (long long)LP * 256,
                                          (const uint2*)p_ipwS, (long long)DPROJ * 256,
                                          (float*)p_zx, (long long)LP * DPROJ, nullptr,
                                          LP, DPROJ, 256, 0, j);
        }
        k_convfused<<<dim3(NC, NB), 256>>>(conv_w, conv_b, dt_bias, A_log, j);
        k_intra_mma<<<dim3(NC, NH, NB), 256, SMEM_INTRA_MMA>>>();
        k_rec<<<dim3(NB * NH, 4), 256>>>();
        k_inter_mma<<<dim3(NC, NH, NB), 256>>>(Dh, j);
        k_gate<<<dim3(LP, NB), 256>>>(norm_w, j);
        if (j == 0)
            launch_split(out_proj_w, p_opwS, (long long)6 * DM * 512);
        {
            dim3 g2((DM + 127) / 128, (LP + 127) / 128, NB);
            tgemm2<<<g2, 256, TG2_SMEM>>>((const unsigned*)p_yB, (long long)LP * 512,
                                          (const uint2*)p_opwS, (long long)DM * 512,
                                          (float*)p_hcur, (long long)LP * DM,
                                          (j == 0) ? (unsigned*)p_hcurB : nullptr,
                                          LP, DM, 512, 1, j);
        }
    }

    // final head
    k_ln<<<NB * L_TOK, 256>>>(ln_w, ln_b);
    launch_split(attn_w1, p_aw1S, (long long)128 * 256);
    {
        dim3 ga(1, (NB * L_TOK + 127) / 128, 1);
        tgemm<<<ga, 256, TG_SMEM>>>((const uint2*)p_hnS, 0, (const uint2*)p_aw1S, 0, attn_b1,
                                    (float*)p_s1, 0, nullptr, NB * L_TOK, 128, 256, 3, 0);
    }
    k_score<<<NB * L_TOK, 128>>>(attn_w2, attn_b2);
    k_softmax<<<1, 1024>>>();
    k_pooled<<<PBLK, 256>>>();
    k_final<<<1, 64>>>(cls_w, cls_b, out, out_size);
}

// round 14
// speedup vs baseline: 1.2094x; 1.2094x over previous
#include <cuda_runtime.h>
#include <cuda_bf16.h>
#include <math.h>

// ---------------- problem constants ----------------
#define L_TOK 10000
#define LP    10048
#define NC    157
#define Q     64
#define DM    512
#define DI    1024
#define DS    64
#define NH    16
#define HD    64
#define DXBC  1152
#define DPROJ 2192
#define NB    3

// ---------------- scratch ----------------
__device__ __align__(16) float g_hcur [(size_t)NB*LP*DM];
__device__ __align__(16) float g_zx   [(size_t)NB*LP*DPROJ];
__device__ __align__(16) float g_xs   [(size_t)NB*LP*DI];
__device__ __align__(16) float g_Bm   [(size_t)NB*LP*DS];
__device__ __align__(16) float g_Cm   [(size_t)NB*LP*DS];
__device__ __align__(16) float g_dtv  [(size_t)NB*LP*NH];
__device__ __align__(16) float g_cum  [(size_t)NB*NH*LP];
__device__ __align__(16) float g_y    [(size_t)NB*LP*DI];
__device__ __align__(16) float g_schunk[(size_t)NB*NH*NC*DS*HD];
__device__ __align__(16) float g_sbef  [(size_t)NB*NH*NC*DS*HD];
__device__ __align__(16) float g_hn   [(size_t)NB*L_TOK*DM];
__device__ __align__(16) float g_s1   [(size_t)NB*L_TOK*128];
__device__ float g_scoreb[NB*L_TOK];
__device__ float g_wts   [NB*L_TOK];
__device__ float g_pooled[DM];

// split-bf16 (old layout, for tgemm fc1/attn path)
__device__ __align__(16) uint2 g_xS   [(size_t)L_TOK*512];
__device__ __align__(16) uint2 g_fc1wS[(size_t)DM*512];
__device__ __align__(16) uint2 g_aw1S [(size_t)128*256];
__device__ __align__(16) uint2 g_hnS  [(size_t)NB*L_TOK*256];
// W split, ktile-fragment layout: per (row, kt): 4 x uint4{hi(p),lo(p),hi(p+4),lo(p+4)}, p=8kt+tig
__device__ __align__(16) uint4 g_ipw4 [(size_t)6*DPROJ*128];   // Kp=256 -> 128 uint4/row
__device__ __align__(16) uint4 g_opw4 [(size_t)6*DM*256];      // Kp=512 -> 256 uint4/row
// A plain-bf16, ktile layout: per (row, kt): 4 x uint2{pair p, pair p+4}
__device__ __align__(16) unsigned g_hcurB[(size_t)NB*LP*256];
__device__ __align__(16) unsigned g_yB   [(size_t)NB*LP*512];

// layout bijection for A pairs: pair p -> unsigned index within row
__device__ __forceinline__ int a2i(int p) {
    return (p & ~7) | ((p & 3) << 1) | ((p >> 2) & 1);
}

// ---------------- helpers ----------------
__device__ __forceinline__ float bsum(float v) {
    __shared__ float sh[32];
    int lane = threadIdx.x & 31, w = threadIdx.x >> 5;
    #pragma unroll
    for (int o = 16; o > 0; o >>= 1) v += __shfl_xor_sync(0xffffffffu, v, o);
    if (lane == 0) sh[w] = v;
    __syncthreads();
    int nw = blockDim.x >> 5;
    v = (threadIdx.x < nw) ? sh[threadIdx.x] : 0.f;
    if (w == 0) {
        #pragma unroll
        for (int o = 16; o > 0; o >>= 1) v += __shfl_xor_sync(0xffffffffu, v, o);
        if (threadIdx.x == 0) sh[0] = v;
    }
    __syncthreads();
    float r = sh[0];
    __syncthreads();
    return r;
}

__device__ __forceinline__ unsigned pack_bf16(float f0, float f1) {
    unsigned r;
    asm("cvt.rn.bf16x2.f32 %0, %1, %2;" : "=r"(r) : "f"(f1), "f"(f0));
    return r;
}

__device__ __forceinline__ uint2 split_bf16_pair(float f0, float f1) {
    unsigned hp, lp;
    asm("cvt.rn.bf16x2.f32 %0, %1, %2;" : "=r"(hp) : "f"(f1), "f"(f0));
    __nv_bfloat162 h = *reinterpret_cast<__nv_bfloat162*>(&hp);
    float r0 = f0 - __bfloat162float(h.x);
    float r1 = f1 - __bfloat162float(h.y);
    asm("cvt.rn.bf16x2.f32 %0, %1, %2;" : "=r"(lp) : "f"(r1), "f"(r0));
    uint2 q; q.x = hp; q.y = lp;
    return q;
}

__global__ void k_split(const float* __restrict__ in, uint2* __restrict__ out, long long npairs) {
    long long i = (long long)blockIdx.x * 256 + threadIdx.x;
    if (i >= npairs) return;
    float2 v = ((const float2*)in)[i];
    out[i] = split_bf16_pair(v.x, v.y);
}

// merged split of x, fc1_w (old layout)
#define NPX ((long long)L_TOK * 512)
#define NPF ((long long)DM * 512)
__global__ void k_split_all(const float* __restrict__ x, const float* __restrict__ fw) {
    long long i = (long long)blockIdx.x * 256 + threadIdx.x;
    const float* src; uint2* dst; long long off;
    if (i < NPX) { src = x; dst = g_xS; off = i; }
    else if (i < NPX + NPF) { src = fw; dst = g_fc1wS; off = i - NPX; }
    else return;
    float2 v = ((const float2*)src)[off];
    dst[off] = split_bf16_pair(v.x, v.y);
}

// split W into ktile-fragment layout. one uint4 per thread.
__global__ void k_splitW(const float* __restrict__ src, uint4* __restrict__ dst,
                         long long nu4, int K) {
    long long u = (long long)blockIdx.x * 256 + threadIdx.x;
    if (u >= nu4) return;
    int perrow = K >> 2;                 // uint4 per row
    long long row = u / perrow;
    int rem = (int)(u % perrow);
    int kt = rem >> 2, tig = rem & 3;
    int k0 = kt * 16 + tig * 2;
    const float* rp = src + row * K;
    float2 va = *(const float2*)&rp[k0];
    float2 vb = *(const float2*)&rp[k0 + 8];
    uint2 sa = split_bf16_pair(va.x, va.y);
    uint2 sb = split_bf16_pair(vb.x, vb.y);
    dst[u] = make_uint4(sa.x, sa.y, sb.x, sb.y);
}

__device__ __forceinline__ void mma16(float c[4], const unsigned a[4], const unsigned b[2]) {
    asm volatile(
        "mma.sync.aligned.m16n8k16.row.col.f32.bf16.bf16.f32 "
        "{%0,%1,%2,%3},{%4,%5,%6,%7},{%8,%9},{%0,%1,%2,%3};"
        : "+f"(c[0]), "+f"(c[1]), "+f"(c[2]), "+f"(c[3])
        : "r"(a[0]), "r"(a[1]), "r"(a[2]), "r"(a[3]), "r"(b[0]), "r"(b[1]));
}

__device__ __forceinline__ void cp8(unsigned dst, const void* src, bool pred) {
    int sz = pred ? 8 : 0;
    asm volatile("cp.async.ca.shared.global [%0], [%1], 8, %2;" :: "r"(dst), "l"(src), "r"(sz));
}
__device__ __forceinline__ void cp16(unsigned dst, const void* src, bool pred) {
    int sz = pred ? 16 : 0;
    asm volatile("cp.async.cg.shared.global [%0], [%1], 16, %2;" :: "r"(dst), "l"(src), "r"(sz));
}

// ---------------- tgemm: 3xBF16 split both sides (fc1, attn1) — R8-proven ----------------
// op: 0=store, 1=C+=, 2=relu(v+bias) (+bf16 aux, A-layout remap), 3=tanh(v+bias)
#define STAGES 4
#define S4 130
#define TG_SMEM (STAGES * 4 * S4 * 16 * 2)

__global__ __launch_bounds__(256, 2) void tgemm(
    const uint2* __restrict__ A, long long sA,
    const uint2* __restrict__ W, long long sW,
    const float* __restrict__ bias,
    float* __restrict__ C, long long sC,
    unsigned* __restrict__ Caux,
    int M, int N, int Kp, int op, int joff)
{
    extern __shared__ uint4 sm4[];
    uint4* As = sm4;
    uint4* Ws = sm4 + STAGES * 4 * S4;

    int z = blockIdx.z;
    A += (long long)z * sA;
    C += (long long)z * sC;
    W += (long long)(2 * z + joff) * sW;
    if (Caux) Caux += (long long)z * (sC >> 1);

    int tid = threadIdx.x;
    int warp = tid >> 5, lane = tid & 31;
    int wm = warp & 3, wn = warp >> 2;
    int g = lane >> 2, tig = lane & 3;
    int row0 = blockIdx.y * 128, col0 = blockIdx.x * 128;

    int ar = tid >> 1, half = tid & 1;
    bool aok = (row0 + ar) < M;
    bool wok = (col0 + ar) < N;
    const uint2* Ag = A + (long long)(row0 + ar) * Kp + half * 4;
    const uint2* Wg = W + (long long)(col0 + ar) * Kp + half * 4;
    unsigned aSm = (unsigned)__cvta_generic_to_shared(As);
    unsigned wSm = (unsigned)__cvta_generic_to_shared(Ws);

    float c[2][8][4];
    #pragma unroll
    for (int mt = 0; mt < 2; mt++)
        #pragma unroll
        for (int nt = 0; nt < 8; nt++)
            #pragma unroll
            for (int q = 0; q < 4; q++) c[mt][nt][q] = 0.f;

    int nK = Kp >> 3;

    #define ISSUE(kt, slot) do { \
        const uint2* _Ap = Ag + (kt) * 8; \
        const uint2* _Wp = Wg + (kt) * 8; \
        _Pragma("unroll") \
        for (int i = 0; i < 4; i++) { \
            unsigned off = (unsigned)((((slot) * 4 + i) * S4 + ar) * 16 + half * 8); \
            cp8(aSm + off, _Ap + i, aok); \
            cp8(wSm + off, _Wp + i, wok); \
        } \
    } while (0)

    #pragma unroll
    for (int s = 0; s < STAGES - 1; s++) {
        if (s < nK) ISSUE(s, s);
        asm volatile("cp.async.commit_group;");
    }

    for (int kt = 0; kt < nK; kt++) {
        asm volatile("cp.async.wait_group %0;" :: "n"(STAGES - 2));
        __syncthreads();

        int slot = kt & 3;
        const uint4* Ab = As + slot * 4 * S4;
        const uint4* Wb = Ws + slot * 4 * S4;

        uint4 fa[2][2];
        #pragma unroll
        for (int mt = 0; mt < 2; mt++) {
            int m0 = wm * 32 + mt * 16;
            fa[mt][0] = Ab[tig * S4 + m0 + g];
            fa[mt][1] = Ab[tig * S4 + m0 + g + 8];
        }
        unsigned ahi[2][4], alo[2][4];
        #pragma unroll
        for (int mt = 0; mt < 2; mt++) {
            ahi[mt][0] = fa[mt][0].x; ahi[mt][1] = fa[mt][1].x;
            ahi[mt][2] = fa[mt][0].z; ahi[mt][3] = fa[mt][1].z;
            alo[mt][0] = fa[mt][0].y; alo[mt][1] = fa[mt][1].y;
            alo[mt][2] = fa[mt][0].w; alo[mt][3] = fa[mt][1].w;
        }
        #pragma unroll
        for (int nt = 0; nt < 8; nt++) {
            int n0 = wn * 64 + nt * 8;
            uint4 fb = Wb[tig * S4 + n0 + g];
            unsigned bhi[2] = {fb.x, fb.z};
            unsigned blo[2] = {fb.y, fb.w};
            #pragma unroll
            for (int mt = 0; mt < 2; mt++) {
                mma16(c[mt][nt], alo[mt], bhi);
                mma16(c[mt][nt], ahi[mt], blo);
                mma16(c[mt][nt], ahi[mt], bhi);
            }
        }

        int pre = kt + STAGES - 1;
        if (pre < nK) ISSUE(pre, pre & 3);
        asm volatile("cp.async.commit_group;");
    }
    asm volatile("cp.async.wait_all;");

    #pragma unroll
    for (int mt = 0; mt < 2; mt++) {
        #pragma unroll
        for (int nt = 0; nt < 8; nt++) {
            int cc = col0 + wn * 64 + nt * 8 + 2 * tig;
            if (cc >= N) continue;
            #pragma unroll
            for (int hf = 0; hf < 2; hf++) {
                int r = row0 + wm * 32 + mt * 16 + g + hf * 8;
                if (r >= M) continue;
                float v0 = c[mt][nt][hf * 2 + 0];
                float v1 = c[mt][nt][hf * 2 + 1];
                long long ci = (long long)r * N + cc;
                if (op == 0) {
                    *(float2*)&C[ci] = make_float2(v0, v1);
                } else if (op == 1) {
                    float2 o = *(float2*)&C[ci];
                    o.x += v0; o.y += v1;
                    *(float2*)&C[ci] = o;
                } else if (op == 2) {
                    v0 = fmaxf(v0 + bias[cc], 0.f);
                    v1 = fmaxf(v1 + bias[cc + 1], 0.f);
                    *(float2*)&C[ci] = make_float2(v0, v1);
                    if (Caux) Caux[(long long)r * (N >> 1) + a2i(cc >> 1)] = pack_bf16(v0, v1);
                } else {
                    v0 += bias[cc]; v1 += bias[cc + 1];
                    *(float2*)&C[ci] = make_float2(tanhf(v0), tanhf(v1));
                }
            }
        }
    }
    #undef ISSUE
}

// ---------------- tgemm2: bf16-A x split-W, all cp16, conflict-free layouts ----------------
// A global: uint2{pair p, pair p+4} per (row, kt, tig); W global: uint4 frag per (row, kt, tig)
// smem A: 32B rows, W: 64B rows. op: 0=store, 1=C+= (+aux in A-layout)
#define NSLOT 3
#define TG2_SMEM (NSLOT * 2 * (128 * 32 + 128 * 64))

__global__ __launch_bounds__(256, 2) void tgemm2(
    const uint2* __restrict__ A, long long sA,      // uint2 units per z
    const uint4* __restrict__ W, long long sW,      // uint4 units per z
    float* __restrict__ C, long long sC,
    unsigned* __restrict__ Caux,
    int M, int N, int Kp, int op, int joff)
{
    extern __shared__ char smc[];
    uint2* Asm = (uint2*)smc;                              // NSLOT*2 ktiles * 128 rows * 4
    uint4* Wsm = (uint4*)(smc + NSLOT * 2 * 128 * 32);

    int z = blockIdx.z;
    A += (long long)z * sA;
    C += (long long)z * sC;
    W += (long long)(2 * z + joff) * sW;
    if (Caux) Caux += (long long)z * (sC >> 1);

    int tid = threadIdx.x;
    int warp = tid >> 5, lane = tid & 31;
    int wm = warp & 1, wn = warp >> 1;          // 2 m-warps x 4 n-warps
    int g = lane >> 2, tig = lane & 3;
    int row0 = blockIdx.y * 128, col0 = blockIdx.x * 128;

    int ar = tid >> 1, half = tid & 1;
    bool aok = (row0 + ar) < M;
    bool wok = (col0 + ar) < N;
    int pr = Kp >> 1;                            // uint2 (A) / uint4 (W) per row
    const uint2* Ag = A + (long long)(row0 + ar) * pr + half * 2;
    const uint4* Wg = W + (long long)(col0 + ar) * pr + half * 2;
    unsigned aB = (unsigned)__cvta_generic_to_shared(Asm);
    unsigned wB = (unsigned)__cvta_generic_to_shared(Wsm);

    float c[4][4][4];
    #pragma unroll
    for (int mt = 0; mt < 4; mt++)
        #pragma unroll
        for (int nt = 0; nt < 4; nt++)
            #pragma unroll
            for (int q = 0; q < 4; q++) c[mt][nt][q] = 0.f;

    int nG = Kp >> 4;

    #define ISSUEG(gi, s) do { \
        _Pragma("unroll") \
        for (int u = 0; u < 2; u++) { \
            int _kt = (gi) * 2 + u; \
            cp16(aB + (unsigned)((((s) * 2 + u) * 128 + ar) * 32 + half * 16), Ag + _kt * 4, aok); \
            cp16(wB + (unsigned)((((s) * 2 + u) * 128 + ar) * 64 + half * 32),      Wg + _kt * 4,     wok); \
            cp16(wB + (unsigned)((((s) * 2 + u) * 128 + ar) * 64 + half * 32 + 16), Wg + _kt * 4 + 1, wok); \
        } \
    } while (0)

    ISSUEG(0, 0);
    asm volatile("cp.async.commit_group;");
    if (1 < nG) ISSUEG(1, 1);
    asm volatile("cp.async.commit_group;");

    int sc = 0, si = 2;
    for (int gi = 0; gi < nG; gi++) {
        asm volatile("cp.async.wait_group 1;");
        __syncthreads();

        #pragma unroll
        for (int u = 0; u < 2; u++) {
            const uint2* Ab = Asm + (sc * 2 + u) * 128 * 4;
            const uint4* Wb = Wsm + (sc * 2 + u) * 128 * 4;

            unsigned a[4][4];
            #pragma unroll
            for (int mt = 0; mt < 4; mt++) {
                int m0 = wm * 64 + mt * 16;
                uint2 q0 = Ab[(m0 + g) * 4 + tig];
                uint2 q1 = Ab[(m0 + g + 8) * 4 + tig];
                a[mt][0] = q0.x; a[mt][1] = q1.x;
                a[mt][2] = q0.y; a[mt][3] = q1.y;
            }
            #pragma unroll
            for (int nt = 0; nt < 4; nt++) {
                int n0 = wn * 32 + nt * 8;
                uint4 fb = Wb[(n0 + g) * 4 + tig];
                unsigned bhi[2] = {fb.x, fb.z};
                unsigned blo[2] = {fb.y, fb.w};
                #pragma unroll
                for (int mt = 0; mt < 4; mt++) {
                    mma16(c[mt][nt], a[mt], blo);
                    mma16(c[mt][nt], a[mt], bhi);
                }
            }
        }

        int pre = gi + 2;
        if (pre < nG) ISSUEG(pre, si);
        asm volatile("cp.async.commit_group;");
        sc++; if (sc == NSLOT) sc = 0;
        si++; if (si == NSLOT) si = 0;
    }
    asm volatile("cp.async.wait_all;");

    #pragma unroll
    for (int mt = 0; mt < 4; mt++) {
        #pragma unroll
        for (int nt = 0; nt < 4; nt++) {
            int cc = col0 + wn * 32 + nt * 8 + 2 * tig;
            if (cc >= N) continue;
            #pragma unroll
            for (int hf = 0; hf < 2; hf++) {
                int r = row0 + wm * 64 + mt * 16 + g + hf * 8;
                if (r >= M) continue;
                float v0 = c[mt][nt][hf * 2 + 0];
                float v1 = c[mt][nt][hf * 2 + 1];
                long long ci = (long long)r * N + cc;
                if (op == 0) {
                    *(float2*)&C[ci] = make_float2(v0, v1);
                } else {
                    float2 o = *(float2*)&C[ci];
                    o.x += v0; o.y += v1;
                    *(float2*)&C[ci] = o;
                    if (Caux) Caux[(long long)r * (N >> 1) + a2i(cc >> 1)] = pack_bf16(o.x, o.y);
                }
            }
        }
    }
    #undef ISSUEG
}

// ---------------- branch prep (coalesced, A-layout aux) + pad-row zeroing ----------------
__global__ void k_prep2() {
    long long i = (long long)blockIdx.x * 256 + threadIdx.x;
    const long long mainN = (long long)L_TOK * 128;
    if (i < mainN) {
        int t = (int)(i >> 7), q = (int)(i & 127);
        float4 v = *((const float4*)g_hcur + (long long)t * 128 + q);
        int d0 = q * 4, p = q * 2;
        *(float4*)&g_hcur[(long long)LP * DM + (long long)t * DM + (508 - d0)] =
            make_float4(v.w, v.z, v.y, v.x);
        g_hcurB[(long long)LP * 256 + (long long)t * 256 + a2i(255 - p)] = pack_bf16(v.y, v.x);
        g_hcurB[(long long)LP * 256 + (long long)t * 256 + a2i(254 - p)] = pack_bf16(v.w, v.z);
        int tt = (t % 100) * 100 + t / 100;
        *(float4*)&g_hcur[2LL * LP * DM + (long long)tt * DM + d0] = v;
        g_hcurB[2LL * LP * 256 + (long long)tt * 256 + a2i(p)]     = pack_bf16(v.x, v.y);
        g_hcurB[2LL * LP * 256 + (long long)tt * 256 + a2i(p + 1)] = pack_bf16(v.z, v.w);
        return;
    }
    long long j = i - mainN;
    if (j >= (long long)NB * (LP - L_TOK) * 128) return;
    int b = (int)(j / ((LP - L_TOK) * 128));
    int rem = (int)(j % ((LP - L_TOK) * 128));
    int t = L_TOK + rem / 128, q = rem % 128;
    *(float4*)&g_hcur[((long long)b * LP + t) * DM + q * 4] = make_float4(0.f, 0.f, 0.f, 0.f);
    g_hcurB[((long long)b * LP + t) * 256 + q * 2]     = 0u;
    g_hcurB[((long long)b * LP + t) * 256 + q * 2 + 1] = 0u;
}

// ---------------- fused conv + silu + dt + cumsum ----------------
__global__ __launch_bounds__(256) void k_convfused(
    const float* __restrict__ cw, const float* __restrict__ cb,
    const float* __restrict__ dt_bias, const float* __restrict__ A_log, int j)
{
    __shared__ float av_s[NH * 64];
    int c = blockIdx.x, b = blockIdx.y;
    int lidx = 2 * b + j;
    int tid = threadIdx.x;
    const float* zbase = g_zx + (long long)b * LP * DPROJ;
    int gt0 = c * Q;

    for (int cc = tid; cc < DXBC; cc += 256) {
        const float* col = zbase + DI + cc;
        const float* wp = cw + (long long)(lidx * DXBC + cc) * 4;
        float w0 = wp[0], w1 = wp[1], w2 = wp[2], w3 = wp[3];
        float bia = cb[lidx * DXBC + cc];
        float h3 = (gt0 - 3 >= 0) ? col[(long long)(gt0 - 3) * DPROJ] : 0.f;
        float h2 = (gt0 - 2 >= 0) ? col[(long long)(gt0 - 2) * DPROJ] : 0.f;
        float h1 = (gt0 - 1 >= 0) ? col[(long long)(gt0 - 1) * DPROJ] : 0.f;
        #pragma unroll 4
        for (int t = 0; t < Q; t++) {
            int gt = gt0 + t;
            float cur = col[(long long)gt * DPROJ];
            float a = bia + w0 * h3 + w1 * h2 + w2 * h1 + w3 * cur;
            float v = a / (1.f + __expf(-a));
            if (gt >= L_TOK) v = 0.f;
            long long tb = (long long)b * LP + gt;
            if (cc < DI)            g_xs[tb * DI + cc] = v;
            else if (cc < DI + DS)  g_Bm[tb * DS + (cc - DI)] = v;
            else                    g_Cm[tb * DS + (cc - DI - DS)] = v;
            h3 = h2; h2 = h1; h1 = cur;
        }
    }

    #pragma unroll
    for (int k = 0; k < 4; k++) {
        int idx = tid + k * 256;
        int h = idx & 15, t = idx >> 4;
        int gt = gt0 + t;
        float draw = zbase[(long long)gt * DPROJ + DI + DXBC + h];
        float xv = draw + dt_bias[lidx * NH + h];
        float sp = (xv > 20.f) ? xv : log1pf(expf(xv));
        if (gt >= L_TOK) sp = 0.f;
        g_dtv[((long long)b * LP + gt) * NH + h] = sp;
        float Ah = -expf(A_log[lidx * NH + h]);
        av_s[h * 64 + t] = sp * Ah;
    }
    __syncthreads();

    int warp = tid >> 5, lane = tid & 31;
    #pragma unroll
    for (int hh = 0; hh < 2; hh++) {
        int h = warp * 2 + hh;
        float x1 = av_s[h * 64 + lane];
        float x2 = av_s[h * 64 + 32 + lane];
        #pragma unroll
        for (int o = 1; o < 32; o <<= 1) { float yv = __shfl_up_sync(0xffffffffu, x1, o); if (lane >= o) x1 += yv; }
        #pragma unroll
        for (int o = 1; o < 32; o <<= 1) { float yv = __shfl_up_sync(0xffffffffu, x2, o); if (lane >= o) x2 += yv; }
        float tot1 = __shfl_sync(0xffffffffu, x1, 31);
        x2 += tot1;
        long long base = (long long)(b * NH + h) * LP + (long long)c * Q;
        g_cum[base + lane] = x1;
        g_cum[base + 32 + lane] = x2;
    }
}

// ---------------- intra-chunk (tensor-core) ----------------
#define SMEM_INTRA_MMA (4096 * 16 + 512)
__global__ __launch_bounds__(256) void k_intra_mma() {
    extern __shared__ uint4 smu[];
    uint4* sC  = smu;
    uint4* sB  = smu + 1024;
    uint4* sUT = smu + 2048;
    uint4* sBw = smu + 3072;
    float* scum = (float*)(smu + 4096);
    float* sdt  = scum + 64;

    int c = blockIdx.x, h = blockIdx.y, b = blockIdx.z;
    long long rowb = (long long)b * LP + (long long)c * Q;
    int tid = threadIdx.x;

    if (tid < 64) {
        scum[tid] = g_cum[(long long)(b * NH + h) * LP + (long long)c * Q + tid];
        sdt[tid]  = g_dtv[(rowb + tid) * NH + h];
    }
    __syncthreads();
    float T = scum[63];

    for (int i = tid; i < 1024; i += 256) {
        int slot = i >> 6, row = i & 63;
        int ks = slot >> 2, tg = slot & 3;
        int k0 = ks * 16 + tg * 2;
        long long rb = rowb + row;
        float2 c0 = *(const float2*)&g_Cm[rb * DS + k0];
        float2 c1 = *(const float2*)&g_Cm[rb * DS + k0 + 8];
        uint2 ch0 = split_bf16_pair(c0.x, c0.y);
        uint2 ch1 = split_bf16_pair(c1.x, c1.y);
        sC[i] = make_uint4(ch0.x, ch0.y, ch1.x, ch1.y);
        float2 b0 = *(const float2*)&g_Bm[rb * DS + k0];
        float2 b1 = *(const float2*)&g_Bm[rb * DS + k0 + 8];
        uint2 bh0 = split_bf16_pair(b0.x, b0.y);
        uint2 bh1 = split_bf16_pair(b1.x, b1.y);
        sB[i] = make_uint4(bh0.x, bh0.y, bh1.x, bh1.y);
        float u0 = sdt[k0]     * g_xs[(rowb + k0)     * DI + h * HD + row];
        float u1 = sdt[k0 + 1] * g_xs[(rowb + k0 + 1) * DI + h * HD + row];
        float u2 = sdt[k0 + 8] * g_xs[(rowb + k0 + 8) * DI + h * HD + row];
        float u3 = sdt[k0 + 9] * g_xs[(rowb + k0 + 9) * DI + h * HD + row];
        uint2 uh0 = split_bf16_pair(u0, u1);
        uint2 uh1 = split_bf16_pair(u2, u3);
        sUT[i] = make_uint4(uh0.x, uh0.y, uh1.x, uh1.y);
        float bw0 = g_Bm[(rowb + k0)     * DS + row] * __expf(T - scum[k0]);
        float bw1 = g_Bm[(rowb + k0 + 1) * DS + row] * __expf(T - scum[k0 + 1]);
        float bw2 = g_Bm[(rowb + k0 + 8) * DS + row] * __expf(T - scum[k0 + 8]);
        float bw3 = g_Bm[(rowb + k0 + 9) * DS + row] * __expf(T - scum[k0 + 9]);
        uint2 wh0 = split_bf16_pair(bw0, bw1);
        uint2 wh1 = split_bf16_pair(bw2, bw3);
        sBw[i] = make_uint4(wh0.x, wh0.y, wh1.x, wh1.y);
    }
    __syncthreads();

    int warp = tid >> 5, lane = tid & 31;
    int g = lane >> 2, tig = lane & 3;
    int r0 = (warp & 3) * 16, cbn = (warp >> 2) * 32;

    float accP[4][4];
    #pragma unroll
    for (int nt = 0; nt < 4; nt++)
        #pragma unroll
        for (int q = 0; q < 4; q++) accP[nt][q] = 0.f;
    #pragma unroll
    for (int ks = 0; ks < 4; ks++) {
        uint4 fa0 = sC[(ks * 4 + tig) * 64 + r0 + g];
        uint4 fa1 = sC[(ks * 4 + tig) * 64 + r0 + g + 8];
        unsigned ahi[4] = {fa0.x, fa1.x, fa0.z, fa1.z};
        unsigned alo[4] = {fa0.y, fa1.y, fa0.w, fa1.w};
        #pragma unroll
        for (int nt = 0; nt < 4; nt++) {
            uint4 fb = sB[(ks * 4 + tig) * 64 + cbn + nt * 8 + g];
            unsigned bhi[2] = {fb.x, fb.z}, blo[2] = {fb.y, fb.w};
            mma16(accP[nt], alo, bhi);
            mma16(accP[nt], ahi, blo);
            mma16(accP[nt], ahi, bhi);
        }
    }
    __syncthreads();

    uint2* sP2 = (uint2*)sB;
    #pragma unroll
    for (int nt = 0; nt < 4; nt++) {
        int scol = cbn + nt * 8 + 2 * tig;
        int Pp = scol >> 1;
        int ksp = Pp >> 3, tslot = Pp & 3, halfp = (Pp >> 2) & 1;
        #pragma unroll
        for (int hf = 0; hf < 2; hf++) {
            int t = r0 + g + hf * 8;
            float v0 = accP[nt][hf * 2], v1 = accP[nt][hf * 2 + 1];
            v0 = (scol     <= t) ? v0 * __expf(scum[t] - scum[scol])     : 0.f;
            v1 = (scol + 1 <= t) ? v1 * __expf(scum[t] - scum[scol + 1]) : 0.f;
            sP2[((ksp * 4 + tslot) * 64 + t) * 2 + halfp] = split_bf16_pair(v0, v1);
        }
    }
    __syncthreads();

    float accY[4][4], accS[4][4];
    #pragma unroll
    for (int nt = 0; nt < 4; nt++)
        #pragma unroll
        for (int q = 0; q < 4; q++) { accY[nt][q] = 0.f; accS[nt][q] = 0.f; }
    uint4* sP = sB;
    #pragma unroll
    for (int ks = 0; ks < 4; ks++) {
        uint4 fp0 = sP[(ks * 4 + tig) * 64 + r0 + g];
        uint4 fp1 = sP[(ks * 4 + tig) * 64 + r0 + g + 8];
        unsigned phi[4] = {fp0.x, fp1.x, fp0.z, fp1.z};
        unsigned plo[4] = {fp0.y, fp1.y, fp0.w, fp1.w};
        uint4 fw0 = sBw[(ks * 4 + tig) * 64 + r0 + g];
        uint4 fw1 = sBw[(ks * 4 + tig) * 64 + r0 + g + 8];
        unsigned whi[4] = {fw0.x, fw1.x, fw0.z, fw1.z};
        unsigned wlo[4] = {fw0.y, fw1.y, fw0.w, fw1.w};
        #pragma unroll
        for (int nt = 0; nt < 4; nt++) {
            uint4 fb = sUT[(ks * 4 + tig) * 64 + cbn + nt * 8 + g];
            unsigned bhi[2] = {fb.x, fb.z}, blo[2] = {fb.y, fb.w};
            mma16(accY[nt], plo, bhi); mma16(accY[nt], phi, blo); mma16(accY[nt], phi, bhi);
            mma16(accS[nt], wlo, bhi); mma16(accS[nt], whi, blo); mma16(accS[nt], whi, bhi);
        }
    }

    long long sbase = ((long long)(b * NH + h) * NC + c) * 4096;
    #pragma unroll
    for (int nt = 0; nt < 4; nt++) {
        int p = cbn + nt * 8 + 2 * tig;
        #pragma unroll
        for (int hf = 0; hf < 2; hf++) {
            int r = r0 + g + hf * 8;
            *(float2*)&g_y[(rowb + r) * DI + h * HD + p] =
                make_float2(accY[nt][hf * 2], accY[nt][hf * 2 + 1]);
            *(float2*)&g_schunk[sbase + r * 64 + p] =
                make_float2(accS[nt][hf * 2], accS[nt][hf * 2 + 1]);
        }
    }
}

// ---------------- chunk-state recurrence (4-way split, prefetched) ----------------
__global__ __launch_bounds__(256) void k_rec() {
    int bh = blockIdx.x;
    int qd = blockIdx.y;
    int tid = threadIdx.x;
    int off = qd * 1024 + tid;
    float S[4], v[4], nv[4];
    #pragma unroll
    for (int i = 0; i < 4; i++) S[i] = 0.f;
    const float* cumrow = g_cum + (long long)bh * LP;
    long long base = (long long)bh * NC * 4096;
    #pragma unroll
    for (int i = 0; i < 4; i++) v[i] = g_schunk[base + off + i * 256];
    for (int c = 0; c < NC; c++) {
        float e = __expf(cumrow[c * Q + 63]);
        if (c + 1 < NC) {
            long long nb = base + 4096;
            #pragma unroll
            for (int i = 0; i < 4; i++) nv[i] = g_schunk[nb + off + i * 256];
        }
        #pragma unroll
        for (int i = 0; i < 4; i++) {
            g_sbef[base + off + i * 256] = S[i];
            S[i] = e * S[i] + v[i];
            v[i] = nv[i];
        }
        base += 4096;
    }
}

// ---------------- inter-chunk (tensor-core) ----------------
__global__ __launch_bounds__(256) void k_inter_mma(const float* __restrict__ Dh, int j) {
    __shared__ uint4 sC[1024];
    __shared__ uint4 sST[1024];
    __shared__ float scum[64];

    int c = blockIdx.x, h = blockIdx.y, b = blockIdx.z;
    long long rowb = (long long)b * LP + (long long)c * Q;
    long long sbase = ((long long)(b * NH + h) * NC + c) * 4096;
    int tid = threadIdx.x;

    if (tid < 64)
        scum[tid] = g_cum[(long long)(b * NH + h) * LP + (long long)c * Q + tid];

    for (int i = tid; i < 1024; i += 256) {
        int slot = i >> 6, row = i & 63;
        int ks = slot >> 2, tg = slot & 3;
        int k0 = ks * 16 + tg * 2;
        long long rb = rowb + row;
        float2 c0 = *(const float2*)&g_Cm[rb * DS + k0];
        float2 c1 = *(const float2*)&g_Cm[rb * DS + k0 + 8];
        uint2 ch0 = split_bf16_pair(c0.x, c0.y);
        uint2 ch1 = split_bf16_pair(c1.x, c1.y);
        sC[i] = make_uint4(ch0.x, ch0.y, ch1.x, ch1.y);
        float s0 = g_sbef[sbase + (k0)     * 64 + row];
        float s1 = g_sbef[sbase + (k0 + 1) * 64 + row];
        float s2 = g_sbef[sbase + (k0 + 8) * 64 + row];
        float s3 = g_sbef[sbase + (k0 + 9) * 64 + row];
        uint2 sh0 = split_bf16_pair(s0, s1);
        uint2 sh1 = split_bf16_pair(s2, s3);
        sST[i] = make_uint4(sh0.x, sh0.y, sh1.x, sh1.y);
    }
    __syncthreads();

    int warp = tid >> 5, lane = tid & 31;
    int g = lane >> 2, tig = lane & 3;
    int r0 = (warp & 3) * 16, cbn = (warp >> 2) * 32;

    float acc[4][4];
    #pragma unroll
    for (int nt = 0; nt < 4; nt++)
        #pragma unroll
        for (int q = 0; q < 4; q++) acc[nt][q] = 0.f;
    #pragma unroll
    for (int ks = 0; ks < 4; ks++) {
        uint4 fa0 = sC[(ks * 4 + tig) * 64 + r0 + g];
        uint4 fa1 = sC[(ks * 4 + tig) * 64 + r0 + g + 8];
        unsigned ahi[4] = {fa0.x, fa1.x, fa0.z, fa1.z};
        unsigned alo[4] = {fa0.y, fa1.y, fa0.w, fa1.w};
        #pragma unroll
        for (int nt = 0; nt < 4; nt++) {
            uint4 fb = sST[(ks * 4 + tig) * 64 + cbn + nt * 8 + g];
            unsigned bhi[2] = {fb.x, fb.z}, blo[2] = {fb.y, fb.w};
            mma16(acc[nt], alo, bhi);
            mma16(acc[nt], ahi, blo);
            mma16(acc[nt], ahi, bhi);
        }
    }

    float dh = Dh[(2 * b + j) * NH + h];
    #pragma unroll
    for (int nt = 0; nt < 4; nt++) {
        int p = cbn + nt * 8 + 2 * tig;
        #pragma unroll
        for (int hf = 0; hf < 2; hf++) {
            int t = r0 + g + hf * 8;
            float e = __expf(scum[t]);
            long long ydx = (rowb + t) * DI + h * HD + p;
            float2 o = *(float2*)&g_y[ydx];
            float2 xs2 = *(const float2*)&g_xs[ydx];
            o.x += e * acc[nt][hf * 2]     + dh * xs2.x;
            o.y += e * acc[nt][hf * 2 + 1] + dh * xs2.y;
            *(float2*)&g_y[ydx] = o;
        }
    }
}

// ---------------- gate (silu(z)) + RMSNorm -> bf16 in A-layout ----------------
__global__ __launch_bounds__(256) void k_gate(const float* __restrict__ norm_w, int j) {
    int t = blockIdx.x, b = blockIdx.y;
    int lidx = 2 * b + j;
    const float* z = g_zx + ((long long)b * LP + t) * DPROJ;
    const float* yr = g_y + ((long long)b * LP + t) * DI;
    unsigned* yo = g_yB + ((long long)b * LP + t) * 512;
    int tid = threadIdx.x;
    int kt = tid >> 2, jj = tid & 3;
    int k0 = kt * 16 + jj * 2;
    float2 z0 = *(const float2*)&z[k0];
    float2 z1 = *(const float2*)&z[k0 + 8];
    float2 y0 = *(const float2*)&yr[k0];
    float2 y1 = *(const float2*)&yr[k0 + 8];
    float va = y0.x * (z0.x / (1.f + __expf(-z0.x)));
    float vb = y0.y * (z0.y / (1.f + __expf(-z0.y)));
    float vc = y1.x * (z1.x / (1.f + __expf(-z1.x)));
    float vd = y1.y * (z1.y / (1.f + __expf(-z1.y)));
    float ss = va * va + vb * vb + vc * vc + vd * vd;
    float tot = bsum(ss);
    float scale = rsqrtf(tot / (float)DI + 1e-5f);
    float2 n0 = *(const float2*)&norm_w[lidx * DI + k0];
    float2 n1 = *(const float2*)&norm_w[lidx * DI + k0 + 8];
    uint2 packed;
    packed.x = pack_bf16(va * scale * n0.x, vb * scale * n0.y);
    packed.y = pack_bf16(vc * scale * n1.x, vd * scale * n1.y);
    *(uint2*)&yo[kt * 8 + jj * 2] = packed;
}

// ---------------- final LayerNorm: fp32 hn + split pairs (old layout for attn1) ----------------
__global__ __launch_bounds__(256) void k_ln(const float* __restrict__ lnw, const float* __restrict__ lnb) {
    int g = blockIdx.x;
    int b = g / L_TOK, t = g % L_TOK;
    const float* row = g_hcur + ((long long)b * LP + t) * DM;
    int tid = threadIdx.x;
    float2 v = *(const float2*)&row[2 * tid];
    float s = bsum(v.x + v.y);
    float sq = bsum(v.x * v.x + v.y * v.y);
    float mu = s / (float)DM;
    float var = sq / (float)DM - mu * mu;
    float inv = rsqrtf(var + 1e-5f);
    float o0 = (v.x - mu) * inv * lnw[2 * tid]     + lnb[2 * tid];
    float o1 = (v.y - mu) * inv * lnw[2 * tid + 1] + lnb[2 * tid + 1];
    *(float2*)&g_hn[(long long)g * DM + 2 * tid] = make_float2(o0, o1);
    g_hnS[(long long)g * 256 + tid] = split_bf16_pair(o0, o1);
}

// ---------------- attention scalar score ----------------
__global__ void k_score(const float* __restrict__ w2, const float* __restrict__ b2) {
    int g = blockIdx.x;
    int tid = threadIdx.x;
    float v = g_s1[(long long)g * 128 + tid] * w2[tid];
    v = bsum(v);
    if (tid == 0) g_scoreb[g] = v + b2[0];
}

// ---------------- softmax (+ zero pooled) ----------------
__global__ void k_softmax() {
    const int n = NB * L_TOK;
    __shared__ float red[32];
    __shared__ float s_max, s_sum;
    int tid = threadIdx.x;
    if (tid < DM) g_pooled[tid] = 0.f;
    float m = -1e30f;
    for (int i = tid; i < n; i += 1024) m = fmaxf(m, g_scoreb[i]);
    #pragma unroll
    for (int o = 16; o > 0; o >>= 1) m = fmaxf(m, __shfl_xor_sync(0xffffffffu, m, o));
    if ((tid & 31) == 0) red[tid >> 5] = m;
    __syncthreads();
    if (tid < 32) {
        float v = red[tid];
        #pragma unroll
        for (int o = 16; o > 0; o >>= 1) v = fmaxf(v, __shfl_xor_sync(0xffffffffu, v, o));
        if (tid == 0) s_max = v;
    }
    __syncthreads();
    float m0 = s_max;
    float s = 0.f;
    for (int i = tid; i < n; i += 1024) s += expf(g_scoreb[i] - m0);
    #pragma unroll
    for (int o = 16; o > 0; o >>= 1) s += __shfl_xor_sync(0xffffffffu, s, o);
    if ((tid & 31) == 0) red[tid >> 5] = s;
    __syncthreads();
    if (tid < 32) {
        float v = red[tid];
        #pragma unroll
        for (int o = 16; o > 0; o >>= 1) v += __shfl_xor_sync(0xffffffffu, v, o);
        if (tid == 0) s_sum = v;
    }
    __syncthreads();
    float inv = 1.f / s_sum;
    for (int i = tid; i < n; i += 1024) g_wts[i] = expf(g_scoreb[i] - m0) * inv;
}

// ---------------- pooled ----------------
#define PBLK 120
__global__ __launch_bounds__(256) void k_pooled() {
    const int total = NB * L_TOK;
    int per = (total + PBLK - 1) / PBLK;
    int g0 = blockIdx.x * per;
    int g1 = g0 + per; if (g1 > total) g1 = total;
    int tid = threadIdx.x;
    float a0 = 0.f, a1 = 0.f;
    for (int g = g0; g < g1; g++) {
        float w = g_wts[g];
        float2 v = *(const float2*)&g_hn[(long long)g * DM + 2 * tid];
        a0 = fmaf(w, v.x, a0);
        a1 = fmaf(w, v.y, a1);
    }
    atomicAdd(&g_pooled[2 * tid], a0);
    atomicAdd(&g_pooled[2 * tid + 1], a1);
}

// ---------------- final classifier ----------------
__global__ void k_final(const float* __restrict__ cls_w, const float* __restrict__ cls_b,
                        float* __restrict__ out, int out_size) {
    int tid = threadIdx.x;
    int cls = tid >> 5, lane = tid & 31;
    float acc = 0.f;
    for (int d = lane; d < DM; d += 32) acc += g_pooled[d] * cls_w[cls * DM + d];
    #pragma unroll
    for (int o = 16; o > 0; o >>= 1) acc += __shfl_xor_sync(0xffffffffu, acc, o);
    __shared__ float lg[2];
    if (lane == 0) lg[cls] = acc;
    __syncthreads();
    if (tid == 0) {
        float l0 = lg[0] + cls_b[0], l1 = lg[1] + cls_b[1];
        float m = fmaxf(l0, l1);
        float e0 = expf(l0 - m), e1 = expf(l1 - m);
        float s = e0 + e1;
        out[0] = l0;
        out[1] = l1;
        if (out_size >= 4) { out[2] = e0 / s; out[3] = e1 / s; }
    }
}

// ---------------- launch ----------------
static inline void launch_split(const float* src, void* dst, long long npairs) {
    k_split<<<(int)((npairs + 255) / 256), 256>>>(src, (uint2*)dst, npairs);
}

extern "C" void kernel_launch(void* const* d_in, const int* in_sizes, int n_in,
                              void* d_out, int out_size) {
    const float* x        = (const float*)d_in[0];
    const float* fc1_w    = (const float*)d_in[1];
    const float* fc1_b    = (const float*)d_in[2];
    const float* in_proj_w= (const float*)d_in[3];
    const float* conv_w   = (const float*)d_in[4];
    const float* conv_b   = (const float*)d_in[5];
    const float* dt_bias  = (const float*)d_in[6];
    const float* A_log    = (const float*)d_in[7];
    const float* Dh       = (const float*)d_in[8];
    const float* norm_w   = (const float*)d_in[9];
    const float* out_proj_w=(const float*)d_in[10];
    const float* ln_w     = (const float*)d_in[11];
    const float* ln_b     = (const float*)d_in[12];
    const float* attn_w1  = (const float*)d_in[13];
    const float* attn_b1  = (const float*)d_in[14];
    const float* attn_w2  = (const float*)d_in[15];
    const float* attn_b2  = (const float*)d_in[16];
    const float* cls_w    = (const float*)d_in[17];
    const float* cls_b    = (const float*)d_in[18];
    float* out = (float*)d_out;

    void *p_hcur, *p_zx, *p_y, *p_s1;
    void *p_xS, *p_fc1wS, *p_ipw4, *p_opw4, *p_aw1S, *p_hcurB, *p_yB, *p_hnS;
    cudaGetSymbolAddress(&p_hcur,  g_hcur);
    cudaGetSymbolAddress(&p_zx,    g_zx);
    cudaGetSymbolAddress(&p_y,     g_y);
    cudaGetSymbolAddress(&p_s1,    g_s1);
    cudaGetSymbolAddress(&p_xS,    g_xS);
    cudaGetSymbolAddress(&p_fc1wS, g_fc1wS);
    cudaGetSymbolAddress(&p_ipw4,  g_ipw4);
    cudaGetSymbolAddress(&p_opw4,  g_opw4);
    cudaGetSymbolAddress(&p_aw1S,  g_aw1S);
    cudaGetSymbolAddress(&p_hcurB, g_hcurB);
    cudaGetSymbolAddress(&p_yB,    g_yB);
    cudaGetSymbolAddress(&p_hnS,   g_hnS);

    cudaFuncSetAttribute(tgemm,  cudaFuncAttributeMaxDynamicSharedMemorySize, TG_SMEM);
    cudaFuncSetAttribute(tgemm2, cudaFuncAttributeMaxDynamicSharedMemorySize, TG2_SMEM);
    cudaFuncSetAttribute(k_intra_mma, cudaFuncAttributeMaxDynamicSharedMemorySize, SMEM_INTRA_MMA);

    // splits: x + fc1_w (old layout), in_proj_w (W-layout)
    {
        long long tot = NPX + NPF;
        k_split_all<<<(int)((tot + 255) / 256), 256>>>(x, fc1_w);
    }
    {
        long long nu4 = (long long)6 * DPROJ * 128;
        k_splitW<<<(int)((nu4 + 255) / 256), 256>>>(in_proj_w, (uint4*)p_ipw4, nu4, 512);
    }
    // fc1 (op=2, aux -> hcurB in A-layout)
    {
        dim3 grid((DM + 127) / 128, (L_TOK + 127) / 128, 1);
        tgemm<<<grid, 256, TG_SMEM>>>((const uint2*)p_xS, 0, (const uint2*)p_fc1wS, 0, fc1_b,
                                      (float*)p_hcur, 0, (unsigned*)p_hcurB, L_TOK, DM, 512, 2, 0);
    }
    // branch prep + pad zero
    {
        long long tot = (long long)L_TOK * 128 + (long long)NB * (LP - L_TOK) * 128;
        k_prep2<<<(int)((tot + 255) / 256), 256>>>();
    }

    for (int j = 0; j < 2; j++) {
        // in_proj (tgemm2, all-cp16)
        {
            dim3 g1((DPROJ + 127) / 128, (LP + 127) / 128, NB);
            tgemm2<<<g1, 256, TG2_SMEM>>>((const uint2*)p_hcurB, (long long)LP * 128,
                                          (const uint4*)p_ipw4, (long long)DPROJ * 128,
                                          (float*)p_zx, (long long)LP * DPROJ, nullptr,
                                          LP, DPROJ, 256, 0, j);
        }
        k_convfused<<<dim3(NC, NB), 256>>>(conv_w, conv_b, dt_bias, A_log, j);
        k_intra_mma<<<dim3(NC, NH, NB), 256, SMEM_INTRA_MMA>>>();
        k_rec<<<dim3(NB * NH, 4), 256>>>();
        k_inter_mma<<<dim3(NC, NH, NB), 256>>>(Dh, j);
        k_gate<<<dim3(LP, NB), 256>>>(norm_w, j);
        if (j == 0) {
            long long nu4 = (long long)6 * DM * 256;
            k_splitW<<<(int)((nu4 + 255) / 256), 256>>>(out_proj_w, (uint4*)p_opw4, nu4, 1024);
        }
        // out_proj (tgemm2) + residual + aux hcurB (A-layout) for next layer
        {
            dim3 g2((DM + 127) / 128, (LP + 127) / 128, NB);
            tgemm2<<<g2, 256, TG2_SMEM>>>((const uint2*)p_yB, (long long)LP * 256,
                                          (const uint4*)p_opw4, (long long)DM * 256,
                                          (float*)p_hcur, (long long)LP * DM,
                                          (j == 0) ? (unsigned*)p_hcurB : nullptr,
                                          LP, DM, 512, 1, j);
        }
    }

    // final head
    k_ln<<<NB * L_TOK, 256>>>(ln_w, ln_b);
    launch_split(attn_w1, p_aw1S, (long long)128 * 256);
    {
        dim3 ga(1, (NB * L_TOK + 127) / 128, 1);
        tgemm<<<ga, 256, TG_SMEM>>>((const uint2*)p_hnS, 0, (const uint2*)p_aw1S, 0, attn_b1,
                                    (float*)p_s1, 0, nullptr, NB * L_TOK, 128, 256, 3, 0);
    }
    k_score<<<NB * L_TOK, 128>>>(attn_w2, attn_b2);
    k_softmax<<<1, 1024>>>();
    k_pooled<<<PBLK, 256>>>();
    k_final<<<1, 64>>>(cls_w, cls_b, out, out_size);
}

// round 15
// speedup vs baseline: 1.3303x; 1.1000x over previous
#include <cuda_runtime.h>
#include <cuda_bf16.h>
#include <math.h>

// ---------------- problem constants ----------------
#define L_TOK 10000
#define LP    10048
#define NC    157
#define Q     64
#define DM    512
#define DI    1024
#define DS    64
#define NH    16
#define HD    64
#define DXBC  1152
#define DPROJ 2192
#define NB    3

// ---------------- scratch ----------------
__device__ __align__(16) float g_hcur [(size_t)NB*LP*DM];
__device__ __align__(16) float g_zx   [(size_t)NB*LP*DPROJ];
__device__ __align__(16) float g_xs   [(size_t)NB*LP*DI];
__device__ __align__(16) float g_Bm   [(size_t)NB*LP*DS];
__device__ __align__(16) float g_Cm   [(size_t)NB*LP*DS];
__device__ __align__(16) float g_dtv  [(size_t)NB*LP*NH];
__device__ __align__(16) float g_cum  [(size_t)NB*NH*LP];
__device__ __align__(16) float g_y    [(size_t)NB*LP*DI];
__device__ __align__(16) float g_schunk[(size_t)NB*NH*NC*DS*HD];
__device__ __align__(16) float g_sbef  [(size_t)NB*NH*NC*DS*HD];
__device__ __align__(16) float g_hn   [(size_t)NB*L_TOK*DM];
__device__ __align__(16) float g_s1   [(size_t)NB*L_TOK*128];
__device__ float g_scoreb[NB*L_TOK];
__device__ float g_wts   [NB*L_TOK];
__device__ float g_pooled[DM];

// split-bf16 (old layout, for tgemm fc1/attn path)
__device__ __align__(16) uint2 g_xS   [(size_t)L_TOK*512];
__device__ __align__(16) uint2 g_fc1wS[(size_t)DM*512];
__device__ __align__(16) uint2 g_aw1S [(size_t)128*256];
__device__ __align__(16) uint2 g_hnS  [(size_t)NB*L_TOK*256];
// W split, ktile-fragment layout
__device__ __align__(16) uint4 g_ipw4 [(size_t)6*DPROJ*128];
__device__ __align__(16) uint4 g_opw4 [(size_t)6*DM*256];
// B/C split, fragment layout: per row 16 x uint4 (4 kt x 4 tig)
__device__ __align__(16) uint4 g_CmS [(size_t)NB*LP*16];
__device__ __align__(16) uint4 g_BmS [(size_t)NB*LP*16];
// A plain-bf16, ktile layout
__device__ __align__(16) unsigned g_hcurB[(size_t)NB*LP*256];
__device__ __align__(16) unsigned g_yB   [(size_t)NB*LP*512];

__device__ __forceinline__ int a2i(int p) {
    return (p & ~7) | ((p & 3) << 1) | ((p >> 2) & 1);
}

// ---------------- helpers ----------------
__device__ __forceinline__ float bsum(float v) {
    __shared__ float sh[32];
    int lane = threadIdx.x & 31, w = threadIdx.x >> 5;
    #pragma unroll
    for (int o = 16; o > 0; o >>= 1) v += __shfl_xor_sync(0xffffffffu, v, o);
    if (lane == 0) sh[w] = v;
    __syncthreads();
    int nw = blockDim.x >> 5;
    v = (threadIdx.x < nw) ? sh[threadIdx.x] : 0.f;
    if (w == 0) {
        #pragma unroll
        for (int o = 16; o > 0; o >>= 1) v += __shfl_xor_sync(0xffffffffu, v, o);
        if (threadIdx.x == 0) sh[0] = v;
    }
    __syncthreads();
    float r = sh[0];
    __syncthreads();
    return r;
}

__device__ __forceinline__ unsigned pack_bf16(float f0, float f1) {
    unsigned r;
    asm("cvt.rn.bf16x2.f32 %0, %1, %2;" : "=r"(r) : "f"(f1), "f"(f0));
    return r;
}

__device__ __forceinline__ uint2 split_bf16_pair(float f0, float f1) {
    unsigned hp, lp;
    asm("cvt.rn.bf16x2.f32 %0, %1, %2;" : "=r"(hp) : "f"(f1), "f"(f0));
    __nv_bfloat162 h = *reinterpret_cast<__nv_bfloat162*>(&hp);
    float r0 = f0 - __bfloat162float(h.x);
    float r1 = f1 - __bfloat162float(h.y);
    asm("cvt.rn.bf16x2.f32 %0, %1, %2;" : "=r"(lp) : "f"(r1), "f"(r0));
    uint2 q; q.x = hp; q.y = lp;
    return q;
}

__global__ void k_split(const float* __restrict__ in, uint2* __restrict__ out, long long npairs) {
    long long i = (long long)blockIdx.x * 256 + threadIdx.x;
    if (i >= npairs) return;
    float2 v = ((const float2*)in)[i];
    out[i] = split_bf16_pair(v.x, v.y);
}

// merged split of x, fc1_w (old layout) + in_proj_w (fragment W layout)
#define NPX ((long long)L_TOK * 512)
#define NPF ((long long)DM * 512)
#define NW4 ((long long)6 * DPROJ * 128)
__global__ void k_split_all(const float* __restrict__ x, const float* __restrict__ fw,
                            const float* __restrict__ iw) {
    long long i = (long long)blockIdx.x * 256 + threadIdx.x;
    if (i < NPX) {
        float2 v = ((const float2*)x)[i];
        g_xS[i] = split_bf16_pair(v.x, v.y);
        return;
    }
    if (i < NPX + NPF) {
        long long off = i - NPX;
        float2 v = ((const float2*)fw)[off];
        g_fc1wS[off] = split_bf16_pair(v.x, v.y);
        return;
    }
    long long u = i - NPX - NPF;
    if (u >= NW4) return;
    long long row = u >> 7;              // 128 uint4 per row (K=512)
    int rem = (int)(u & 127);
    int kt = rem >> 2, tig = rem & 3;
    int k0 = kt * 16 + tig * 2;
    const float* rp = iw + row * 512;
    float2 va = *(const float2*)&rp[k0];
    float2 vb = *(const float2*)&rp[k0 + 8];
    uint2 sa = split_bf16_pair(va.x, va.y);
    uint2 sb = split_bf16_pair(vb.x, vb.y);
    g_ipw4[u] = make_uint4(sa.x, sa.y, sb.x, sb.y);
}

// split W into ktile-fragment layout (out_proj)
__global__ void k_splitW(const float* __restrict__ src, uint4* __restrict__ dst,
                         long long nu4, int K) {
    long long u = (long long)blockIdx.x * 256 + threadIdx.x;
    if (u >= nu4) return;
    int perrow = K >> 2;
    long long row = u / perrow;
    int rem = (int)(u % perrow);
    int kt = rem >> 2, tig = rem & 3;
    int k0 = kt * 16 + tig * 2;
    const float* rp = src + row * K;
    float2 va = *(const float2*)&rp[k0];
    float2 vb = *(const float2*)&rp[k0 + 8];
    uint2 sa = split_bf16_pair(va.x, va.y);
    uint2 sb = split_bf16_pair(vb.x, vb.y);
    dst[u] = make_uint4(sa.x, sa.y, sb.x, sb.y);
}

// split B,C into fragment layout (per layer)
__global__ void k_splitBC() {
    const long long N1 = (long long)NB * LP * 16;
    long long u = (long long)blockIdx.x * 256 + threadIdx.x;
    const float* src; uint4* dst; long long v;
    if (u < N1) { src = g_Cm; dst = g_CmS; v = u; }
    else if (u < 2 * N1) { src = g_Bm; dst = g_BmS; v = u - N1; }
    else return;
    long long row = v >> 4;
    int rem = (int)(v & 15);
    int kt = rem >> 2, tig = rem & 3;
    int k0 = kt * 16 + tig * 2;
    float2 va = *(const float2*)&src[row * DS + k0];
    float2 vb = *(const float2*)&src[row * DS + k0 + 8];
    uint2 sa = split_bf16_pair(va.x, va.y);
    uint2 sb = split_bf16_pair(vb.x, vb.y);
    dst[v] = make_uint4(sa.x, sa.y, sb.x, sb.y);
}

__device__ __forceinline__ void mma16(float c[4], const unsigned a[4], const unsigned b[2]) {
    asm volatile(
        "mma.sync.aligned.m16n8k16.row.col.f32.bf16.bf16.f32 "
        "{%0,%1,%2,%3},{%4,%5,%6,%7},{%8,%9},{%0,%1,%2,%3};"
        : "+f"(c[0]), "+f"(c[1]), "+f"(c[2]), "+f"(c[3])
        : "r"(a[0]), "r"(a[1]), "r"(a[2]), "r"(a[3]), "r"(b[0]), "r"(b[1]));
}

__device__ __forceinline__ void cp8(unsigned dst, const void* src, bool pred) {
    int sz = pred ? 8 : 0;
    asm volatile("cp.async.ca.shared.global [%0], [%1], 8, %2;" :: "r"(dst), "l"(src), "r"(sz));
}
__device__ __forceinline__ void cp16(unsigned dst, const void* src, bool pred) {
    int sz = pred ? 16 : 0;
    asm volatile("cp.async.cg.shared.global [%0], [%1], 16, %2;" :: "r"(dst), "l"(src), "r"(sz));
}

// ---------------- tgemm: 3xBF16 split both sides (fc1, attn1) ----------------
#define STAGES 4
#define S4 130
#define TG_SMEM (STAGES * 4 * S4 * 16 * 2)

__global__ __launch_bounds__(256, 2) void tgemm(
    const uint2* __restrict__ A, long long sA,
    const uint2* __restrict__ W, long long sW,
    const float* __restrict__ bias,
    float* __restrict__ C, long long sC,
    unsigned* __restrict__ Caux,
    int M, int N, int Kp, int op, int joff)
{
    extern __shared__ uint4 sm4[];
    uint4* As = sm4;
    uint4* Ws = sm4 + STAGES * 4 * S4;

    int z = blockIdx.z;
    A += (long long)z * sA;
    C += (long long)z * sC;
    W += (long long)(2 * z + joff) * sW;
    if (Caux) Caux += (long long)z * (sC >> 1);

    int tid = threadIdx.x;
    int warp = tid >> 5, lane = tid & 31;
    int wm = warp & 3, wn = warp >> 2;
    int g = lane >> 2, tig = lane & 3;
    int row0 = blockIdx.y * 128, col0 = blockIdx.x * 128;

    int ar = tid >> 1, half = tid & 1;
    bool aok = (row0 + ar) < M;
    bool wok = (col0 + ar) < N;
    const uint2* Ag = A + (long long)(row0 + ar) * Kp + half * 4;
    const uint2* Wg = W + (long long)(col0 + ar) * Kp + half * 4;
    unsigned aSm = (unsigned)__cvta_generic_to_shared(As);
    unsigned wSm = (unsigned)__cvta_generic_to_shared(Ws);

    float c[2][8][4];
    #pragma unroll
    for (int mt = 0; mt < 2; mt++)
        #pragma unroll
        for (int nt = 0; nt < 8; nt++)
            #pragma unroll
            for (int q = 0; q < 4; q++) c[mt][nt][q] = 0.f;

    int nK = Kp >> 3;

    #define ISSUE(kt, slot) do { \
        const uint2* _Ap = Ag + (kt) * 8; \
        const uint2* _Wp = Wg + (kt) * 8; \
        _Pragma("unroll") \
        for (int i = 0; i < 4; i++) { \
            unsigned off = (unsigned)((((slot) * 4 + i) * S4 + ar) * 16 + half * 8); \
            cp8(aSm + off, _Ap + i, aok); \
            cp8(wSm + off, _Wp + i, wok); \
        } \
    } while (0)

    #pragma unroll
    for (int s = 0; s < STAGES - 1; s++) {
        if (s < nK) ISSUE(s, s);
        asm volatile("cp.async.commit_group;");
    }

    for (int kt = 0; kt < nK; kt++) {
        asm volatile("cp.async.wait_group %0;" :: "n"(STAGES - 2));
        __syncthreads();

        int slot = kt & 3;
        const uint4* Ab = As + slot * 4 * S4;
        const uint4* Wb = Ws + slot * 4 * S4;

        uint4 fa[2][2];
        #pragma unroll
        for (int mt = 0; mt < 2; mt++) {
            int m0 = wm * 32 + mt * 16;
            fa[mt][0] = Ab[tig * S4 + m0 + g];
            fa[mt][1] = Ab[tig * S4 + m0 + g + 8];
        }
        unsigned ahi[2][4], alo[2][4];
        #pragma unroll
        for (int mt = 0; mt < 2; mt++) {
            ahi[mt][0] = fa[mt][0].x; ahi[mt][1] = fa[mt][1].x;
            ahi[mt][2] = fa[mt][0].z; ahi[mt][3] = fa[mt][1].z;
            alo[mt][0] = fa[mt][0].y; alo[mt][1] = fa[mt][1].y;
            alo[mt][2] = fa[mt][0].w; alo[mt][3] = fa[mt][1].w;
        }
        #pragma unroll
        for (int nt = 0; nt < 8; nt++) {
            int n0 = wn * 64 + nt * 8;
            uint4 fb = Wb[tig * S4 + n0 + g];
            unsigned bhi[2] = {fb.x, fb.z};
            unsigned blo[2] = {fb.y, fb.w};
            #pragma unroll
            for (int mt = 0; mt < 2; mt++) {
                mma16(c[mt][nt], alo[mt], bhi);
                mma16(c[mt][nt], ahi[mt], blo);
                mma16(c[mt][nt], ahi[mt], bhi);
            }
        }

        int pre = kt + STAGES - 1;
        if (pre < nK) ISSUE(pre, pre & 3);
        asm volatile("cp.async.commit_group;");
    }
    asm volatile("cp.async.wait_all;");

    #pragma unroll
    for (int mt = 0; mt < 2; mt++) {
        #pragma unroll
        for (int nt = 0; nt < 8; nt++) {
            int cc = col0 + wn * 64 + nt * 8 + 2 * tig;
            if (cc >= N) continue;
            #pragma unroll
            for (int hf = 0; hf < 2; hf++) {
                int r = row0 + wm * 32 + mt * 16 + g + hf * 8;
                if (r >= M) continue;
                float v0 = c[mt][nt][hf * 2 + 0];
                float v1 = c[mt][nt][hf * 2 + 1];
                long long ci = (long long)r * N + cc;
                if (op == 0) {
                    *(float2*)&C[ci] = make_float2(v0, v1);
                } else if (op == 1) {
                    float2 o = *(float2*)&C[ci];
                    o.x += v0; o.y += v1;
                    *(float2*)&C[ci] = o;
                } else if (op == 2) {
                    v0 = fmaxf(v0 + bias[cc], 0.f);
                    v1 = fmaxf(v1 + bias[cc + 1], 0.f);
                    *(float2*)&C[ci] = make_float2(v0, v1);
                    if (Caux) Caux[(long long)r * (N >> 1) + a2i(cc >> 1)] = pack_bf16(v0, v1);
                } else {
                    v0 += bias[cc]; v1 += bias[cc + 1];
                    *(float2*)&C[ci] = make_float2(tanhf(v0), tanhf(v1));
                }
            }
        }
    }
    #undef ISSUE
}

// ---------------- tgemm2: bf16-A x split-W, all cp16, NSLOT=4 deep pipeline ----------------
#define NSLOT 4
#define TG2_SMEM (NSLOT * 2 * (128 * 32 + 128 * 64))

__global__ __launch_bounds__(256, 2) void tgemm2(
    const uint2* __restrict__ A, long long sA,
    const uint4* __restrict__ W, long long sW,
    float* __restrict__ C, long long sC,
    unsigned* __restrict__ Caux,
    int M, int N, int Kp, int op, int joff)
{
    extern __shared__ char smc[];
    uint2* Asm = (uint2*)smc;
    uint4* Wsm = (uint4*)(smc + NSLOT * 2 * 128 * 32);

    int z = blockIdx.z;
    A += (long long)z * sA;
    C += (long long)z * sC;
    W += (long long)(2 * z + joff) * sW;
    if (Caux) Caux += (long long)z * (sC >> 1);

    int tid = threadIdx.x;
    int warp = tid >> 5, lane = tid & 31;
    int wm = warp & 1, wn = warp >> 1;
    int g = lane >> 2, tig = lane & 3;
    int row0 = blockIdx.y * 128, col0 = blockIdx.x * 128;

    int ar = tid >> 1, half = tid & 1;
    bool aok = (row0 + ar) < M;
    bool wok = (col0 + ar) < N;
    int pr = Kp >> 1;
    const uint2* Ag = A + (long long)(row0 + ar) * pr + half * 2;
    const uint4* Wg = W + (long long)(col0 + ar) * pr + half * 2;
    unsigned aB = (unsigned)__cvta_generic_to_shared(Asm);
    unsigned wB = (unsigned)__cvta_generic_to_shared(Wsm);

    float c[4][4][4];
    #pragma unroll
    for (int mt = 0; mt < 4; mt++)
        #pragma unroll
        for (int nt = 0; nt < 4; nt++)
            #pragma unroll
            for (int q = 0; q < 4; q++) c[mt][nt][q] = 0.f;

    int nG = Kp >> 4;

    #define ISSUEG(gi, s) do { \
        _Pragma("unroll") \
        for (int u = 0; u < 2; u++) { \
            int _kt = (gi) * 2 + u; \
            cp16(aB + (unsigned)((((s) * 2 + u) * 128 + ar) * 32 + half * 16), Ag + _kt * 4, aok); \
            cp16(wB + (unsigned)((((s) * 2 + u) * 128 + ar) * 64 + half * 32),      Wg + _kt * 4,     wok); \
            cp16(wB + (unsigned)((((s) * 2 + u) * 128 + ar) * 64 + half * 32 + 16), Wg + _kt * 4 + 1, wok); \
        } \
    } while (0)

    ISSUEG(0, 0);
    asm volatile("cp.async.commit_group;");
    if (1 < nG) ISSUEG(1, 1);
    asm volatile("cp.async.commit_group;");
    if (2 < nG) ISSUEG(2, 2);
    asm volatile("cp.async.commit_group;");

    int sc = 0, si = 3;
    for (int gi = 0; gi < nG; gi++) {
        asm volatile("cp.async.wait_group 2;");
        __syncthreads();

        #pragma unroll
        for (int u = 0; u < 2; u++) {
            const uint2* Ab = Asm + (sc * 2 + u) * 128 * 4;
            const uint4* Wb = Wsm + (sc * 2 + u) * 128 * 4;

            unsigned a[4][4];
            #pragma unroll
            for (int mt = 0; mt < 4; mt++) {
                int m0 = wm * 64 + mt * 16;
                uint2 q0 = Ab[(m0 + g) * 4 + tig];
                uint2 q1 = Ab[(m0 + g + 8) * 4 + tig];
                a[mt][0] = q0.x; a[mt][1] = q1.x;
                a[mt][2] = q0.y; a[mt][3] = q1.y;
            }
            #pragma unroll
            for (int nt = 0; nt < 4; nt++) {
                int n0 = wn * 32 + nt * 8;
                uint4 fb = Wb[(n0 + g) * 4 + tig];
                unsigned bhi[2] = {fb.x, fb.z};
                unsigned blo[2] = {fb.y, fb.w};
                #pragma unroll
                for (int mt = 0; mt < 4; mt++) {
                    mma16(c[mt][nt], a[mt], blo);
                    mma16(c[mt][nt], a[mt], bhi);
                }
            }
        }

        int pre = gi + 3;
        if (pre < nG) ISSUEG(pre, si);
        asm volatile("cp.async.commit_group;");
        sc++; if (sc == NSLOT) sc = 0;
        si++; if (si == NSLOT) si = 0;
    }
    asm volatile("cp.async.wait_all;");

    #pragma unroll
    for (int mt = 0; mt < 4; mt++) {
        #pragma unroll
        for (int nt = 0; nt < 4; nt++) {
            int cc = col0 + wn * 32 + nt * 8 + 2 * tig;
            if (cc >= N) continue;
            #pragma unroll
            for (int hf = 0; hf < 2; hf++) {
                int r = row0 + wm * 64 + mt * 16 + g + hf * 8;
                if (r >= M) continue;
                float v0 = c[mt][nt][hf * 2 + 0];
                float v1 = c[mt][nt][hf * 2 + 1];
                long long ci = (long long)r * N + cc;
                if (op == 0) {
                    *(float2*)&C[ci] = make_float2(v0, v1);
                } else {
                    float2 o = *(float2*)&C[ci];
                    o.x += v0; o.y += v1;
                    *(float2*)&C[ci] = o;
                    if (Caux) Caux[(long long)r * (N >> 1) + a2i(cc >> 1)] = pack_bf16(o.x, o.y);
                }
            }
        }
    }
    #undef ISSUEG
}

// ---------------- branch prep + pad-row zeroing ----------------
__global__ void k_prep2() {
    long long i = (long long)blockIdx.x * 256 + threadIdx.x;
    const long long mainN = (long long)L_TOK * 128;
    if (i < mainN) {
        int t = (int)(i >> 7), q = (int)(i & 127);
        float4 v = *((const float4*)g_hcur + (long long)t * 128 + q);
        int d0 = q * 4, p = q * 2;
        *(float4*)&g_hcur[(long long)LP * DM + (long long)t * DM + (508 - d0)] =
            make_float4(v.w, v.z, v.y, v.x);
        g_hcurB[(long long)LP * 256 + (long long)t * 256 + a2i(255 - p)] = pack_bf16(v.y, v.x);
        g_hcurB[(long long)LP * 256 + (long long)t * 256 + a2i(254 - p)] = pack_bf16(v.w, v.z);
        int tt = (t % 100) * 100 + t / 100;
        *(float4*)&g_hcur[2LL * LP * DM + (long long)tt * DM + d0] = v;
        g_hcurB[2LL * LP * 256 + (long long)tt * 256 + a2i(p)]     = pack_bf16(v.x, v.y);
        g_hcurB[2LL * LP * 256 + (long long)tt * 256 + a2i(p + 1)] = pack_bf16(v.z, v.w);
        return;
    }
    long long j = i - mainN;
    if (j >= (long long)NB * (LP - L_TOK) * 128) return;
    int b = (int)(j / ((LP - L_TOK) * 128));
    int rem = (int)(j % ((LP - L_TOK) * 128));
    int t = L_TOK + rem / 128, q = rem % 128;
    *(float4*)&g_hcur[((long long)b * LP + t) * DM + q * 4] = make_float4(0.f, 0.f, 0.f, 0.f);
    g_hcurB[((long long)b * LP + t) * 256 + q * 2]     = 0u;
    g_hcurB[((long long)b * LP + t) * 256 + q * 2 + 1] = 0u;
}

// ---------------- fused conv + silu + dt + cumsum ----------------
__global__ __launch_bounds__(256) void k_convfused(
    const float* __restrict__ cw, const float* __restrict__ cb,
    const float* __restrict__ dt_bias, const float* __restrict__ A_log, int j)
{
    __shared__ float av_s[NH * 64];
    int c = blockIdx.x, b = blockIdx.y;
    int lidx = 2 * b + j;
    int tid = threadIdx.x;
    const float* zbase = g_zx + (long long)b * LP * DPROJ;
    int gt0 = c * Q;

    for (int cc = tid; cc < DXBC; cc += 256) {
        const float* col = zbase + DI + cc;
        const float* wp = cw + (long long)(lidx * DXBC + cc) * 4;
        float w0 = wp[0], w1 = wp[1], w2 = wp[2], w3 = wp[3];
        float bia = cb[lidx * DXBC + cc];
        float h3 = (gt0 - 3 >= 0) ? col[(long long)(gt0 - 3) * DPROJ] : 0.f;
        float h2 = (gt0 - 2 >= 0) ? col[(long long)(gt0 - 2) * DPROJ] : 0.f;
        float h1 = (gt0 - 1 >= 0) ? col[(long long)(gt0 - 1) * DPROJ] : 0.f;
        #pragma unroll 4
        for (int t = 0; t < Q; t++) {
            int gt = gt0 + t;
            float cur = col[(long long)gt * DPROJ];
            float a = bia + w0 * h3 + w1 * h2 + w2 * h1 + w3 * cur;
            float v = a / (1.f + __expf(-a));
            if (gt >= L_TOK) v = 0.f;
            long long tb = (long long)b * LP + gt;
            if (cc < DI)            g_xs[tb * DI + cc] = v;
            else if (cc < DI + DS)  g_Bm[tb * DS + (cc - DI)] = v;
            else                    g_Cm[tb * DS + (cc - DI - DS)] = v;
            h3 = h2; h2 = h1; h1 = cur;
        }
    }

    #pragma unroll
    for (int k = 0; k < 4; k++) {
        int idx = tid + k * 256;
        int h = idx & 15, t = idx >> 4;
        int gt = gt0 + t;
        float draw = zbase[(long long)gt * DPROJ + DI + DXBC + h];
        float xv = draw + dt_bias[lidx * NH + h];
        float sp = (xv > 20.f) ? xv : log1pf(expf(xv));
        if (gt >= L_TOK) sp = 0.f;
        g_dtv[((long long)b * LP + gt) * NH + h] = sp;
        float Ah = -expf(A_log[lidx * NH + h]);
        av_s[h * 64 + t] = sp * Ah;
    }
    __syncthreads();

    int warp = tid >> 5, lane = tid & 31;
    #pragma unroll
    for (int hh = 0; hh < 2; hh++) {
        int h = warp * 2 + hh;
        float x1 = av_s[h * 64 + lane];
        float x2 = av_s[h * 64 + 32 + lane];
        #pragma unroll
        for (int o = 1; o < 32; o <<= 1) { float yv = __shfl_up_sync(0xffffffffu, x1, o); if (lane >= o) x1 += yv; }
        #pragma unroll
        for (int o = 1; o < 32; o <<= 1) { float yv = __shfl_up_sync(0xffffffffu, x2, o); if (lane >= o) x2 += yv; }
        float tot1 = __shfl_sync(0xffffffffu, x1, 31);
        x2 += tot1;
        long long base = (long long)(b * NH + h) * LP + (long long)c * Q;
        g_cum[base + lane] = x1;
        g_cum[base + 32 + lane] = x2;
    }
}

// ---------------- intra-chunk (tensor-core); C/B tiles copied pre-split ----------------
#define SMEM_INTRA_MMA (4096 * 16 + 512)
__global__ __launch_bounds__(256) void k_intra_mma() {
    extern __shared__ uint4 smu[];
    uint4* sC  = smu;            // row-major-frag: [row*16 + kt*4 + tig]
    uint4* sB  = smu + 1024;     // row-major-frag (aliased by split-P old layout in stage 2)
    uint4* sUT = smu + 2048;     // old layout [(ks*4+tig)*64 + row]
    uint4* sBw = smu + 3072;     // old layout
    float* scum = (float*)(smu + 4096);
    float* sdt  = scum + 64;

    int c = blockIdx.x, h = blockIdx.y, b = blockIdx.z;
    long long rowb = (long long)b * LP + (long long)c * Q;
    int tid = threadIdx.x;

    if (tid < 64) {
        scum[tid] = g_cum[(long long)(b * NH + h) * LP + (long long)c * Q + tid];
        sdt[tid]  = g_dtv[(rowb + tid) * NH + h];
    }
    __syncthreads();
    float T = scum[63];

    // copy pre-split C/B fragments (straight copy)
    {
        const uint4* gC = g_CmS + rowb * 16;
        const uint4* gB = g_BmS + rowb * 16;
        for (int i = tid; i < 1024; i += 256) {
            sC[i] = gC[i];
            sB[i] = gB[i];
        }
    }
    // UT / Bw (computed, old layout)
    for (int i = tid; i < 1024; i += 256) {
        int slot = i >> 6, row = i & 63;
        int ks = slot >> 2, tg = slot & 3;
        int k0 = ks * 16 + tg * 2;
        float u0 = sdt[k0]     * g_xs[(rowb + k0)     * DI + h * HD + row];
        float u1 = sdt[k0 + 1] * g_xs[(rowb + k0 + 1) * DI + h * HD + row];
        float u2 = sdt[k0 + 8] * g_xs[(rowb + k0 + 8) * DI + h * HD + row];
        float u3 = sdt[k0 + 9] * g_xs[(rowb + k0 + 9) * DI + h * HD + row];
        uint2 uh0 = split_bf16_pair(u0, u1);
        uint2 uh1 = split_bf16_pair(u2, u3);
        sUT[i] = make_uint4(uh0.x, uh0.y, uh1.x, uh1.y);
        float bw0 = g_Bm[(rowb + k0)     * DS + row] * __expf(T - scum[k0]);
        float bw1 = g_Bm[(rowb + k0 + 1) * DS + row] * __expf(T - scum[k0 + 1]);
        float bw2 = g_Bm[(rowb + k0 + 8) * DS + row] * __expf(T - scum[k0 + 8]);
        float bw3 = g_Bm[(rowb + k0 + 9) * DS + row] * __expf(T - scum[k0 + 9]);
        uint2 wh0 = split_bf16_pair(bw0, bw1);
        uint2 wh1 = split_bf16_pair(bw2, bw3);
        sBw[i] = make_uint4(wh0.x, wh0.y, wh1.x, wh1.y);
    }
    __syncthreads();

    int warp = tid >> 5, lane = tid & 31;
    int g = lane >> 2, tig = lane & 3;
    int r0 = (warp & 3) * 16, cbn = (warp >> 2) * 32;

    // stage 1: P_raw = C @ B^T (row-major-frag operand reads)
    float accP[4][4];
    #pragma unroll
    for (int nt = 0; nt < 4; nt++)
        #pragma unroll
        for (int q = 0; q < 4; q++) accP[nt][q] = 0.f;
    #pragma unroll
    for (int ks = 0; ks < 4; ks++) {
        uint4 fa0 = sC[(r0 + g) * 16 + ks * 4 + tig];
        uint4 fa1 = sC[(r0 + g + 8) * 16 + ks * 4 + tig];
        unsigned ahi[4] = {fa0.x, fa1.x, fa0.z, fa1.z};
        unsigned alo[4] = {fa0.y, fa1.y, fa0.w, fa1.w};
        #pragma unroll
        for (int nt = 0; nt < 4; nt++) {
            uint4 fb = sB[(cbn + nt * 8 + g) * 16 + ks * 4 + tig];
            unsigned bhi[2] = {fb.x, fb.z}, blo[2] = {fb.y, fb.w};
            mma16(accP[nt], alo, bhi);
            mma16(accP[nt], ahi, blo);
            mma16(accP[nt], ahi, bhi);
        }
    }
    __syncthreads();

    uint2* sP2 = (uint2*)sB;
    #pragma unroll
    for (int nt = 0; nt < 4; nt++) {
        int scol = cbn + nt * 8 + 2 * tig;
        int Pp = scol >> 1;
        int ksp = Pp >> 3, tslot = Pp & 3, halfp = (Pp >> 2) & 1;
        #pragma unroll
        for (int hf = 0; hf < 2; hf++) {
            int t = r0 + g + hf * 8;
            float v0 = accP[nt][hf * 2], v1 = accP[nt][hf * 2 + 1];
            v0 = (scol     <= t) ? v0 * __expf(scum[t] - scum[scol])     : 0.f;
            v1 = (scol + 1 <= t) ? v1 * __expf(scum[t] - scum[scol + 1]) : 0.f;
            sP2[((ksp * 4 + tslot) * 64 + t) * 2 + halfp] = split_bf16_pair(v0, v1);
        }
    }
    __syncthreads();

    // stage 2: Y = P @ U, S = Bw^T @ U (old-layout operands)
    float accY[4][4], accS[4][4];
    #pragma unroll
    for (int nt = 0; nt < 4; nt++)
        #pragma unroll
        for (int q = 0; q < 4; q++) { accY[nt][q] = 0.f; accS[nt][q] = 0.f; }
    uint4* sP = sB;
    #pragma unroll
    for (int ks = 0; ks < 4; ks++) {
        uint4 fp0 = sP[(ks * 4 + tig) * 64 + r0 + g];
        uint4 fp1 = sP[(ks * 4 + tig) * 64 + r0 + g + 8];
        unsigned phi[4] = {fp0.x, fp1.x, fp0.z, fp1.z};
        unsigned plo[4] = {fp0.y, fp1.y, fp0.w, fp1.w};
        uint4 fw0 = sBw[(ks * 4 + tig) * 64 + r0 + g];
        uint4 fw1 = sBw[(ks * 4 + tig) * 64 + r0 + g + 8];
        unsigned whi[4] = {fw0.x, fw1.x, fw0.z, fw1.z};
        unsigned wlo[4] = {fw0.y, fw1.y, fw0.w, fw1.w};
        #pragma unroll
        for (int nt = 0; nt < 4; nt++) {
            uint4 fb = sUT[(ks * 4 + tig) * 64 + cbn + nt * 8 + g];
            unsigned bhi[2] = {fb.x, fb.z}, blo[2] = {fb.y, fb.w};
            mma16(accY[nt], plo, bhi); mma16(accY[nt], phi, blo); mma16(accY[nt], phi, bhi);
            mma16(accS[nt], wlo, bhi); mma16(accS[nt], whi, blo); mma16(accS[nt], whi, bhi);
        }
    }

    long long sbase = ((long long)(b * NH + h) * NC + c) * 4096;
    #pragma unroll
    for (int nt = 0; nt < 4; nt++) {
        int p = cbn + nt * 8 + 2 * tig;
        #pragma unroll
        for (int hf = 0; hf < 2; hf++) {
            int r = r0 + g + hf * 8;
            *(float2*)&g_y[(rowb + r) * DI + h * HD + p] =
                make_float2(accY[nt][hf * 2], accY[nt][hf * 2 + 1]);
            *(float2*)&g_schunk[sbase + r * 64 + p] =
                make_float2(accS[nt][hf * 2], accS[nt][hf * 2 + 1]);
        }
    }
}

// ---------------- chunk-state recurrence (4-way split, prefetched) ----------------
__global__ __launch_bounds__(256) void k_rec() {
    int bh = blockIdx.x;
    int qd = blockIdx.y;
    int tid = threadIdx.x;
    int off = qd * 1024 + tid;
    float S[4], v[4], nv[4];
    #pragma unroll
    for (int i = 0; i < 4; i++) S[i] = 0.f;
    const float* cumrow = g_cum + (long long)bh * LP;
    long long base = (long long)bh * NC * 4096;
    #pragma unroll
    for (int i = 0; i < 4; i++) v[i] = g_schunk[base + off + i * 256];
    for (int c = 0; c < NC; c++) {
        float e = __expf(cumrow[c * Q + 63]);
        if (c + 1 < NC) {
            long long nb = base + 4096;
            #pragma unroll
            for (int i = 0; i < 4; i++) nv[i] = g_schunk[nb + off + i * 256];
        }
        #pragma unroll
        for (int i = 0; i < 4; i++) {
            g_sbef[base + off + i * 256] = S[i];
            S[i] = e * S[i] + v[i];
            v[i] = nv[i];
        }
        base += 4096;
    }
}

// ---------------- inter-chunk (tensor-core); C tile copied pre-split ----------------
__global__ __launch_bounds__(256) void k_inter_mma(const float* __restrict__ Dh, int j) {
    __shared__ uint4 sC[1024];    // row-major-frag
    __shared__ uint4 sST[1024];   // old layout
    __shared__ float scum[64];

    int c = blockIdx.x, h = blockIdx.y, b = blockIdx.z;
    long long rowb = (long long)b * LP + (long long)c * Q;
    long long sbase = ((long long)(b * NH + h) * NC + c) * 4096;
    int tid = threadIdx.x;

    if (tid < 64)
        scum[tid] = g_cum[(long long)(b * NH + h) * LP + (long long)c * Q + tid];

    {
        const uint4* gC = g_CmS + rowb * 16;
        for (int i = tid; i < 1024; i += 256) sC[i] = gC[i];
    }
    for (int i = tid; i < 1024; i += 256) {
        int slot = i >> 6, row = i & 63;
        int ks = slot >> 2, tg = slot & 3;
        int k0 = ks * 16 + tg * 2;
        float s0 = g_sbef[sbase + (k0)     * 64 + row];
        float s1 = g_sbef[sbase + (k0 + 1) * 64 + row];
        float s2 = g_sbef[sbase + (k0 + 8) * 64 + row];
        float s3 = g_sbef[sbase + (k0 + 9) * 64 + row];
        uint2 sh0 = split_bf16_pair(s0, s1);
        uint2 sh1 = split_bf16_pair(s2, s3);
        sST[i] = make_uint4(sh0.x, sh0.y, sh1.x, sh1.y);
    }
    __syncthreads();

    int warp = tid >> 5, lane = tid & 31;
    int g = lane >> 2, tig = lane & 3;
    int r0 = (warp & 3) * 16, cbn = (warp >> 2) * 32;

    float acc[4][4];
    #pragma unroll
    for (int nt = 0; nt < 4; nt++)
        #pragma unroll
        for (int q = 0; q < 4; q++) acc[nt][q] = 0.f;
    #pragma unroll
    for (int ks = 0; ks < 4; ks++) {
        uint4 fa0 = sC[(r0 + g) * 16 + ks * 4 + tig];
        uint4 fa1 = sC[(r0 + g + 8) * 16 + ks * 4 + tig];
        unsigned ahi[4] = {fa0.x, fa1.x, fa0.z, fa1.z};
        unsigned alo[4] = {fa0.y, fa1.y, fa0.w, fa1.w};
        #pragma unroll
        for (int nt = 0; nt < 4; nt++) {
            uint4 fb = sST[(ks * 4 + tig) * 64 + cbn + nt * 8 + g];
            unsigned bhi[2] = {fb.x, fb.z}, blo[2] = {fb.y, fb.w};
            mma16(acc[nt], alo, bhi);
            mma16(acc[nt], ahi, blo);
            mma16(acc[nt], ahi, bhi);
        }
    }

    float dh = Dh[(2 * b + j) * NH + h];
    #pragma unroll
    for (int nt = 0; nt < 4; nt++) {
        int p = cbn + nt * 8 + 2 * tig;
        #pragma unroll
        for (int hf = 0; hf < 2; hf++) {
            int t = r0 + g + hf * 8;
            float e = __expf(scum[t]);
            long long ydx = (rowb + t) * DI + h * HD + p;
            float2 o = *(float2*)&g_y[ydx];
            float2 xs2 = *(const float2*)&g_xs[ydx];
            o.x += e * acc[nt][hf * 2]     + dh * xs2.x;
            o.y += e * acc[nt][hf * 2 + 1] + dh * xs2.y;
            *(float2*)&g_y[ydx] = o;
        }
    }
}

// ---------------- gate (silu(z)) + RMSNorm -> bf16 in A-layout ----------------
__global__ __launch_bounds__(256) void k_gate(const float* __restrict__ norm_w, int j) {
    int t = blockIdx.x, b = blockIdx.y;
    int lidx = 2 * b + j;
    const float* z = g_zx + ((long long)b * LP + t) * DPROJ;
    const float* yr = g_y + ((long long)b * LP + t) * DI;
    unsigned* yo = g_yB + ((long long)b * LP + t) * 512;
    int tid = threadIdx.x;
    int kt = tid >> 2, jj = tid & 3;
    int k0 = kt * 16 + jj * 2;
    float2 z0 = *(const float2*)&z[k0];
    float2 z1 = *(const float2*)&z[k0 + 8];
    float2 y0 = *(const float2*)&yr[k0];
    float2 y1 = *(const float2*)&yr[k0 + 8];
    float va = y0.x * (z0.x / (1.f + __expf(-z0.x)));
    float vb = y0.y * (z0.y / (1.f + __expf(-z0.y)));
    float vc = y1.x * (z1.x / (1.f + __expf(-z1.x)));
    float vd = y1.y * (z1.y / (1.f + __expf(-z1.y)));
    float ss = va * va + vb * vb + vc * vc + vd * vd;
    float tot = bsum(ss);
    float scale = rsqrtf(tot / (float)DI + 1e-5f);
    float2 n0 = *(const float2*)&norm_w[lidx * DI + k0];
    float2 n1 = *(const float2*)&norm_w[lidx * DI + k0 + 8];
    uint2 packed;
    packed.x = pack_bf16(va * scale * n0.x, vb * scale * n0.y);
    packed.y = pack_bf16(vc * scale * n1.x, vd * scale * n1.y);
    *(uint2*)&yo[kt * 8 + jj * 2] = packed;
}

// ---------------- final LayerNorm: fp32 hn + split pairs ----------------
__global__ __launch_bounds__(256) void k_ln(const float* __restrict__ lnw, const float* __restrict__ lnb) {
    int g = blockIdx.x;
    int b = g / L_TOK, t = g % L_TOK;
    const float* row = g_hcur + ((long long)b * LP + t) * DM;
    int tid = threadIdx.x;
    float2 v = *(const float2*)&row[2 * tid];
    float s = bsum(v.x + v.y);
    float sq = bsum(v.x * v.x + v.y * v.y);
    float mu = s / (float)DM;
    float var = sq / (float)DM - mu * mu;
    float inv = rsqrtf(var + 1e-5f);
    float o0 = (v.x - mu) * inv * lnw[2 * tid]     + lnb[2 * tid];
    float o1 = (v.y - mu) * inv * lnw[2 * tid + 1] + lnb[2 * tid + 1];
    *(float2*)&g_hn[(long long)g * DM + 2 * tid] = make_float2(o0, o1);
    g_hnS[(long long)g * 256 + tid] = split_bf16_pair(o0, o1);
}

// ---------------- attention scalar score ----------------
__global__ void k_score(const float* __restrict__ w2, const float* __restrict__ b2) {
    int g = blockIdx.x;
    int tid = threadIdx.x;
    float v = g_s1[(long long)g * 128 + tid] * w2[tid];
    v = bsum(v);
    if (tid == 0) g_scoreb[g] = v + b2[0];
}

// ---------------- softmax (+ zero pooled) ----------------
__global__ void k_softmax() {
    const int n = NB * L_TOK;
    __shared__ float red[32];
    __shared__ float s_max, s_sum;
    int tid = threadIdx.x;
    if (tid < DM) g_pooled[tid] = 0.f;
    float m = -1e30f;
    for (int i = tid; i < n; i += 1024) m = fmaxf(m, g_scoreb[i]);
    #pragma unroll
    for (int o = 16; o > 0; o >>= 1) m = fmaxf(m, __shfl_xor_sync(0xffffffffu, m, o));
    if ((tid & 31) == 0) red[tid >> 5] = m;
    __syncthreads();
    if (tid < 32) {
        float v = red[tid];
        #pragma unroll
        for (int o = 16; o > 0; o >>= 1) v = fmaxf(v, __shfl_xor_sync(0xffffffffu, v, o));
        if (tid == 0) s_max = v;
    }
    __syncthreads();
    float m0 = s_max;
    float s = 0.f;
    for (int i = tid; i < n; i += 1024) s += expf(g_scoreb[i] - m0);
    #pragma unroll
    for (int o = 16; o > 0; o >>= 1) s += __shfl_xor_sync(0xffffffffu, s, o);
    if ((tid & 31) == 0) red[tid >> 5] = s;
    __syncthreads();
    if (tid < 32) {
        float v = red[tid];
        #pragma unroll
        for (int o = 16; o > 0; o >>= 1) v += __shfl_xor_sync(0xffffffffu, v, o);
        if (tid == 0) s_sum = v;
    }
    __syncthreads();
    float inv = 1.f / s_sum;
    for (int i = tid; i < n; i += 1024) g_wts[i] = expf(g_scoreb[i] - m0) * inv;
}

// ---------------- pooled ----------------
#define PBLK 120
__global__ __launch_bounds__(256) void k_pooled() {
    const int total = NB * L_TOK;
    int per = (total + PBLK - 1) / PBLK;
    int g0 = blockIdx.x * per;
    int g1 = g0 + per; if (g1 > total) g1 = total;
    int tid = threadIdx.x;
    float a0 = 0.f, a1 = 0.f;
    for (int g = g0; g < g1; g++) {
        float w = g_wts[g];
        float2 v = *(const float2*)&g_hn[(long long)g * DM + 2 * tid];
        a0 = fmaf(w, v.x, a0);
        a1 = fmaf(w, v.y, a1);
    }
    atomicAdd(&g_pooled[2 * tid], a0);
    atomicAdd(&g_pooled[2 * tid + 1], a1);
}

// ---------------- final classifier ----------------
__global__ void k_final(const float* __restrict__ cls_w, const float* __restrict__ cls_b,
                        float* __restrict__ out, int out_size) {
    int tid = threadIdx.x;
    int cls = tid >> 5, lane = tid & 31;
    float acc = 0.f;
    for (int d = lane; d < DM; d += 32) acc += g_pooled[d] * cls_w[cls * DM + d];
    #pragma unroll
    for (int o = 16; o > 0; o >>= 1) acc += __shfl_xor_sync(0xffffffffu, acc, o);
    __shared__ float lg[2];
    if (lane == 0) lg[cls] = acc;
    __syncthreads();
    if (tid == 0) {
        float l0 = lg[0] + cls_b[0], l1 = lg[1] + cls_b[1];
        float m = fmaxf(l0, l1);
        float e0 = expf(l0 - m), e1 = expf(l1 - m);
        float s = e0 + e1;
        out[0] = l0;
        out[1] = l1;
        if (out_size >= 4) { out[2] = e0 / s; out[3] = e1 / s; }
    }
}

// ---------------- launch ----------------
static inline void launch_split(const float* src, void* dst, long long npairs) {
    k_split<<<(int)((npairs + 255) / 256), 256>>>(src, (uint2*)dst, npairs);
}

extern "C" void kernel_launch(void* const* d_in, const int* in_sizes, int n_in,
                              void* d_out, int out_size) {
    const float* x        = (const float*)d_in[0];
    const float* fc1_w    = (const float*)d_in[1];
    const float* fc1_b    = (const float*)d_in[2];
    const float* in_proj_w= (const float*)d_in[3];
    const float* conv_w   = (const float*)d_in[4];
    const float* conv_b   = (const float*)d_in[5];
    const float* dt_bias  = (const float*)d_in[6];
    const float* A_log    = (const float*)d_in[7];
    const float* Dh       = (const float*)d_in[8];
    const float* norm_w   = (const float*)d_in[9];
    const float* out_proj_w=(const float*)d_in[10];
    const float* ln_w     = (const float*)d_in[11];
    const float* ln_b     = (const float*)d_in[12];
    const float* attn_w1  = (const float*)d_in[13];
    const float* attn_b1  = (const float*)d_in[14];
    const float* attn_w2  = (const float*)d_in[15];
    const float* attn_b2  = (const float*)d_in[16];
    const float* cls_w    = (const float*)d_in[17];
    const float* cls_b    = (const float*)d_in[18];
    float* out = (float*)d_out;

    void *p_hcur, *p_zx, *p_s1;
    void *p_xS, *p_fc1wS, *p_ipw4, *p_opw4, *p_aw1S, *p_hcurB, *p_yB, *p_hnS;
    cudaGetSymbolAddress(&p_hcur,  g_hcur);
    cudaGetSymbolAddress(&p_zx,    g_zx);
    cudaGetSymbolAddress(&p_s1,    g_s1);
    cudaGetSymbolAddress(&p_xS,    g_xS);
    cudaGetSymbolAddress(&p_fc1wS, g_fc1wS);
    cudaGetSymbolAddress(&p_ipw4,  g_ipw4);
    cudaGetSymbolAddress(&p_opw4,  g_opw4);
    cudaGetSymbolAddress(&p_aw1S,  g_aw1S);
    cudaGetSymbolAddress(&p_hcurB, g_hcurB);
    cudaGetSymbolAddress(&p_yB,    g_yB);
    cudaGetSymbolAddress(&p_hnS,   g_hnS);

    cudaFuncSetAttribute(tgemm,  cudaFuncAttributeMaxDynamicSharedMemorySize, TG_SMEM);
    cudaFuncSetAttribute(tgemm2, cudaFuncAttributeMaxDynamicSharedMemorySize, TG2_SMEM);
    cudaFuncSetAttribute(k_intra_mma, cudaFuncAttributeMaxDynamicSharedMemorySize, SMEM_INTRA_MMA);

    // 1: merged splits (x, fc1_w old layout; in_proj_w fragment layout)
    {
        long long tot = NPX + NPF + NW4;
        k_split_all<<<(int)((tot + 255) / 256), 256>>>(x, fc1_w, in_proj_w);
    }
    // 2: fc1
    {
        dim3 grid((DM + 127) / 128, (L_TOK + 127) / 128, 1);
        tgemm<<<grid, 256, TG_SMEM>>>((const uint2*)p_xS, 0, (const uint2*)p_fc1wS, 0, fc1_b,
                                      (float*)p_hcur, 0, (unsigned*)p_hcurB, L_TOK, DM, 512, 2, 0);
    }
    // 3: branch prep + pad zero
    {
        long long tot = (long long)L_TOK * 128 + (long long)NB * (LP - L_TOK) * 128;
        k_prep2<<<(int)((tot + 255) / 256), 256>>>();
    }

    for (int j = 0; j < 2; j++) {
        // 4 (j=0): in_proj <- ncu capture window
        {
            dim3 g1((DPROJ + 127) / 128, (LP + 127) / 128, NB);
            tgemm2<<<g1, 256, TG2_SMEM>>>((const uint2*)p_hcurB, (long long)LP * 128,
                                          (const uint4*)p_ipw4, (long long)DPROJ * 128,
                                          (float*)p_zx, (long long)LP * DPROJ, nullptr,
                                          LP, DPROJ, 256, 0, j);
        }
        k_convfused<<<dim3(NC, NB), 256>>>(conv_w, conv_b, dt_bias, A_log, j);
        {
            long long tot = 2LL * NB * LP * 16;
            k_splitBC<<<(int)((tot + 255) / 256), 256>>>();
        }
        k_intra_mma<<<dim3(NC, NH, NB), 256, SMEM_INTRA_MMA>>>();
        k_rec<<<dim3(NB * NH, 4), 256>>>();
        k_inter_mma<<<dim3(NC, NH, NB), 256>>>(Dh, j);
        k_gate<<<dim3(LP, NB), 256>>>(norm_w, j);
        if (j == 0) {
            long long nu4 = (long long)6 * DM * 256;
            k_splitW<<<(int)((nu4 + 255) / 256), 256>>>(out_proj_w, (uint4*)p_opw4, nu4, 1024);
        }
        {
            dim3 g2((DM + 127) / 128, (LP + 127) / 128, NB);
            tgemm2<<<g2, 256, TG2_SMEM>>>((const uint2*)p_yB, (long long)LP * 256,
                                          (const uint4*)p_opw4, (long long)DM * 256,
                                          (float*)p_hcur, (long long)LP * DM,
                                          (j == 0) ? (unsigned*)p_hcurB : nullptr,
                                          LP, DM, 512, 1, j);
        }
    }

    // final head
    k_ln<<<NB * L_TOK, 256>>>(ln_w, ln_b);
    launch_split(attn_w1, p_aw1S, (long long)128 * 256);
    {
        dim3 ga(1, (NB * L_TOK + 127) / 128, 1);
        tgemm<<<ga, 256, TG_SMEM>>>((const uint2*)p_hnS, 0, (const uint2*)p_aw1S, 0, attn_b1,
                                    (float*)p_s1, 0, nullptr, NB * L_TOK, 128, 256, 3, 0);
    }
    k_score<<<NB * L_TOK, 128>>>(attn_w2, attn_b2);
    k_softmax<<<1, 1024>>>();
    k_pooled<<<PBLK, 256>>>();
    k_final<<<1, 64>>>(cls_w, cls_b, out, out_size);
}

// round 16
// speedup vs baseline: 1.3578x; 1.0207x over previous
#include <cuda_runtime.h>
#include <cuda_bf16.h>
#include <math.h>

// ---------------- problem constants ----------------
#define L_TOK 10000
#define LP    10048
#define NC    157
#define Q     64
#define DM    512
#define DI    1024
#define DS    64
#define NH    16
#define HD    64
#define DXBC  1152
#define DPROJ 2192
#define NB    3

// ---------------- scratch ----------------
__device__ __align__(16) float g_hcur [(size_t)NB*LP*DM];
__device__ __align__(16) float g_zx   [(size_t)NB*LP*DPROJ];
__device__ __align__(16) float g_xs   [(size_t)NB*LP*DI];
__device__ __align__(16) float g_Bm   [(size_t)NB*LP*DS];
__device__ __align__(16) float g_Cm   [(size_t)NB*LP*DS];
__device__ __align__(16) float g_dtv  [(size_t)NB*LP*NH];
__device__ __align__(16) float g_cum  [(size_t)NB*NH*LP];
__device__ __align__(16) float g_y    [(size_t)NB*LP*DI];
__device__ __align__(16) float g_schunk[(size_t)NB*NH*NC*DS*HD];
__device__ __align__(16) float g_sbef  [(size_t)NB*NH*NC*DS*HD];
__device__ __align__(16) float g_hn   [(size_t)NB*L_TOK*DM];
__device__ __align__(16) float g_s1   [(size_t)NB*L_TOK*128];
__device__ float g_scoreb[NB*L_TOK];
__device__ float g_wts   [NB*L_TOK];
__device__ float g_pooled[DM];

// split-bf16 (old layout, for tgemm fc1/attn path)
__device__ __align__(16) uint2 g_xS   [(size_t)L_TOK*512];
__device__ __align__(16) uint2 g_fc1wS[(size_t)DM*512];
__device__ __align__(16) uint2 g_aw1S [(size_t)128*256];
__device__ __align__(16) uint2 g_hnS  [(size_t)NB*L_TOK*256];
// W split, ktile-fragment layout
__device__ __align__(16) uint4 g_ipw4 [(size_t)6*DPROJ*128];
__device__ __align__(16) uint4 g_opw4 [(size_t)6*DM*256];
// B/C split, fragment layout: per row 16 x uint4 (4 kt x 4 tig)
__device__ __align__(16) uint4 g_CmS [(size_t)NB*LP*16];
__device__ __align__(16) uint4 g_BmS [(size_t)NB*LP*16];
// A plain-bf16, ktile layout
__device__ __align__(16) unsigned g_hcurB[(size_t)NB*LP*256];
__device__ __align__(16) unsigned g_yB   [(size_t)NB*LP*512];

__device__ __forceinline__ int a2i(int p) {
    return (p & ~7) | ((p & 3) << 1) | ((p >> 2) & 1);
}

// ---------------- helpers ----------------
__device__ __forceinline__ float bsum(float v) {
    __shared__ float sh[32];
    int lane = threadIdx.x & 31, w = threadIdx.x >> 5;
    #pragma unroll
    for (int o = 16; o > 0; o >>= 1) v += __shfl_xor_sync(0xffffffffu, v, o);
    if (lane == 0) sh[w] = v;
    __syncthreads();
    int nw = blockDim.x >> 5;
    v = (threadIdx.x < nw) ? sh[threadIdx.x] : 0.f;
    if (w == 0) {
        #pragma unroll
        for (int o = 16; o > 0; o >>= 1) v += __shfl_xor_sync(0xffffffffu, v, o);
        if (threadIdx.x == 0) sh[0] = v;
    }
    __syncthreads();
    float r = sh[0];
    __syncthreads();
    return r;
}

__device__ __forceinline__ unsigned pack_bf16(float f0, float f1) {
    unsigned r;
    asm("cvt.rn.bf16x2.f32 %0, %1, %2;" : "=r"(r) : "f"(f1), "f"(f0));
    return r;
}

__device__ __forceinline__ uint2 split_bf16_pair(float f0, float f1) {
    unsigned hp, lp;
    asm("cvt.rn.bf16x2.f32 %0, %1, %2;" : "=r"(hp) : "f"(f1), "f"(f0));
    __nv_bfloat162 h = *reinterpret_cast<__nv_bfloat162*>(&hp);
    float r0 = f0 - __bfloat162float(h.x);
    float r1 = f1 - __bfloat162float(h.y);
    asm("cvt.rn.bf16x2.f32 %0, %1, %2;" : "=r"(lp) : "f"(r1), "f"(r0));
    uint2 q; q.x = hp; q.y = lp;
    return q;
}

__global__ void k_split(const float* __restrict__ in, uint2* __restrict__ out, long long npairs) {
    long long i = (long long)blockIdx.x * 256 + threadIdx.x;
    if (i >= npairs) return;
    float2 v = ((const float2*)in)[i];
    out[i] = split_bf16_pair(v.x, v.y);
}

// merged split of x, fc1_w (old layout) + in_proj_w (fragment W layout)
#define NPX ((long long)L_TOK * 512)
#define NPF ((long long)DM * 512)
#define NW4 ((long long)6 * DPROJ * 128)
__global__ void k_split_all(const float* __restrict__ x, const float* __restrict__ fw,
                            const float* __restrict__ iw) {
    long long i = (long long)blockIdx.x * 256 + threadIdx.x;
    if (i < NPX) {
        float2 v = ((const float2*)x)[i];
        g_xS[i] = split_bf16_pair(v.x, v.y);
        return;
    }
    if (i < NPX + NPF) {
        long long off = i - NPX;
        float2 v = ((const float2*)fw)[off];
        g_fc1wS[off] = split_bf16_pair(v.x, v.y);
        return;
    }
    long long u = i - NPX - NPF;
    if (u >= NW4) return;
    long long row = u >> 7;
    int rem = (int)(u & 127);
    int kt = rem >> 2, tig = rem & 3;
    int k0 = kt * 16 + tig * 2;
    const float* rp = iw + row * 512;
    float2 va = *(const float2*)&rp[k0];
    float2 vb = *(const float2*)&rp[k0 + 8];
    uint2 sa = split_bf16_pair(va.x, va.y);
    uint2 sb = split_bf16_pair(vb.x, vb.y);
    g_ipw4[u] = make_uint4(sa.x, sa.y, sb.x, sb.y);
}

// split W into ktile-fragment layout (out_proj)
__global__ void k_splitW(const float* __restrict__ src, uint4* __restrict__ dst,
                         long long nu4, int K) {
    long long u = (long long)blockIdx.x * 256 + threadIdx.x;
    if (u >= nu4) return;
    int perrow = K >> 2;
    long long row = u / perrow;
    int rem = (int)(u % perrow);
    int kt = rem >> 2, tig = rem & 3;
    int k0 = kt * 16 + tig * 2;
    const float* rp = src + row * K;
    float2 va = *(const float2*)&rp[k0];
    float2 vb = *(const float2*)&rp[k0 + 8];
    uint2 sa = split_bf16_pair(va.x, va.y);
    uint2 sb = split_bf16_pair(vb.x, vb.y);
    dst[u] = make_uint4(sa.x, sa.y, sb.x, sb.y);
}

// split B,C into fragment layout (per layer)
__global__ void k_splitBC() {
    const long long N1 = (long long)NB * LP * 16;
    long long u = (long long)blockIdx.x * 256 + threadIdx.x;
    const float* src; uint4* dst; long long v;
    if (u < N1) { src = g_Cm; dst = g_CmS; v = u; }
    else if (u < 2 * N1) { src = g_Bm; dst = g_BmS; v = u - N1; }
    else return;
    long long row = v >> 4;
    int rem = (int)(v & 15);
    int kt = rem >> 2, tig = rem & 3;
    int k0 = kt * 16 + tig * 2;
    float2 va = *(const float2*)&src[row * DS + k0];
    float2 vb = *(const float2*)&src[row * DS + k0 + 8];
    uint2 sa = split_bf16_pair(va.x, va.y);
    uint2 sb = split_bf16_pair(vb.x, vb.y);
    dst[v] = make_uint4(sa.x, sa.y, sb.x, sb.y);
}

__device__ __forceinline__ void mma16(float c[4], const unsigned a[4], const unsigned b[2]) {
    asm volatile(
        "mma.sync.aligned.m16n8k16.row.col.f32.bf16.bf16.f32 "
        "{%0,%1,%2,%3},{%4,%5,%6,%7},{%8,%9},{%0,%1,%2,%3};"
        : "+f"(c[0]), "+f"(c[1]), "+f"(c[2]), "+f"(c[3])
        : "r"(a[0]), "r"(a[1]), "r"(a[2]), "r"(a[3]), "r"(b[0]), "r"(b[1]));
}

__device__ __forceinline__ void cp8(unsigned dst, const void* src, bool pred) {
    int sz = pred ? 8 : 0;
    asm volatile("cp.async.ca.shared.global [%0], [%1], 8, %2;" :: "r"(dst), "l"(src), "r"(sz));
}
__device__ __forceinline__ void cp16(unsigned dst, const void* src, bool pred) {
    int sz = pred ? 16 : 0;
    asm volatile("cp.async.cg.shared.global [%0], [%1], 16, %2;" :: "r"(dst), "l"(src), "r"(sz));
}

// ---------------- tgemm: 3xBF16 split both sides (fc1, attn1) ----------------
#define STAGES 4
#define S4 130
#define TG_SMEM (STAGES * 4 * S4 * 16 * 2)

__global__ __launch_bounds__(256, 2) void tgemm(
    const uint2* __restrict__ A, long long sA,
    const uint2* __restrict__ W, long long sW,
    const float* __restrict__ bias,
    float* __restrict__ C, long long sC,
    unsigned* __restrict__ Caux,
    int M, int N, int Kp, int op, int joff)
{
    extern __shared__ uint4 sm4[];
    uint4* As = sm4;
    uint4* Ws = sm4 + STAGES * 4 * S4;

    int z = blockIdx.z;
    A += (long long)z * sA;
    C += (long long)z * sC;
    W += (long long)(2 * z + joff) * sW;
    if (Caux) Caux += (long long)z * (sC >> 1);

    int tid = threadIdx.x;
    int warp = tid >> 5, lane = tid & 31;
    int wm = warp & 3, wn = warp >> 2;
    int g = lane >> 2, tig = lane & 3;
    int row0 = blockIdx.y * 128, col0 = blockIdx.x * 128;

    int ar = tid >> 1, half = tid & 1;
    bool aok = (row0 + ar) < M;
    bool wok = (col0 + ar) < N;
    const uint2* Ag = A + (long long)(row0 + ar) * Kp + half * 4;
    const uint2* Wg = W + (long long)(col0 + ar) * Kp + half * 4;
    unsigned aSm = (unsigned)__cvta_generic_to_shared(As);
    unsigned wSm = (unsigned)__cvta_generic_to_shared(Ws);

    float c[2][8][4];
    #pragma unroll
    for (int mt = 0; mt < 2; mt++)
        #pragma unroll
        for (int nt = 0; nt < 8; nt++)
            #pragma unroll
            for (int q = 0; q < 4; q++) c[mt][nt][q] = 0.f;

    int nK = Kp >> 3;

    #define ISSUE(kt, slot) do { \
        const uint2* _Ap = Ag + (kt) * 8; \
        const uint2* _Wp = Wg + (kt) * 8; \
        _Pragma("unroll") \
        for (int i = 0; i < 4; i++) { \
            unsigned off = (unsigned)((((slot) * 4 + i) * S4 + ar) * 16 + half * 8); \
            cp8(aSm + off, _Ap + i, aok); \
            cp8(wSm + off, _Wp + i, wok); \
        } \
    } while (0)

    #pragma unroll
    for (int s = 0; s < STAGES - 1; s++) {
        if (s < nK) ISSUE(s, s);
        asm volatile("cp.async.commit_group;");
    }

    for (int kt = 0; kt < nK; kt++) {
        asm volatile("cp.async.wait_group %0;" :: "n"(STAGES - 2));
        __syncthreads();

        int slot = kt & 3;
        const uint4* Ab = As + slot * 4 * S4;
        const uint4* Wb = Ws + slot * 4 * S4;

        uint4 fa[2][2];
        #pragma unroll
        for (int mt = 0; mt < 2; mt++) {
            int m0 = wm * 32 + mt * 16;
            fa[mt][0] = Ab[tig * S4 + m0 + g];
            fa[mt][1] = Ab[tig * S4 + m0 + g + 8];
        }
        unsigned ahi[2][4], alo[2][4];
        #pragma unroll
        for (int mt = 0; mt < 2; mt++) {
            ahi[mt][0] = fa[mt][0].x; ahi[mt][1] = fa[mt][1].x;
            ahi[mt][2] = fa[mt][0].z; ahi[mt][3] = fa[mt][1].z;
            alo[mt][0] = fa[mt][0].y; alo[mt][1] = fa[mt][1].y;
            alo[mt][2] = fa[mt][0].w; alo[mt][3] = fa[mt][1].w;
        }
        #pragma unroll
        for (int nt = 0; nt < 8; nt++) {
            int n0 = wn * 64 + nt * 8;
            uint4 fb = Wb[tig * S4 + n0 + g];
            unsigned bhi[2] = {fb.x, fb.z};
            unsigned blo[2] = {fb.y, fb.w};
            #pragma unroll
            for (int mt = 0; mt < 2; mt++) {
                mma16(c[mt][nt], alo[mt], bhi);
                mma16(c[mt][nt], ahi[mt], blo);
                mma16(c[mt][nt], ahi[mt], bhi);
            }
        }

        int pre = kt + STAGES - 1;
        if (pre < nK) ISSUE(pre, pre & 3);
        asm volatile("cp.async.commit_group;");
    }
    asm volatile("cp.async.wait_all;");

    #pragma unroll
    for (int mt = 0; mt < 2; mt++) {
        #pragma unroll
        for (int nt = 0; nt < 8; nt++) {
            int cc = col0 + wn * 64 + nt * 8 + 2 * tig;
            if (cc >= N) continue;
            #pragma unroll
            for (int hf = 0; hf < 2; hf++) {
                int r = row0 + wm * 32 + mt * 16 + g + hf * 8;
                if (r >= M) continue;
                float v0 = c[mt][nt][hf * 2 + 0];
                float v1 = c[mt][nt][hf * 2 + 1];
                long long ci = (long long)r * N + cc;
                if (op == 0) {
                    *(float2*)&C[ci] = make_float2(v0, v1);
                } else if (op == 1) {
                    float2 o = *(float2*)&C[ci];
                    o.x += v0; o.y += v1;
                    *(float2*)&C[ci] = o;
                } else if (op == 2) {
                    v0 = fmaxf(v0 + bias[cc], 0.f);
                    v1 = fmaxf(v1 + bias[cc + 1], 0.f);
                    *(float2*)&C[ci] = make_float2(v0, v1);
                    if (Caux) Caux[(long long)r * (N >> 1) + a2i(cc >> 1)] = pack_bf16(v0, v1);
                } else {
                    v0 += bias[cc]; v1 += bias[cc + 1];
                    *(float2*)&C[ci] = make_float2(tanhf(v0), tanhf(v1));
                }
            }
        }
    }
    #undef ISSUE
}

// ---------------- tgemm2: bf16-A x split-W, all cp16, NSLOT=4, fully unrolled slots ----------------
#define NSLOT 4
#define TG2_SMEM (NSLOT * 2 * (128 * 32 + 128 * 64))

__global__ __launch_bounds__(256, 2) void tgemm2(
    const uint2* __restrict__ A, long long sA,
    const uint4* __restrict__ W, long long sW,
    float* __restrict__ C, long long sC,
    unsigned* __restrict__ Caux,
    int M, int N, int Kp, int op, int joff)
{
    extern __shared__ char smc[];
    uint2* Asm = (uint2*)smc;
    uint4* Wsm = (uint4*)(smc + NSLOT * 2 * 128 * 32);

    int z = blockIdx.z;
    A += (long long)z * sA;
    C += (long long)z * sC;
    W += (long long)(2 * z + joff) * sW;
    if (Caux) Caux += (long long)z * (sC >> 1);

    int tid = threadIdx.x;
    int warp = tid >> 5, lane = tid & 31;
    int wm = warp & 1, wn = warp >> 1;
    int g = lane >> 2, tig = lane & 3;
    int row0 = blockIdx.y * 128, col0 = blockIdx.x * 128;

    int ar = tid >> 1, half = tid & 1;
    bool aok = (row0 + ar) < M;
    bool wok = (col0 + ar) < N;
    int pr = Kp >> 1;
    const uint2* Ag = A + (long long)(row0 + ar) * pr + half * 2;
    const uint4* Wg = W + (long long)(col0 + ar) * pr + half * 2;
    unsigned aB = (unsigned)__cvta_generic_to_shared(Asm);
    unsigned wB = (unsigned)__cvta_generic_to_shared(Wsm);

    float c[4][4][4];
    #pragma unroll
    for (int mt = 0; mt < 4; mt++)
        #pragma unroll
        for (int nt = 0; nt < 4; nt++)
            #pragma unroll
            for (int q = 0; q < 4; q++) c[mt][nt][q] = 0.f;

    int nG = Kp >> 4;    // 16 or 32 — always divisible by 4

    #define ISSUEG(gi, s) do { \
        _Pragma("unroll") \
        for (int u = 0; u < 2; u++) { \
            int _kt = (gi) * 2 + u; \
            cp16(aB + (unsigned)((((s) * 2 + u) * 128 + ar) * 32 + half * 16), Ag + _kt * 4, aok); \
            cp16(wB + (unsigned)((((s) * 2 + u) * 128 + ar) * 64 + half * 32),      Wg + _kt * 4,     wok); \
            cp16(wB + (unsigned)((((s) * 2 + u) * 128 + ar) * 64 + half * 32 + 16), Wg + _kt * 4 + 1, wok); \
        } \
    } while (0)

    // compute one slot (compile-time ss)
    #define COMPUTE(ss) do { \
        _Pragma("unroll") \
        for (int u = 0; u < 2; u++) { \
            const uint2* Ab = Asm + ((ss) * 2 + u) * 128 * 4; \
            const uint4* Wb = Wsm + ((ss) * 2 + u) * 128 * 4; \
            unsigned a[4][4]; \
            _Pragma("unroll") \
            for (int mt = 0; mt < 4; mt++) { \
                int m0 = wm * 64 + mt * 16; \
                uint2 q0 = Ab[(m0 + g) * 4 + tig]; \
                uint2 q1 = Ab[(m0 + g + 8) * 4 + tig]; \
                a[mt][0] = q0.x; a[mt][1] = q1.x; \
                a[mt][2] = q0.y; a[mt][3] = q1.y; \
            } \
            _Pragma("unroll") \
            for (int nt = 0; nt < 4; nt++) { \
                int n0 = wn * 32 + nt * 8; \
                uint4 fb = Wb[(n0 + g) * 4 + tig]; \
                unsigned bhi[2] = {fb.x, fb.z}; \
                unsigned blo[2] = {fb.y, fb.w}; \
                _Pragma("unroll") \
                for (int mt = 0; mt < 4; mt++) { \
                    mma16(c[mt][nt], a[mt], blo); \
                    mma16(c[mt][nt], a[mt], bhi); \
                } \
            } \
        } \
    } while (0)

    ISSUEG(0, 0);
    asm volatile("cp.async.commit_group;");
    ISSUEG(1, 1);
    asm volatile("cp.async.commit_group;");
    ISSUEG(2, 2);
    asm volatile("cp.async.commit_group;");

    for (int gq = 0; gq < nG; gq += 4) {
        #pragma unroll
        for (int ss = 0; ss < 4; ss++) {
            asm volatile("cp.async.wait_group 2;");
            __syncthreads();
            COMPUTE(ss);
            int pre = gq + ss + 3;
            if (pre < nG) ISSUEG(pre, (ss + 3) & 3);
            asm volatile("cp.async.commit_group;");
        }
    }
    asm volatile("cp.async.wait_all;");

    #pragma unroll
    for (int mt = 0; mt < 4; mt++) {
        #pragma unroll
        for (int nt = 0; nt < 4; nt++) {
            int cc = col0 + wn * 32 + nt * 8 + 2 * tig;
            if (cc >= N) continue;
            #pragma unroll
            for (int hf = 0; hf < 2; hf++) {
                int r = row0 + wm * 64 + mt * 16 + g + hf * 8;
                if (r >= M) continue;
                float v0 = c[mt][nt][hf * 2 + 0];
                float v1 = c[mt][nt][hf * 2 + 1];
                long long ci = (long long)r * N + cc;
                if (op == 0) {
                    *(float2*)&C[ci] = make_float2(v0, v1);
                } else {
                    float2 o = *(float2*)&C[ci];
                    o.x += v0; o.y += v1;
                    *(float2*)&C[ci] = o;
                    if (Caux) Caux[(long long)r * (N >> 1) + a2i(cc >> 1)] = pack_bf16(o.x, o.y);
                }
            }
        }
    }
    #undef ISSUEG
    #undef COMPUTE
}

// ---------------- branch prep + pad-row zeroing ----------------
__global__ void k_prep2() {
    long long i = (long long)blockIdx.x * 256 + threadIdx.x;
    const long long mainN = (long long)L_TOK * 128;
    if (i < mainN) {
        int t = (int)(i >> 7), q = (int)(i & 127);
        float4 v = *((const float4*)g_hcur + (long long)t * 128 + q);
        int d0 = q * 4, p = q * 2;
        *(float4*)&g_hcur[(long long)LP * DM + (long long)t * DM + (508 - d0)] =
            make_float4(v.w, v.z, v.y, v.x);
        g_hcurB[(long long)LP * 256 + (long long)t * 256 + a2i(255 - p)] = pack_bf16(v.y, v.x);
        g_hcurB[(long long)LP * 256 + (long long)t * 256 + a2i(254 - p)] = pack_bf16(v.w, v.z);
        int tt = (t % 100) * 100 + t / 100;
        *(float4*)&g_hcur[2LL * LP * DM + (long long)tt * DM + d0] = v;
        g_hcurB[2LL * LP * 256 + (long long)tt * 256 + a2i(p)]     = pack_bf16(v.x, v.y);
        g_hcurB[2LL * LP * 256 + (long long)tt * 256 + a2i(p + 1)] = pack_bf16(v.z, v.w);
        return;
    }
    long long j = i - mainN;
    if (j >= (long long)NB * (LP - L_TOK) * 128) return;
    int b = (int)(j / ((LP - L_TOK) * 128));
    int rem = (int)(j % ((LP - L_TOK) * 128));
    int t = L_TOK + rem / 128, q = rem % 128;
    *(float4*)&g_hcur[((long long)b * LP + t) * DM + q * 4] = make_float4(0.f, 0.f, 0.f, 0.f);
    g_hcurB[((long long)b * LP + t) * 256 + q * 2]     = 0u;
    g_hcurB[((long long)b * LP + t) * 256 + q * 2 + 1] = 0u;
}

// ---------------- fused conv + silu + dt + cumsum ----------------
__global__ __launch_bounds__(256) void k_convfused(
    const float* __restrict__ cw, const float* __restrict__ cb,
    const float* __restrict__ dt_bias, const float* __restrict__ A_log, int j)
{
    __shared__ float av_s[NH * 64];
    int c = blockIdx.x, b = blockIdx.y;
    int lidx = 2 * b + j;
    int tid = threadIdx.x;
    const float* zbase = g_zx + (long long)b * LP * DPROJ;
    int gt0 = c * Q;

    for (int cc = tid; cc < DXBC; cc += 256) {
        const float* col = zbase + DI + cc;
        const float* wp = cw + (long long)(lidx * DXBC + cc) * 4;
        float w0 = wp[0], w1 = wp[1], w2 = wp[2], w3 = wp[3];
        float bia = cb[lidx * DXBC + cc];
        float h3 = (gt0 - 3 >= 0) ? col[(long long)(gt0 - 3) * DPROJ] : 0.f;
        float h2 = (gt0 - 2 >= 0) ? col[(long long)(gt0 - 2) * DPROJ] : 0.f;
        float h1 = (gt0 - 1 >= 0) ? col[(long long)(gt0 - 1) * DPROJ] : 0.f;
        #pragma unroll 4
        for (int t = 0; t < Q; t++) {
            int gt = gt0 + t;
            float cur = col[(long long)gt * DPROJ];
            float a = bia + w0 * h3 + w1 * h2 + w2 * h1 + w3 * cur;
            float v = a / (1.f + __expf(-a));
            if (gt >= L_TOK) v = 0.f;
            long long tb = (long long)b * LP + gt;
            if (cc < DI)            g_xs[tb * DI + cc] = v;
            else if (cc < DI + DS)  g_Bm[tb * DS + (cc - DI)] = v;
            else                    g_Cm[tb * DS + (cc - DI - DS)] = v;
            h3 = h2; h2 = h1; h1 = cur;
        }
    }

    #pragma unroll
    for (int k = 0; k < 4; k++) {
        int idx = tid + k * 256;
        int h = idx & 15, t = idx >> 4;
        int gt = gt0 + t;
        float draw = zbase[(long long)gt * DPROJ + DI + DXBC + h];
        float xv = draw + dt_bias[lidx * NH + h];
        float sp = (xv > 20.f) ? xv : log1pf(expf(xv));
        if (gt >= L_TOK) sp = 0.f;
        g_dtv[((long long)b * LP + gt) * NH + h] = sp;
        float Ah = -expf(A_log[lidx * NH + h]);
        av_s[h * 64 + t] = sp * Ah;
    }
    __syncthreads();

    int warp = tid >> 5, lane = tid & 31;
    #pragma unroll
    for (int hh = 0; hh < 2; hh++) {
        int h = warp * 2 + hh;
        float x1 = av_s[h * 64 + lane];
        float x2 = av_s[h * 64 + 32 + lane];
        #pragma unroll
        for (int o = 1; o < 32; o <<= 1) { float yv = __shfl_up_sync(0xffffffffu, x1, o); if (lane >= o) x1 += yv; }
        #pragma unroll
        for (int o = 1; o < 32; o <<= 1) { float yv = __shfl_up_sync(0xffffffffu, x2, o); if (lane >= o) x2 += yv; }
        float tot1 = __shfl_sync(0xffffffffu, x1, 31);
        x2 += tot1;
        long long base = (long long)(b * NH + h) * LP + (long long)c * Q;
        g_cum[base + lane] = x1;
        g_cum[base + 32 + lane] = x2;
    }
}

// ---------------- intra-chunk (tensor-core); C/B tiles copied pre-split ----------------
#define SMEM_INTRA_MMA (4096 * 16 + 512)
__global__ __launch_bounds__(256) void k_intra_mma() {
    extern __shared__ uint4 smu[];
    uint4* sC  = smu;
    uint4* sB  = smu + 1024;
    uint4* sUT = smu + 2048;
    uint4* sBw = smu + 3072;
    float* scum = (float*)(smu + 4096);
    float* sdt  = scum + 64;

    int c = blockIdx.x, h = blockIdx.y, b = blockIdx.z;
    long long rowb = (long long)b * LP + (long long)c * Q;
    int tid = threadIdx.x;

    if (tid < 64) {
        scum[tid] = g_cum[(long long)(b * NH + h) * LP + (long long)c * Q + tid];
        sdt[tid]  = g_dtv[(rowb + tid) * NH + h];
    }
    __syncthreads();
    float T = scum[63];

    {
        const uint4* gC = g_CmS + rowb * 16;
        const uint4* gB = g_BmS + rowb * 16;
        for (int i = tid; i < 1024; i += 256) {
            sC[i] = gC[i];
            sB[i] = gB[i];
        }
    }
    for (int i = tid; i < 1024; i += 256) {
        int slot = i >> 6, row = i & 63;
        int ks = slot >> 2, tg = slot & 3;
        int k0 = ks * 16 + tg * 2;
        float u0 = sdt[k0]     * g_xs[(rowb + k0)     * DI + h * HD + row];
        float u1 = sdt[k0 + 1] * g_xs[(rowb + k0 + 1) * DI + h * HD + row];
        float u2 = sdt[k0 + 8] * g_xs[(rowb + k0 + 8) * DI + h * HD + row];
        float u3 = sdt[k0 + 9] * g_xs[(rowb + k0 + 9) * DI + h * HD + row];
        uint2 uh0 = split_bf16_pair(u0, u1);
        uint2 uh1 = split_bf16_pair(u2, u3);
        sUT[i] = make_uint4(uh0.x, uh0.y, uh1.x, uh1.y);
        float bw0 = g_Bm[(rowb + k0)     * DS + row] * __expf(T - scum[k0]);
        float bw1 = g_Bm[(rowb + k0 + 1) * DS + row] * __expf(T - scum[k0 + 1]);
        float bw2 = g_Bm[(rowb + k0 + 8) * DS + row] * __expf(T - scum[k0 + 8]);
        float bw3 = g_Bm[(rowb + k0 + 9) * DS + row] * __expf(T - scum[k0 + 9]);
        uint2 wh0 = split_bf16_pair(bw0, bw1);
        uint2 wh1 = split_bf16_pair(bw2, bw3);
        sBw[i] = make_uint4(wh0.x, wh0.y, wh1.x, wh1.y);
    }
    __syncthreads();

    int warp = tid >> 5, lane = tid & 31;
    int g = lane >> 2, tig = lane & 3;
    int r0 = (warp & 3) * 16, cbn = (warp >> 2) * 32;

    float accP[4][4];
    #pragma unroll
    for (int nt = 0; nt < 4; nt++)
        #pragma unroll
        for (int q = 0; q < 4; q++) accP[nt][q] = 0.f;
    #pragma unroll
    for (int ks = 0; ks < 4; ks++) {
        uint4 fa0 = sC[(r0 + g) * 16 + ks * 4 + tig];
        uint4 fa1 = sC[(r0 + g + 8) * 16 + ks * 4 + tig];
        unsigned ahi[4] = {fa0.x, fa1.x, fa0.z, fa1.z};
        unsigned alo[4] = {fa0.y, fa1.y, fa0.w, fa1.w};
        #pragma unroll
        for (int nt = 0; nt < 4; nt++) {
            uint4 fb = sB[(cbn + nt * 8 + g) * 16 + ks * 4 + tig];
            unsigned bhi[2] = {fb.x, fb.z}, blo[2] = {fb.y, fb.w};
            mma16(accP[nt], alo, bhi);
            mma16(accP[nt], ahi, blo);
            mma16(accP[nt], ahi, bhi);
        }
    }
    __syncthreads();

    uint2* sP2 = (uint2*)sB;
    #pragma unroll
    for (int nt = 0; nt < 4; nt++) {
        int scol = cbn + nt * 8 + 2 * tig;
        int Pp = scol >> 1;
        int ksp = Pp >> 3, tslot = Pp & 3, halfp = (Pp >> 2) & 1;
        #pragma unroll
        for (int hf = 0; hf < 2; hf++) {
            int t = r0 + g + hf * 8;
            float v0 = accP[nt][hf * 2], v1 = accP[nt][hf * 2 + 1];
            v0 = (scol     <= t) ? v0 * __expf(scum[t] - scum[scol])     : 0.f;
            v1 = (scol + 1 <= t) ? v1 * __expf(scum[t] - scum[scol + 1]) : 0.f;
            sP2[((ksp * 4 + tslot) * 64 + t) * 2 + halfp] = split_bf16_pair(v0, v1);
        }
    }
    __syncthreads();

    float accY[4][4], accS[4][4];
    #pragma unroll
    for (int nt = 0; nt < 4; nt++)
        #pragma unroll
        for (int q = 0; q < 4; q++) { accY[nt][q] = 0.f; accS[nt][q] = 0.f; }
    uint4* sP = sB;
    #pragma unroll
    for (int ks = 0; ks < 4; ks++) {
        uint4 fp0 = sP[(ks * 4 + tig) * 64 + r0 + g];
        uint4 fp1 = sP[(ks * 4 + tig) * 64 + r0 + g + 8];
        unsigned phi[4] = {fp0.x, fp1.x, fp0.z, fp1.z};
        unsigned plo[4] = {fp0.y, fp1.y, fp0.w, fp1.w};
        uint4 fw0 = sBw[(ks * 4 + tig) * 64 + r0 + g];
        uint4 fw1 = sBw[(ks * 4 + tig) * 64 + r0 + g + 8];
        unsigned whi[4] = {fw0.x, fw1.x, fw0.z, fw1.z};
        unsigned wlo[4] = {fw0.y, fw1.y, fw0.w, fw1.w};
        #pragma unroll
        for (int nt = 0; nt < 4; nt++) {
            uint4 fb = sUT[(ks * 4 + tig) * 64 + cbn + nt * 8 + g];
            unsigned bhi[2] = {fb.x, fb.z}, blo[2] = {fb.y, fb.w};
            mma16(accY[nt], plo, bhi); mma16(accY[nt], phi, blo); mma16(accY[nt], phi, bhi);
            mma16(accS[nt], wlo, bhi); mma16(accS[nt], whi, blo); mma16(accS[nt], whi, bhi);
        }
    }

    long long sbase = ((long long)(b * NH + h) * NC + c) * 4096;
    #pragma unroll
    for (int nt = 0; nt < 4; nt++) {
        int p = cbn + nt * 8 + 2 * tig;
        #pragma unroll
        for (int hf = 0; hf < 2; hf++) {
            int r = r0 + g + hf * 8;
            *(float2*)&g_y[(rowb + r) * DI + h * HD + p] =
                make_float2(accY[nt][hf * 2], accY[nt][hf * 2 + 1]);
            *(float2*)&g_schunk[sbase + r * 64 + p] =
                make_float2(accS[nt][hf * 2], accS[nt][hf * 2 + 1]);
        }
    }
}

// ---------------- chunk-state recurrence (4-way split, prefetched) ----------------
__global__ __launch_bounds__(256) void k_rec() {
    int bh = blockIdx.x;
    int qd = blockIdx.y;
    int tid = threadIdx.x;
    int off = qd * 1024 + tid;
    float S[4], v[4], nv[4];
    #pragma unroll
    for (int i = 0; i < 4; i++) S[i] = 0.f;
    const float* cumrow = g_cum + (long long)bh * LP;
    long long base = (long long)bh * NC * 4096;
    #pragma unroll
    for (int i = 0; i < 4; i++) v[i] = g_schunk[base + off + i * 256];
    for (int c = 0; c < NC; c++) {
        float e = __expf(cumrow[c * Q + 63]);
        if (c + 1 < NC) {
            long long nb = base + 4096;
            #pragma unroll
            for (int i = 0; i < 4; i++) nv[i] = g_schunk[nb + off + i * 256];
        }
        #pragma unroll
        for (int i = 0; i < 4; i++) {
            g_sbef[base + off + i * 256] = S[i];
            S[i] = e * S[i] + v[i];
            v[i] = nv[i];
        }
        base += 4096;
    }
}

// ---------------- inter-chunk (tensor-core); C tile copied pre-split ----------------
__global__ __launch_bounds__(256) void k_inter_mma(const float* __restrict__ Dh, int j) {
    __shared__ uint4 sC[1024];
    __shared__ uint4 sST[1024];
    __shared__ float scum[64];

    int c = blockIdx.x, h = blockIdx.y, b = blockIdx.z;
    long long rowb = (long long)b * LP + (long long)c * Q;
    long long sbase = ((long long)(b * NH + h) * NC + c) * 4096;
    int tid = threadIdx.x;

    if (tid < 64)
        scum[tid] = g_cum[(long long)(b * NH + h) * LP + (long long)c * Q + tid];

    {
        const uint4* gC = g_CmS + rowb * 16;
        for (int i = tid; i < 1024; i += 256) sC[i] = gC[i];
    }
    for (int i = tid; i < 1024; i += 256) {
        int slot = i >> 6, row = i & 63;
        int ks = slot >> 2, tg = slot & 3;
        int k0 = ks * 16 + tg * 2;
        float s0 = g_sbef[sbase + (k0)     * 64 + row];
        float s1 = g_sbef[sbase + (k0 + 1) * 64 + row];
        float s2 = g_sbef[sbase + (k0 + 8) * 64 + row];
        float s3 = g_sbef[sbase + (k0 + 9) * 64 + row];
        uint2 sh0 = split_bf16_pair(s0, s1);
        uint2 sh1 = split_bf16_pair(s2, s3);
        sST[i] = make_uint4(sh0.x, sh0.y, sh1.x, sh1.y);
    }
    __syncthreads();

    int warp = tid >> 5, lane = tid & 31;
    int g = lane >> 2, tig = lane & 3;
    int r0 = (warp & 3) * 16, cbn = (warp >> 2) * 32;

    float acc[4][4];
    #pragma unroll
    for (int nt = 0; nt < 4; nt++)
        #pragma unroll
        for (int q = 0; q < 4; q++) acc[nt][q] = 0.f;
    #pragma unroll
    for (int ks = 0; ks < 4; ks++) {
        uint4 fa0 = sC[(r0 + g) * 16 + ks * 4 + tig];
        uint4 fa1 = sC[(r0 + g + 8) * 16 + ks * 4 + tig];
        unsigned ahi[4] = {fa0.x, fa1.x, fa0.z, fa1.z};
        unsigned alo[4] = {fa0.y, fa1.y, fa0.w, fa1.w};
        #pragma unroll
        for (int nt = 0; nt < 4; nt++) {
            uint4 fb = sST[(ks * 4 + tig) * 64 + cbn + nt * 8 + g];
            unsigned bhi[2] = {fb.x, fb.z}, blo[2] = {fb.y, fb.w};
            mma16(acc[nt], alo, bhi);
            mma16(acc[nt], ahi, blo);
            mma16(acc[nt], ahi, bhi);
        }
    }

    float dh = Dh[(2 * b + j) * NH + h];
    #pragma unroll
    for (int nt = 0; nt < 4; nt++) {
        int p = cbn + nt * 8 + 2 * tig;
        #pragma unroll
        for (int hf = 0; hf < 2; hf++) {
            int t = r0 + g + hf * 8;
            float e = __expf(scum[t]);
            long long ydx = (rowb + t) * DI + h * HD + p;
            float2 o = *(float2*)&g_y[ydx];
            float2 xs2 = *(const float2*)&g_xs[ydx];
            o.x += e * acc[nt][hf * 2]     + dh * xs2.x;
            o.y += e * acc[nt][hf * 2 + 1] + dh * xs2.y;
            *(float2*)&g_y[ydx] = o;
        }
    }
}

// ---------------- gate (silu(z)) + RMSNorm -> bf16 in A-layout ----------------
__global__ __launch_bounds__(256) void k_gate(const float* __restrict__ norm_w, int j) {
    int t = blockIdx.x, b = blockIdx.y;
    int lidx = 2 * b + j;
    const float* z = g_zx + ((long long)b * LP + t) * DPROJ;
    const float* yr = g_y + ((long long)b * LP + t) * DI;
    unsigned* yo = g_yB + ((long long)b * LP + t) * 512;
    int tid = threadIdx.x;
    int kt = tid >> 2, jj = tid & 3;
    int k0 = kt * 16 + jj * 2;
    float2 z0 = *(const float2*)&z[k0];
    float2 z1 = *(const float2*)&z[k0 + 8];
    float2 y0 = *(const float2*)&yr[k0];
    float2 y1 = *(const float2*)&yr[k0 + 8];
    float va = y0.x * (z0.x / (1.f + __expf(-z0.x)));
    float vb = y0.y * (z0.y / (1.f + __expf(-z0.y)));
    float vc = y1.x * (z1.x / (1.f + __expf(-z1.x)));
    float vd = y1.y * (z1.y / (1.f + __expf(-z1.y)));
    float ss = va * va + vb * vb + vc * vc + vd * vd;
    float tot = bsum(ss);
    float scale = rsqrtf(tot / (float)DI + 1e-5f);
    float2 n0 = *(const float2*)&norm_w[lidx * DI + k0];
    float2 n1 = *(const float2*)&norm_w[lidx * DI + k0 + 8];
    uint2 packed;
    packed.x = pack_bf16(va * scale * n0.x, vb * scale * n0.y);
    packed.y = pack_bf16(vc * scale * n1.x, vd * scale * n1.y);
    *(uint2*)&yo[kt * 8 + jj * 2] = packed;
}

// ---------------- final LayerNorm: fp32 hn + split pairs ----------------
__global__ __launch_bounds__(256) void k_ln(const float* __restrict__ lnw, const float* __restrict__ lnb) {
    int g = blockIdx.x;
    int b = g / L_TOK, t = g % L_TOK;
    const float* row = g_hcur + ((long long)b * LP + t) * DM;
    int tid = threadIdx.x;
    float2 v = *(const float2*)&row[2 * tid];
    float s = bsum(v.x + v.y);
    float sq = bsum(v.x * v.x + v.y * v.y);
    float mu = s / (float)DM;
    float var = sq / (float)DM - mu * mu;
    float inv = rsqrtf(var + 1e-5f);
    float o0 = (v.x - mu) * inv * lnw[2 * tid]     + lnb[2 * tid];
    float o1 = (v.y - mu) * inv * lnw[2 * tid + 1] + lnb[2 * tid + 1];
    *(float2*)&g_hn[(long long)g * DM + 2 * tid] = make_float2(o0, o1);
    g_hnS[(long long)g * 256 + tid] = split_bf16_pair(o0, o1);
}

// ---------------- attention scalar score ----------------
__global__ void k_score(const float* __restrict__ w2, const float* __restrict__ b2) {
    int g = blockIdx.x;
    int tid = threadIdx.x;
    float v = g_s1[(long long)g * 128 + tid] * w2[tid];
    v = bsum(v);
    if (tid == 0) g_scoreb[g] = v + b2[0];
}

// ---------------- softmax (+ zero pooled) ----------------
__global__ void k_softmax() {
    const int n = NB * L_TOK;
    __shared__ float red[32];
    __shared__ float s_max, s_sum;
    int tid = threadIdx.x;
    if (tid < DM) g_pooled[tid] = 0.f;
    float m = -1e30f;
    for (int i = tid; i < n; i += 1024) m = fmaxf(m, g_scoreb[i]);
    #pragma unroll
    for (int o = 16; o > 0; o >>= 1) m = fmaxf(m, __shfl_xor_sync(0xffffffffu, m, o));
    if ((tid & 31) == 0) red[tid >> 5] = m;
    __syncthreads();
    if (tid < 32) {
        float v = red[tid];
        #pragma unroll
        for (int o = 16; o > 0; o >>= 1) v = fmaxf(v, __shfl_xor_sync(0xffffffffu, v, o));
        if (tid == 0) s_max = v;
    }
    __syncthreads();
    float m0 = s_max;
    float s = 0.f;
    for (int i = tid; i < n; i += 1024) s += expf(g_scoreb[i] - m0);
    #pragma unroll
    for (int o = 16; o > 0; o >>= 1) s += __shfl_xor_sync(0xffffffffu, s, o);
    if ((tid & 31) == 0) red[tid >> 5] = s;
    __syncthreads();
    if (tid < 32) {
        float v = red[tid];
        #pragma unroll
        for (int o = 16; o > 0; o >>= 1) v += __shfl_xor_sync(0xffffffffu, v, o);
        if (tid == 0) s_sum = v;
    }
    __syncthreads();
    float inv = 1.f / s_sum;
    for (int i = tid; i < n; i += 1024) g_wts[i] = expf(g_scoreb[i] - m0) * inv;
}

// ---------------- pooled ----------------
#define PBLK 120
__global__ __launch_bounds__(256) void k_pooled() {
    const int total = NB * L_TOK;
    int per = (total + PBLK - 1) / PBLK;
    int g0 = blockIdx.x * per;
    int g1 = g0 + per; if (g1 > total) g1 = total;
    int tid = threadIdx.x;
    float a0 = 0.f, a1 = 0.f;
    for (int g = g0; g < g1; g++) {
        float w = g_wts[g];
        float2 v = *(const float2*)&g_hn[(long long)g * DM + 2 * tid];
        a0 = fmaf(w, v.x, a0);
        a1 = fmaf(w, v.y, a1);
    }
    atomicAdd(&g_pooled[2 * tid], a0);
    atomicAdd(&g_pooled[2 * tid + 1], a1);
}

// ---------------- final classifier ----------------
__global__ void k_final(const float* __restrict__ cls_w, const float* __restrict__ cls_b,
                        float* __restrict__ out, int out_size) {
    int tid = threadIdx.x;
    int cls = tid >> 5, lane = tid & 31;
    float acc = 0.f;
    for (int d = lane; d < DM; d += 32) acc += g_pooled[d] * cls_w[cls * DM + d];
    #pragma unroll
    for (int o = 16; o > 0; o >>= 1) acc += __shfl_xor_sync(0xffffffffu, acc, o);
    __shared__ float lg[2];
    if (lane == 0) lg[cls] = acc;
    __syncthreads();
    if (tid == 0) {
        float l0 = lg[0] + cls_b[0], l1 = lg[1] + cls_b[1];
        float m = fmaxf(l0, l1);
        float e0 = expf(l0 - m), e1 = expf(l1 - m);
        float s = e0 + e1;
        out[0] = l0;
        out[1] = l1;
        if (out_size >= 4) { out[2] = e0 / s; out[3] = e1 / s; }
    }
}

// ---------------- launch ----------------
static inline void launch_split(const float* src, void* dst, long long npairs) {
    k_split<<<(int)((npairs + 255) / 256), 256>>>(src, (uint2*)dst, npairs);
}

extern "C" void kernel_launch(void* const* d_in, const int* in_sizes, int n_in,
                              void* d_out, int out_size) {
    const float* x        = (const float*)d_in[0];
    const float* fc1_w    = (const float*)d_in[1];
    const float* fc1_b    = (const float*)d_in[2];
    const float* in_proj_w= (const float*)d_in[3];
    const float* conv_w   = (const float*)d_in[4];
    const float* conv_b   = (const float*)d_in[5];
    const float* dt_bias  = (const float*)d_in[6];
    const float* A_log    = (const float*)d_in[7];
    const float* Dh       = (const float*)d_in[8];
    const float* norm_w   = (const float*)d_in[9];
    const float* out_proj_w=(const float*)d_in[10];
    const float* ln_w     = (const float*)d_in[11];
    const float* ln_b     = (const float*)d_in[12];
    const float* attn_w1  = (const float*)d_in[13];
    const float* attn_b1  = (const float*)d_in[14];
    const float* attn_w2  = (const float*)d_in[15];
    const float* attn_b2  = (const float*)d_in[16];
    const float* cls_w    = (const float*)d_in[17];
    const float* cls_b    = (const float*)d_in[18];
    float* out = (float*)d_out;

    void *p_hcur, *p_zx, *p_s1;
    void *p_xS, *p_fc1wS, *p_ipw4, *p_opw4, *p_aw1S, *p_hcurB, *p_yB, *p_hnS;
    cudaGetSymbolAddress(&p_hcur,  g_hcur);
    cudaGetSymbolAddress(&p_zx,    g_zx);
    cudaGetSymbolAddress(&p_s1,    g_s1);
    cudaGetSymbolAddress(&p_xS,    g_xS);
    cudaGetSymbolAddress(&p_fc1wS, g_fc1wS);
    cudaGetSymbolAddress(&p_ipw4,  g_ipw4);
    cudaGetSymbolAddress(&p_opw4,  g_opw4);
    cudaGetSymbolAddress(&p_aw1S,  g_aw1S);
    cudaGetSymbolAddress(&p_hcurB, g_hcurB);
    cudaGetSymbolAddress(&p_yB,    g_yB);
    cudaGetSymbolAddress(&p_hnS,   g_hnS);

    cudaFuncSetAttribute(tgemm,  cudaFuncAttributeMaxDynamicSharedMemorySize, TG_SMEM);
    cudaFuncSetAttribute(tgemm2, cudaFuncAttributeMaxDynamicSharedMemorySize, TG2_SMEM);
    cudaFuncSetAttribute(k_intra_mma, cudaFuncAttributeMaxDynamicSharedMemorySize, SMEM_INTRA_MMA);

    // 1: merged splits
    {
        long long tot = NPX + NPF + NW4;
        k_split_all<<<(int)((tot + 255) / 256), 256>>>(x, fc1_w, in_proj_w);
    }
    // 2: fc1
    {
        dim3 grid((DM + 127) / 128, (L_TOK + 127) / 128, 1);
        tgemm<<<grid, 256, TG_SMEM>>>((const uint2*)p_xS, 0, (const uint2*)p_fc1wS, 0, fc1_b,
                                      (float*)p_hcur, 0, (unsigned*)p_hcurB, L_TOK, DM, 512, 2, 0);
    }
    // 3: branch prep + pad zero
    {
        long long tot = (long long)L_TOK * 128 + (long long)NB * (LP - L_TOK) * 128;
        k_prep2<<<(int)((tot + 255) / 256), 256>>>();
    }

    for (int j = 0; j < 2; j++) {
        // 4 (j=0): in_proj <- ncu capture window
        {
            dim3 g1((DPROJ + 127) / 128, (LP + 127) / 128, NB);
            tgemm2<<<g1, 256, TG2_SMEM>>>((const uint2*)p_hcurB, (long long)LP * 128,
                                          (const uint4*)p_ipw4, (long long)DPROJ * 128,
                                          (float*)p_zx, (long long)LP * DPROJ, nullptr,
                                          LP, DPROJ, 256, 0, j);
        }
        k_convfused<<<dim3(NC, NB), 256>>>(conv_w, conv_b, dt_bias, A_log, j);
        {
            long long tot = 2LL * NB * LP * 16;
            k_splitBC<<<(int)((tot + 255) / 256), 256>>>();
        }
        k_intra_mma<<<dim3(NC, NH, NB), 256, SMEM_INTRA_MMA>>>();
        k_rec<<<dim3(NB * NH, 4), 256>>>();
        k_inter_mma<<<dim3(NC, NH, NB), 256>>>(Dh, j);
        k_gate<<<dim3(LP, NB), 256>>>(norm_w, j);
        if (j == 0) {
            long long nu4 = (long long)6 * DM * 256;
            k_splitW<<<(int)((nu4 + 255) / 256), 256>>>(out_proj_w, (uint4*)p_opw4, nu4, 1024);
        }
        {
            dim3 g2((DM + 127) / 128, (LP + 127) / 128, NB);
            tgemm2<<<g2, 256, TG2_SMEM>>>((const uint2*)p_yB, (long long)LP * 256,
                                          (const uint4*)p_opw4, (long long)DM * 256,
                                          (float*)p_hcur, (long long)LP * DM,
                                          (j == 0) ? (unsigned*)p_hcurB : nullptr,
                                          LP, DM, 512, 1, j);
        }
    }

    // final head
    k_ln<<<NB * L_TOK, 256>>>(ln_w, ln_b);
    launch_split(attn_w1, p_aw1S, (long long)128 * 256);
    {
        dim3 ga(1, (NB * L_TOK + 127) / 128, 1);
        tgemm<<<ga, 256, TG_SMEM>>>((const uint2*)p_hnS, 0, (const uint2*)p_aw1S, 0, attn_b1,
                                    (float*)p_s1, 0, nullptr, NB * L_TOK, 128, 256, 3, 0);
    }
    k_score<<<NB * L_TOK, 128>>>(attn_w2, attn_b2);
    k_softmax<<<1, 1024>>>();
    k_pooled<<<PBLK, 256>>>();
    k_final<<<1, 64>>>(cls_w, cls_b, out, out_size);
}

// round 17
// speedup vs baseline: 1.3676x; 1.0072x over previous
#include <cuda_runtime.h>
#include <cuda_bf16.h>
#include <math.h>

// ---------------- problem constants ----------------
#define L_TOK 10000
#define LP    10048
#define NC    157
#define Q     64
#define DM    512
#define DI    1024
#define DS    64
#define NH    16
#define HD    64
#define DXBC  1152
#define DPROJ 2192
#define NB    3

// ---------------- scratch ----------------
__device__ __align__(16) float g_hcur [(size_t)NB*LP*DM];
__device__ __align__(16) float g_zx   [(size_t)NB*LP*DPROJ];
__device__ __align__(16) float g_xs   [(size_t)NB*LP*DI];
__device__ __align__(16) float g_Bm   [(size_t)NB*LP*DS];
__device__ __align__(16) float g_Cm   [(size_t)NB*LP*DS];
__device__ __align__(16) float g_dtv  [(size_t)NB*LP*NH];
__device__ __align__(16) float g_cum  [(size_t)NB*NH*LP];
__device__ __align__(16) float g_y    [(size_t)NB*LP*DI];
__device__ __align__(16) float g_schunk[(size_t)NB*NH*NC*DS*HD];
__device__ __align__(16) float g_sbef  [(size_t)NB*NH*NC*DS*HD];
__device__ __align__(16) float g_hn   [(size_t)NB*L_TOK*DM];
__device__ __align__(16) float g_s1   [(size_t)NB*L_TOK*128];
__device__ float g_scoreb[NB*L_TOK];
__device__ float g_wts   [NB*L_TOK];
__device__ float g_pooled[DM];

// fragment-layout split buffers (uint4 {hi(p),lo(p),hi(p+4),lo(p+4)} per (row, kt, tig))
__device__ __align__(16) uint4 g_xF   [(size_t)L_TOK*256];     // K=1024
__device__ __align__(16) uint4 g_fc1wF[(size_t)DM*256];        // K=1024
__device__ __align__(16) uint4 g_aw1F [(size_t)128*128];       // K=512
__device__ __align__(16) uint4 g_hnF  [(size_t)NB*L_TOK*128];  // K=512
__device__ __align__(16) uint4 g_ipw4 [(size_t)6*DPROJ*128];   // K=512
__device__ __align__(16) uint4 g_opw4 [(size_t)6*DM*256];      // K=1024
// B/C split, fragment layout: per row 16 x uint4
__device__ __align__(16) uint4 g_CmS [(size_t)NB*LP*16];
__device__ __align__(16) uint4 g_BmS [(size_t)NB*LP*16];
// A plain-bf16, ktile layout
__device__ __align__(16) unsigned g_hcurB[(size_t)NB*LP*256];
__device__ __align__(16) unsigned g_yB   [(size_t)NB*LP*512];

__device__ __forceinline__ int a2i(int p) {
    return (p & ~7) | ((p & 3) << 1) | ((p >> 2) & 1);
}

// ---------------- helpers ----------------
__device__ __forceinline__ float bsum(float v) {
    __shared__ float sh[32];
    int lane = threadIdx.x & 31, w = threadIdx.x >> 5;
    #pragma unroll
    for (int o = 16; o > 0; o >>= 1) v += __shfl_xor_sync(0xffffffffu, v, o);
    if (lane == 0) sh[w] = v;
    __syncthreads();
    int nw = blockDim.x >> 5;
    v = (threadIdx.x < nw) ? sh[threadIdx.x] : 0.f;
    if (w == 0) {
        #pragma unroll
        for (int o = 16; o > 0; o >>= 1) v += __shfl_xor_sync(0xffffffffu, v, o);
        if (threadIdx.x == 0) sh[0] = v;
    }
    __syncthreads();
    float r = sh[0];
    __syncthreads();
    return r;
}

__device__ __forceinline__ unsigned pack_bf16(float f0, float f1) {
    unsigned r;
    asm("cvt.rn.bf16x2.f32 %0, %1, %2;" : "=r"(r) : "f"(f1), "f"(f0));
    return r;
}

__device__ __forceinline__ uint2 split_bf16_pair(float f0, float f1) {
    unsigned hp, lp;
    asm("cvt.rn.bf16x2.f32 %0, %1, %2;" : "=r"(hp) : "f"(f1), "f"(f0));
    __nv_bfloat162 h = *reinterpret_cast<__nv_bfloat162*>(&hp);
    float r0 = f0 - __bfloat162float(h.x);
    float r1 = f1 - __bfloat162float(h.y);
    asm("cvt.rn.bf16x2.f32 %0, %1, %2;" : "=r"(lp) : "f"(r1), "f"(r0));
    uint2 q; q.x = hp; q.y = lp;
    return q;
}

// fragment split of one uint4 slot for row-major fp32 source
__device__ __forceinline__ uint4 fragW(const float* rp, int rem) {
    int kt = rem >> 2, tig = rem & 3;
    int k0 = kt * 16 + tig * 2;
    float2 va = *(const float2*)&rp[k0];
    float2 vb = *(const float2*)&rp[k0 + 8];
    uint2 sa = split_bf16_pair(va.x, va.y);
    uint2 sb = split_bf16_pair(vb.x, vb.y);
    return make_uint4(sa.x, sa.y, sb.x, sb.y);
}

// merged fragment split of x (K=1024), fc1_w (K=1024), in_proj_w (K=512)
#define NX4 ((long long)L_TOK * 256)
#define NF4 ((long long)DM * 256)
#define NW4 ((long long)6 * DPROJ * 128)
__global__ void k_split_all(const float* __restrict__ x, const float* __restrict__ fw,
                            const float* __restrict__ iw) {
    long long i = (long long)blockIdx.x * 256 + threadIdx.x;
    if (i < NX4) {
        long long row = i >> 8;
        g_xF[i] = fragW(x + row * 1024, (int)(i & 255));
        return;
    }
    if (i < NX4 + NF4) {
        long long u = i - NX4;
        long long row = u >> 8;
        g_fc1wF[u] = fragW(fw + row * 1024, (int)(u & 255));
        return;
    }
    long long u = i - NX4 - NF4;
    if (u >= NW4) return;
    long long row = u >> 7;
    g_ipw4[u] = fragW(iw + row * 512, (int)(u & 127));
}

// split W into ktile-fragment layout (out_proj K=1024, attn1 K=512)
__global__ void k_splitW(const float* __restrict__ src, uint4* __restrict__ dst,
                         long long nu4, int K) {
    long long u = (long long)blockIdx.x * 256 + threadIdx.x;
    if (u >= nu4) return;
    int perrow = K >> 2;
    long long row = u / perrow;
    dst[u] = fragW(src + row * K, (int)(u % perrow));
}

// split B,C into fragment layout (per layer)
__global__ void k_splitBC() {
    const long long N1 = (long long)NB * LP * 16;
    long long u = (long long)blockIdx.x * 256 + threadIdx.x;
    const float* src; uint4* dst; long long v;
    if (u < N1) { src = g_Cm; dst = g_CmS; v = u; }
    else if (u < 2 * N1) { src = g_Bm; dst = g_BmS; v = u - N1; }
    else return;
    long long row = v >> 4;
    dst[v] = fragW(src + row * DS, (int)(v & 15));
}

__device__ __forceinline__ void mma16(float c[4], const unsigned a[4], const unsigned b[2]) {
    asm volatile(
        "mma.sync.aligned.m16n8k16.row.col.f32.bf16.bf16.f32 "
        "{%0,%1,%2,%3},{%4,%5,%6,%7},{%8,%9},{%0,%1,%2,%3};"
        : "+f"(c[0]), "+f"(c[1]), "+f"(c[2]), "+f"(c[3])
        : "r"(a[0]), "r"(a[1]), "r"(a[2]), "r"(a[3]), "r"(b[0]), "r"(b[1]));
}

__device__ __forceinline__ void cp16(unsigned dst, const void* src, bool pred) {
    int sz = pred ? 16 : 0;
    asm volatile("cp.async.cg.shared.global [%0], [%1], 16, %2;" :: "r"(dst), "l"(src), "r"(sz));
}

// ---------------- tgemm3: split-A x split-W (3 mma), fragment layout, all cp16 ----------------
// used for fc1 (op=2: relu+bias, aux bf16 in A-layout) and attn1 (op=3: tanh+bias)
#define NS3 3
#define TG3_SMEM (NS3 * 2 * (128 * 64 + 128 * 64))

__global__ __launch_bounds__(256, 2) void tgemm3(
    const uint4* __restrict__ A,
    const uint4* __restrict__ W,
    const float* __restrict__ bias,
    float* __restrict__ C,
    unsigned* __restrict__ Caux,
    int M, int N, int Kp, int op)
{
    extern __shared__ char smc[];
    uint4* Asm = (uint4*)smc;                               // NS3*2 ktiles * 128 rows * 4 uint4
    uint4* Wsm = (uint4*)(smc + NS3 * 2 * 128 * 64);

    int tid = threadIdx.x;
    int warp = tid >> 5, lane = tid & 31;
    int wm = warp & 3, wn = warp >> 2;        // 4 m-warps x 2 n-warps, warp tile 32x64
    int g = lane >> 2, tig = lane & 3;
    int row0 = blockIdx.y * 128, col0 = blockIdx.x * 128;

    int ar = tid >> 1, half = tid & 1;
    bool aok = (row0 + ar) < M;
    bool wok = (col0 + ar) < N;
    int pru4 = Kp >> 1;                        // uint4 per row
    const uint4* AgP = A + (long long)(row0 + ar) * pru4 + half * 2;
    const uint4* WgP = W + (long long)(col0 + ar) * pru4 + half * 2;
    unsigned aB = (unsigned)__cvta_generic_to_shared(Asm);
    unsigned wB = (unsigned)__cvta_generic_to_shared(Wsm);

    float c[2][8][4];
    #pragma unroll
    for (int mt = 0; mt < 2; mt++)
        #pragma unroll
        for (int nt = 0; nt < 8; nt++)
            #pragma unroll
            for (int q = 0; q < 4; q++) c[mt][nt][q] = 0.f;

    int nG = Kp >> 4;   // groups of 2 ktiles

    // issue group at current pointers into slot s, then advance pointers
    #define ISSUEG3(s) do { \
        _Pragma("unroll") \
        for (int u = 0; u < 2; u++) { \
            cp16(aB + (unsigned)((((s) * 2 + u) * 128 + ar) * 64 + half * 32),      AgP + u * 4,     aok); \
            cp16(aB + (unsigned)((((s) * 2 + u) * 128 + ar) * 64 + half * 32 + 16), AgP + u * 4 + 1, aok); \
            cp16(wB + (unsigned)((((s) * 2 + u) * 128 + ar) * 64 + half * 32),      WgP + u * 4,     wok); \
            cp16(wB + (unsigned)((((s) * 2 + u) * 128 + ar) * 64 + half * 32 + 16), WgP + u * 4 + 1, wok); \
        } \
        AgP += 8; WgP += 8; \
    } while (0)

    ISSUEG3(0);
    asm volatile("cp.async.commit_group;");
    ISSUEG3(1);
    asm volatile("cp.async.commit_group;");

    int sc = 0, si = 2;
    for (int gi = 0; gi < nG; gi++) {
        asm volatile("cp.async.wait_group 1;");
        __syncthreads();

        #pragma unroll
        for (int u = 0; u < 2; u++) {
            const uint4* Ab = Asm + (sc * 2 + u) * 128 * 4;
            const uint4* Wb = Wsm + (sc * 2 + u) * 128 * 4;

            unsigned ahi[2][4], alo[2][4];
            #pragma unroll
            for (int mt = 0; mt < 2; mt++) {
                int m0 = wm * 32 + mt * 16;
                uint4 fa0 = Ab[(m0 + g) * 4 + tig];
                uint4 fa1 = Ab[(m0 + g + 8) * 4 + tig];
                ahi[mt][0] = fa0.x; ahi[mt][1] = fa1.x; ahi[mt][2] = fa0.z; ahi[mt][3] = fa1.z;
                alo[mt][0] = fa0.y; alo[mt][1] = fa1.y; alo[mt][2] = fa0.w; alo[mt][3] = fa1.w;
            }
            #pragma unroll
            for (int nt = 0; nt < 8; nt++) {
                int n0 = wn * 64 + nt * 8;
                uint4 fb = Wb[(n0 + g) * 4 + tig];
                unsigned bhi[2] = {fb.x, fb.z};
                unsigned blo[2] = {fb.y, fb.w};
                #pragma unroll
                for (int mt = 0; mt < 2; mt++) {
                    mma16(c[mt][nt], alo[mt], bhi);
                    mma16(c[mt][nt], ahi[mt], blo);
                    mma16(c[mt][nt], ahi[mt], bhi);
                }
            }
        }

        if (gi + 2 < nG) ISSUEG3(si);
        asm volatile("cp.async.commit_group;");
        sc++; if (sc == NS3) sc = 0;
        si++; if (si == NS3) si = 0;
    }
    asm volatile("cp.async.wait_all;");

    #pragma unroll
    for (int mt = 0; mt < 2; mt++) {
        #pragma unroll
        for (int nt = 0; nt < 8; nt++) {
            int cc = col0 + wn * 64 + nt * 8 + 2 * tig;
            if (cc >= N) continue;
            #pragma unroll
            for (int hf = 0; hf < 2; hf++) {
                int r = row0 + wm * 32 + mt * 16 + g + hf * 8;
                if (r >= M) continue;
                float v0 = c[mt][nt][hf * 2 + 0];
                float v1 = c[mt][nt][hf * 2 + 1];
                long long ci = (long long)r * N + cc;
                if (op == 2) {
                    v0 = fmaxf(v0 + bias[cc], 0.f);
                    v1 = fmaxf(v1 + bias[cc + 1], 0.f);
                    *(float2*)&C[ci] = make_float2(v0, v1);
                    if (Caux) Caux[(long long)r * (N >> 1) + a2i(cc >> 1)] = pack_bf16(v0, v1);
                } else {
                    v0 += bias[cc]; v1 += bias[cc + 1];
                    *(float2*)&C[ci] = make_float2(tanhf(v0), tanhf(v1));
                }
            }
        }
    }
    #undef ISSUEG3
}

// ---------------- tgemm2: bf16-A x split-W, all cp16, NSLOT=4, unrolled slots (frozen R16) ----------------
#define NSLOT 4
#define TG2_SMEM (NSLOT * 2 * (128 * 32 + 128 * 64))

__global__ __launch_bounds__(256, 2) void tgemm2(
    const uint2* __restrict__ A, long long sA,
    const uint4* __restrict__ W, long long sW,
    float* __restrict__ C, long long sC,
    unsigned* __restrict__ Caux,
    int M, int N, int Kp, int op, int joff)
{
    extern __shared__ char smc[];
    uint2* Asm = (uint2*)smc;
    uint4* Wsm = (uint4*)(smc + NSLOT * 2 * 128 * 32);

    int z = blockIdx.z;
    A += (long long)z * sA;
    C += (long long)z * sC;
    W += (long long)(2 * z + joff) * sW;
    if (Caux) Caux += (long long)z * (sC >> 1);

    int tid = threadIdx.x;
    int warp = tid >> 5, lane = tid & 31;
    int wm = warp & 1, wn = warp >> 1;
    int g = lane >> 2, tig = lane & 3;
    int row0 = blockIdx.y * 128, col0 = blockIdx.x * 128;

    int ar = tid >> 1, half = tid & 1;
    bool aok = (row0 + ar) < M;
    bool wok = (col0 + ar) < N;
    int pr = Kp >> 1;
    const uint2* Ag = A + (long long)(row0 + ar) * pr + half * 2;
    const uint4* Wg = W + (long long)(col0 + ar) * pr + half * 2;
    unsigned aB = (unsigned)__cvta_generic_to_shared(Asm);
    unsigned wB = (unsigned)__cvta_generic_to_shared(Wsm);

    float c[4][4][4];
    #pragma unroll
    for (int mt = 0; mt < 4; mt++)
        #pragma unroll
        for (int nt = 0; nt < 4; nt++)
            #pragma unroll
            for (int q = 0; q < 4; q++) c[mt][nt][q] = 0.f;

    int nG = Kp >> 4;

    #define ISSUEG(gi, s) do { \
        _Pragma("unroll") \
        for (int u = 0; u < 2; u++) { \
            int _kt = (gi) * 2 + u; \
            cp16(aB + (unsigned)((((s) * 2 + u) * 128 + ar) * 32 + half * 16), Ag + _kt * 4, aok); \
            cp16(wB + (unsigned)((((s) * 2 + u) * 128 + ar) * 64 + half * 32),      Wg + _kt * 4,     wok); \
            cp16(wB + (unsigned)((((s) * 2 + u) * 128 + ar) * 64 + half * 32 + 16), Wg + _kt * 4 + 1, wok); \
        } \
    } while (0)

    #define COMPUTE(ss) do { \
        _Pragma("unroll") \
        for (int u = 0; u < 2; u++) { \
            const uint2* Ab = Asm + ((ss) * 2 + u) * 128 * 4; \
            const uint4* Wb = Wsm + ((ss) * 2 + u) * 128 * 4; \
            unsigned a[4][4]; \
            _Pragma("unroll") \
            for (int mt = 0; mt < 4; mt++) { \
                int m0 = wm * 64 + mt * 16; \
                uint2 q0 = Ab[(m0 + g) * 4 + tig]; \
                uint2 q1 = Ab[(m0 + g + 8) * 4 + tig]; \
                a[mt][0] = q0.x; a[mt][1] = q1.x; \
                a[mt][2] = q0.y; a[mt][3] = q1.y; \
            } \
            _Pragma("unroll") \
            for (int nt = 0; nt < 4; nt++) { \
                int n0 = wn * 32 + nt * 8; \
                uint4 fb = Wb[(n0 + g) * 4 + tig]; \
                unsigned bhi[2] = {fb.x, fb.z}; \
                unsigned blo[2] = {fb.y, fb.w}; \
                _Pragma("unroll") \
                for (int mt = 0; mt < 4; mt++) { \
                    mma16(c[mt][nt], a[mt], blo); \
                    mma16(c[mt][nt], a[mt], bhi); \
                } \
            } \
        } \
    } while (0)

    ISSUEG(0, 0);
    asm volatile("cp.async.commit_group;");
    ISSUEG(1, 1);
    asm volatile("cp.async.commit_group;");
    ISSUEG(2, 2);
    asm volatile("cp.async.commit_group;");

    for (int gq = 0; gq < nG; gq += 4) {
        #pragma unroll
        for (int ss = 0; ss < 4; ss++) {
            asm volatile("cp.async.wait_group 2;");
            __syncthreads();
            COMPUTE(ss);
            int pre = gq + ss + 3;
            if (pre < nG) ISSUEG(pre, (ss + 3) & 3);
            asm volatile("cp.async.commit_group;");
        }
    }
    asm volatile("cp.async.wait_all;");

    #pragma unroll
    for (int mt = 0; mt < 4; mt++) {
        #pragma unroll
        for (int nt = 0; nt < 4; nt++) {
            int cc = col0 + wn * 32 + nt * 8 + 2 * tig;
            if (cc >= N) continue;
            #pragma unroll
            for (int hf = 0; hf < 2; hf++) {
                int r = row0 + wm * 64 + mt * 16 + g + hf * 8;
                if (r >= M) continue;
                float v0 = c[mt][nt][hf * 2 + 0];
                float v1 = c[mt][nt][hf * 2 + 1];
                long long ci = (long long)r * N + cc;
                if (op == 0) {
                    *(float2*)&C[ci] = make_float2(v0, v1);
                } else {
                    float2 o = *(float2*)&C[ci];
                    o.x += v0; o.y += v1;
                    *(float2*)&C[ci] = o;
                    if (Caux) Caux[(long long)r * (N >> 1) + a2i(cc >> 1)] = pack_bf16(o.x, o.y);
                }
            }
        }
    }
    #undef ISSUEG
    #undef COMPUTE
}

// ---------------- branch prep + pad-row zeroing ----------------
__global__ void k_prep2() {
    long long i = (long long)blockIdx.x * 256 + threadIdx.x;
    const long long mainN = (long long)L_TOK * 128;
    if (i < mainN) {
        int t = (int)(i >> 7), q = (int)(i & 127);
        float4 v = *((const float4*)g_hcur + (long long)t * 128 + q);
        int d0 = q * 4, p = q * 2;
        *(float4*)&g_hcur[(long long)LP * DM + (long long)t * DM + (508 - d0)] =
            make_float4(v.w, v.z, v.y, v.x);
        g_hcurB[(long long)LP * 256 + (long long)t * 256 + a2i(255 - p)] = pack_bf16(v.y, v.x);
        g_hcurB[(long long)LP * 256 + (long long)t * 256 + a2i(254 - p)] = pack_bf16(v.w, v.z);
        int tt = (t % 100) * 100 + t / 100;
        *(float4*)&g_hcur[2LL * LP * DM + (long long)tt * DM + d0] = v;
        g_hcurB[2LL * LP * 256 + (long long)tt * 256 + a2i(p)]     = pack_bf16(v.x, v.y);
        g_hcurB[2LL * LP * 256 + (long long)tt * 256 + a2i(p + 1)] = pack_bf16(v.z, v.w);
        return;
    }
    long long j = i - mainN;
    if (j >= (long long)NB * (LP - L_TOK) * 128) return;
    int b = (int)(j / ((LP - L_TOK) * 128));
    int rem = (int)(j % ((LP - L_TOK) * 128));
    int t = L_TOK + rem / 128, q = rem % 128;
    *(float4*)&g_hcur[((long long)b * LP + t) * DM + q * 4] = make_float4(0.f, 0.f, 0.f, 0.f);
    g_hcurB[((long long)b * LP + t) * 256 + q * 2]     = 0u;
    g_hcurB[((long long)b * LP + t) * 256 + q * 2 + 1] = 0u;
}

// ---------------- fused conv + silu + dt + cumsum ----------------
__global__ __launch_bounds__(256) void k_convfused(
    const float* __restrict__ cw, const float* __restrict__ cb,
    const float* __restrict__ dt_bias, const float* __restrict__ A_log, int j)
{
    __shared__ float av_s[NH * 64];
    int c = blockIdx.x, b = blockIdx.y;
    int lidx = 2 * b + j;
    int tid = threadIdx.x;
    const float* zbase = g_zx + (long long)b * LP * DPROJ;
    int gt0 = c * Q;

    for (int cc = tid; cc < DXBC; cc += 256) {
        const float* col = zbase + DI + cc;
        const float* wp = cw + (long long)(lidx * DXBC + cc) * 4;
        float w0 = wp[0], w1 = wp[1], w2 = wp[2], w3 = wp[3];
        float bia = cb[lidx * DXBC + cc];
        float h3 = (gt0 - 3 >= 0) ? col[(long long)(gt0 - 3) * DPROJ] : 0.f;
        float h2 = (gt0 - 2 >= 0) ? col[(long long)(gt0 - 2) * DPROJ] : 0.f;
        float h1 = (gt0 - 1 >= 0) ? col[(long long)(gt0 - 1) * DPROJ] : 0.f;
        #pragma unroll 4
        for (int t = 0; t < Q; t++) {
            int gt = gt0 + t;
            float cur = col[(long long)gt * DPROJ];
            float a = bia + w0 * h3 + w1 * h2 + w2 * h1 + w3 * cur;
            float v = a / (1.f + __expf(-a));
            if (gt >= L_TOK) v = 0.f;
            long long tb = (long long)b * LP + gt;
            if (cc < DI)            g_xs[tb * DI + cc] = v;
            else if (cc < DI + DS)  g_Bm[tb * DS + (cc - DI)] = v;
            else                    g_Cm[tb * DS + (cc - DI - DS)] = v;
            h3 = h2; h2 = h1; h1 = cur;
        }
    }

    #pragma unroll
    for (int k = 0; k < 4; k++) {
        int idx = tid + k * 256;
        int h = idx & 15, t = idx >> 4;
        int gt = gt0 + t;
        float draw = zbase[(long long)gt * DPROJ + DI + DXBC + h];
        float xv = draw + dt_bias[lidx * NH + h];
        float sp = (xv > 20.f) ? xv : log1pf(expf(xv));
        if (gt >= L_TOK) sp = 0.f;
        g_dtv[((long long)b * LP + gt) * NH + h] = sp;
        float Ah = -expf(A_log[lidx * NH + h]);
        av_s[h * 64 + t] = sp * Ah;
    }
    __syncthreads();

    int warp = tid >> 5, lane = tid & 31;
    #pragma unroll
    for (int hh = 0; hh < 2; hh++) {
        int h = warp * 2 + hh;
        float x1 = av_s[h * 64 + lane];
        float x2 = av_s[h * 64 + 32 + lane];
        #pragma unroll
        for (int o = 1; o < 32; o <<= 1) { float yv = __shfl_up_sync(0xffffffffu, x1, o); if (lane >= o) x1 += yv; }
        #pragma unroll
        for (int o = 1; o < 32; o <<= 1) { float yv = __shfl_up_sync(0xffffffffu, x2, o); if (lane >= o) x2 += yv; }
        float tot1 = __shfl_sync(0xffffffffu, x1, 31);
        x2 += tot1;
        long long base = (long long)(b * NH + h) * LP + (long long)c * Q;
        g_cum[base + lane] = x1;
        g_cum[base + 32 + lane] = x2;
    }
}

// ---------------- intra-chunk (tensor-core); C/B tiles copied pre-split ----------------
#define SMEM_INTRA_MMA (4096 * 16 + 512)
__global__ __launch_bounds__(256) void k_intra_mma() {
    extern __shared__ uint4 smu[];
    uint4* sC  = smu;
    uint4* sB  = smu + 1024;
    uint4* sUT = smu + 2048;
    uint4* sBw = smu + 3072;
    float* scum = (float*)(smu + 4096);
    float* sdt  = scum + 64;

    int c = blockIdx.x, h = blockIdx.y, b = blockIdx.z;
    long long rowb = (long long)b * LP + (long long)c * Q;
    int tid = threadIdx.x;

    if (tid < 64) {
        scum[tid] = g_cum[(long long)(b * NH + h) * LP + (long long)c * Q + tid];
        sdt[tid]  = g_dtv[(rowb + tid) * NH + h];
    }
    __syncthreads();
    float T = scum[63];

    {
        const uint4* gC = g_CmS + rowb * 16;
        const uint4* gB = g_BmS + rowb * 16;
        for (int i = tid; i < 1024; i += 256) {
            sC[i] = gC[i];
            sB[i] = gB[i];
        }
    }
    for (int i = tid; i < 1024; i += 256) {
        int slot = i >> 6, row = i & 63;
        int ks = slot >> 2, tg = slot & 3;
        int k0 = ks * 16 + tg * 2;
        float u0 = sdt[k0]     * g_xs[(rowb + k0)     * DI + h * HD + row];
        float u1 = sdt[k0 + 1] * g_xs[(rowb + k0 + 1) * DI + h * HD + row];
        float u2 = sdt[k0 + 8] * g_xs[(rowb + k0 + 8) * DI + h * HD + row];
        float u3 = sdt[k0 + 9] * g_xs[(rowb + k0 + 9) * DI + h * HD + row];
        uint2 uh0 = split_bf16_pair(u0, u1);
        uint2 uh1 = split_bf16_pair(u2, u3);
        sUT[i] = make_uint4(uh0.x, uh0.y, uh1.x, uh1.y);
        float bw0 = g_Bm[(rowb + k0)     * DS + row] * __expf(T - scum[k0]);
        float bw1 = g_Bm[(rowb + k0 + 1) * DS + row] * __expf(T - scum[k0 + 1]);
        float bw2 = g_Bm[(rowb + k0 + 8) * DS + row] * __expf(T - scum[k0 + 8]);
        float bw3 = g_Bm[(rowb + k0 + 9) * DS + row] * __expf(T - scum[k0 + 9]);
        uint2 wh0 = split_bf16_pair(bw0, bw1);
        uint2 wh1 = split_bf16_pair(bw2, bw3);
        sBw[i] = make_uint4(wh0.x, wh0.y, wh1.x, wh1.y);
    }
    __syncthreads();

    int warp = tid >> 5, lane = tid & 31;
    int g = lane >> 2, tig = lane & 3;
    int r0 = (warp & 3) * 16, cbn = (warp >> 2) * 32;

    float accP[4][4];
    #pragma unroll
    for (int nt = 0; nt < 4; nt++)
        #pragma unroll
        for (int q = 0; q < 4; q++) accP[nt][q] = 0.f;
    #pragma unroll
    for (int ks = 0; ks < 4; ks++) {
        uint4 fa0 = sC[(r0 + g) * 16 + ks * 4 + tig];
        uint4 fa1 = sC[(r0 + g + 8) * 16 + ks * 4 + tig];
        unsigned ahi[4] = {fa0.x, fa1.x, fa0.z, fa1.z};
        unsigned alo[4] = {fa0.y, fa1.y, fa0.w, fa1.w};
        #pragma unroll
        for (int nt = 0; nt < 4; nt++) {
            uint4 fb = sB[(cbn + nt * 8 + g) * 16 + ks * 4 + tig];
            unsigned bhi[2] = {fb.x, fb.z}, blo[2] = {fb.y, fb.w};
            mma16(accP[nt], alo, bhi);
            mma16(accP[nt], ahi, blo);
            mma16(accP[nt], ahi, bhi);
        }
    }
    __syncthreads();

    uint2* sP2 = (uint2*)sB;
    #pragma unroll
    for (int nt = 0; nt < 4; nt++) {
        int scol = cbn + nt * 8 + 2 * tig;
        int Pp = scol >> 1;
        int ksp = Pp >> 3, tslot = Pp & 3, halfp = (Pp >> 2) & 1;
        #pragma unroll
        for (int hf = 0; hf < 2; hf++) {
            int t = r0 + g + hf * 8;
            float v0 = accP[nt][hf * 2], v1 = accP[nt][hf * 2 + 1];
            v0 = (scol     <= t) ? v0 * __expf(scum[t] - scum[scol])     : 0.f;
            v1 = (scol + 1 <= t) ? v1 * __expf(scum[t] - scum[scol + 1]) : 0.f;
            sP2[((ksp * 4 + tslot) * 64 + t) * 2 + halfp] = split_bf16_pair(v0, v1);
        }
    }
    __syncthreads();

    float accY[4][4], accS[4][4];
    #pragma unroll
    for (int nt = 0; nt < 4; nt++)
        #pragma unroll
        for (int q = 0; q < 4; q++) { accY[nt][q] = 0.f; accS[nt][q] = 0.f; }
    uint4* sP = sB;
    #pragma unroll
    for (int ks = 0; ks < 4; ks++) {
        uint4 fp0 = sP[(ks * 4 + tig) * 64 + r0 + g];
        uint4 fp1 = sP[(ks * 4 + tig) * 64 + r0 + g + 8];
        unsigned phi[4] = {fp0.x, fp1.x, fp0.z, fp1.z};
        unsigned plo[4] = {fp0.y, fp1.y, fp0.w, fp1.w};
        uint4 fw0 = sBw[(ks * 4 + tig) * 64 + r0 + g];
        uint4 fw1 = sBw[(ks * 4 + tig) * 64 + r0 + g + 8];
        unsigned whi[4] = {fw0.x, fw1.x, fw0.z, fw1.z};
        unsigned wlo[4] = {fw0.y, fw1.y, fw0.w, fw1.w};
        #pragma unroll
        for (int nt = 0; nt < 4; nt++) {
            uint4 fb = sUT[(ks * 4 + tig) * 64 + cbn + nt * 8 + g];
            unsigned bhi[2] = {fb.x, fb.z}, blo[2] = {fb.y, fb.w};
            mma16(accY[nt], plo, bhi); mma16(accY[nt], phi, blo); mma16(accY[nt], phi, bhi);
            mma16(accS[nt], wlo, bhi); mma16(accS[nt], whi, blo); mma16(accS[nt], whi, bhi);
        }
    }

    long long sbase = ((long long)(b * NH + h) * NC + c) * 4096;
    #pragma unroll
    for (int nt = 0; nt < 4; nt++) {
        int p = cbn + nt * 8 + 2 * tig;
        #pragma unroll
        for (int hf = 0; hf < 2; hf++) {
            int r = r0 + g + hf * 8;
            *(float2*)&g_y[(rowb + r) * DI + h * HD + p] =
                make_float2(accY[nt][hf * 2], accY[nt][hf * 2 + 1]);
            *(float2*)&g_schunk[sbase + r * 64 + p] =
                make_float2(accS[nt][hf * 2], accS[nt][hf * 2 + 1]);
        }
    }
}

// ---------------- chunk-state recurrence (4-way split, prefetched) ----------------
__global__ __launch_bounds__(256) void k_rec() {
    int bh = blockIdx.x;
    int qd = blockIdx.y;
    int tid = threadIdx.x;
    int off = qd * 1024 + tid;
    float S[4], v[4], nv[4];
    #pragma unroll
    for (int i = 0; i < 4; i++) S[i] = 0.f;
    const float* cumrow = g_cum + (long long)bh * LP;
    long long base = (long long)bh * NC * 4096;
    #pragma unroll
    for (int i = 0; i < 4; i++) v[i] = g_schunk[base + off + i * 256];
    for (int c = 0; c < NC; c++) {
        float e = __expf(cumrow[c * Q + 63]);
        if (c + 1 < NC) {
            long long nb = base + 4096;
            #pragma unroll
            for (int i = 0; i < 4; i++) nv[i] = g_schunk[nb + off + i * 256];
        }
        #pragma unroll
        for (int i = 0; i < 4; i++) {
            g_sbef[base + off + i * 256] = S[i];
            S[i] = e * S[i] + v[i];
            v[i] = nv[i];
        }
        base += 4096;
    }
}

// ---------------- inter-chunk (tensor-core); C tile copied pre-split ----------------
__global__ __launch_bounds__(256) void k_inter_mma(const float* __restrict__ Dh, int j) {
    __shared__ uint4 sC[1024];
    __shared__ uint4 sST[1024];
    __shared__ float scum[64];

    int c = blockIdx.x, h = blockIdx.y, b = blockIdx.z;
    long long rowb = (long long)b * LP + (long long)c * Q;
    long long sbase = ((long long)(b * NH + h) * NC + c) * 4096;
    int tid = threadIdx.x;

    if (tid < 64)
        scum[tid] = g_cum[(long long)(b * NH + h) * LP + (long long)c * Q + tid];

    {
        const uint4* gC = g_CmS + rowb * 16;
        for (int i = tid; i < 1024; i += 256) sC[i] = gC[i];
    }
    for (int i = tid; i < 1024; i += 256) {
        int slot = i >> 6, row = i & 63;
        int ks = slot >> 2, tg = slot & 3;
        int k0 = ks * 16 + tg * 2;
        float s0 = g_sbef[sbase + (k0)     * 64 + row];
        float s1 = g_sbef[sbase + (k0 + 1) * 64 + row];
        float s2 = g_sbef[sbase + (k0 + 8) * 64 + row];
        float s3 = g_sbef[sbase + (k0 + 9) * 64 + row];
        uint2 sh0 = split_bf16_pair(s0, s1);
        uint2 sh1 = split_bf16_pair(s2, s3);
        sST[i] = make_uint4(sh0.x, sh0.y, sh1.x, sh1.y);
    }
    __syncthreads();

    int warp = tid >> 5, lane = tid & 31;
    int g = lane >> 2, tig = lane & 3;
    int r0 = (warp & 3) * 16, cbn = (warp >> 2) * 32;

    float acc[4][4];
    #pragma unroll
    for (int nt = 0; nt < 4; nt++)
        #pragma unroll
        for (int q = 0; q < 4; q++) acc[nt][q] = 0.f;
    #pragma unroll
    for (int ks = 0; ks < 4; ks++) {
        uint4 fa0 = sC[(r0 + g) * 16 + ks * 4 + tig];
        uint4 fa1 = sC[(r0 + g + 8) * 16 + ks * 4 + tig];
        unsigned ahi[4] = {fa0.x, fa1.x, fa0.z, fa1.z};
        unsigned alo[4] = {fa0.y, fa1.y, fa0.w, fa1.w};
        #pragma unroll
        for (int nt = 0; nt < 4; nt++) {
            uint4 fb = sST[(ks * 4 + tig) * 64 + cbn + nt * 8 + g];
            unsigned bhi[2] = {fb.x, fb.z}, blo[2] = {fb.y, fb.w};
            mma16(acc[nt], alo, bhi);
            mma16(acc[nt], ahi, blo);
            mma16(acc[nt], ahi, bhi);
        }
    }

    float dh = Dh[(2 * b + j) * NH + h];
    #pragma unroll
    for (int nt = 0; nt < 4; nt++) {
        int p = cbn + nt * 8 + 2 * tig;
        #pragma unroll
        for (int hf = 0; hf < 2; hf++) {
            int t = r0 + g + hf * 8;
            float e = __expf(scum[t]);
            long long ydx = (rowb + t) * DI + h * HD + p;
            float2 o = *(float2*)&g_y[ydx];
            float2 xs2 = *(const float2*)&g_xs[ydx];
            o.x += e * acc[nt][hf * 2]     + dh * xs2.x;
            o.y += e * acc[nt][hf * 2 + 1] + dh * xs2.y;
            *(float2*)&g_y[ydx] = o;
        }
    }
}

// ---------------- gate (silu(z)) + RMSNorm -> bf16 in A-layout ----------------
__global__ __launch_bounds__(256) void k_gate(const float* __restrict__ norm_w, int j) {
    int t = blockIdx.x, b = blockIdx.y;
    int lidx = 2 * b + j;
    const float* z = g_zx + ((long long)b * LP + t) * DPROJ;
    const float* yr = g_y + ((long long)b * LP + t) * DI;
    unsigned* yo = g_yB + ((long long)b * LP + t) * 512;
    int tid = threadIdx.x;
    int kt = tid >> 2, jj = tid & 3;
    int k0 = kt * 16 + jj * 2;
    float2 z0 = *(const float2*)&z[k0];
    float2 z1 = *(const float2*)&z[k0 + 8];
    float2 y0 = *(const float2*)&yr[k0];
    float2 y1 = *(const float2*)&yr[k0 + 8];
    float va = y0.x * (z0.x / (1.f + __expf(-z0.x)));
    float vb = y0.y * (z0.y / (1.f + __expf(-z0.y)));
    float vc = y1.x * (z1.x / (1.f + __expf(-z1.x)));
    float vd = y1.y * (z1.y / (1.f + __expf(-z1.y)));
    float ss = va * va + vb * vb + vc * vc + vd * vd;
    float tot = bsum(ss);
    float scale = rsqrtf(tot / (float)DI + 1e-5f);
    float2 n0 = *(const float2*)&norm_w[lidx * DI + k0];
    float2 n1 = *(const float2*)&norm_w[lidx * DI + k0 + 8];
    uint2 packed;
    packed.x = pack_bf16(va * scale * n0.x, vb * scale * n0.y);
    packed.y = pack_bf16(vc * scale * n1.x, vd * scale * n1.y);
    *(uint2*)&yo[kt * 8 + jj * 2] = packed;
}

// ---------------- final LayerNorm: fp32 hn + fragment-layout split hnF ----------------
__global__ __launch_bounds__(256) void k_ln(const float* __restrict__ lnw, const float* __restrict__ lnb) {
    int g = blockIdx.x;
    int b = g / L_TOK, t = g % L_TOK;
    const float* row = g_hcur + ((long long)b * LP + t) * DM;
    int tid = threadIdx.x;
    float2 v = *(const float2*)&row[2 * tid];
    float s = bsum(v.x + v.y);
    float sq = bsum(v.x * v.x + v.y * v.y);
    float mu = s / (float)DM;
    float var = sq / (float)DM - mu * mu;
    float inv = rsqrtf(var + 1e-5f);
    float o0 = (v.x - mu) * inv * lnw[2 * tid]     + lnb[2 * tid];
    float o1 = (v.y - mu) * inv * lnw[2 * tid + 1] + lnb[2 * tid + 1];
    *(float2*)&g_hn[(long long)g * DM + 2 * tid] = make_float2(o0, o1);
    // fragment layout: pair p = tid; kt = p>>3, tig = p&3, hsel = (p>>2)&1
    int p = tid;
    int kt = p >> 3, tg = p & 3, hsel = (p >> 2) & 1;
    uint2* hf = (uint2*)g_hnF;
    hf[(long long)g * 256 + (kt * 4 + tg) * 2 + hsel] = split_bf16_pair(o0, o1);
}

// ---------------- attention scalar score ----------------
__global__ void k_score(const float* __restrict__ w2, const float* __restrict__ b2) {
    int g = blockIdx.x;
    int tid = threadIdx.x;
    float v = g_s1[(long long)g * 128 + tid] * w2[tid];
    v = bsum(v);
    if (tid == 0) g_scoreb[g] = v + b2[0];
}

// ---------------- softmax (+ zero pooled) ----------------
__global__ void k_softmax() {
    const int n = NB * L_TOK;
    __shared__ float red[32];
    __shared__ float s_max, s_sum;
    int tid = threadIdx.x;
    if (tid < DM) g_pooled[tid] = 0.f;
    float m = -1e30f;
    for (int i = tid; i < n; i += 1024) m = fmaxf(m, g_scoreb[i]);
    #pragma unroll
    for (int o = 16; o > 0; o >>= 1) m = fmaxf(m, __shfl_xor_sync(0xffffffffu, m, o));
    if ((tid & 31) == 0) red[tid >> 5] = m;
    __syncthreads();
    if (tid < 32) {
        float v = red[tid];
        #pragma unroll
        for (int o = 16; o > 0; o >>= 1) v = fmaxf(v, __shfl_xor_sync(0xffffffffu, v, o));
        if (tid == 0) s_max = v;
    }
    __syncthreads();
    float m0 = s_max;
    float s = 0.f;
    for (int i = tid; i < n; i += 1024) s += expf(g_scoreb[i] - m0);
    #pragma unroll
    for (int o = 16; o > 0; o >>= 1) s += __shfl_xor_sync(0xffffffffu, s, o);
    if ((tid & 31) == 0) red[tid >> 5] = s;
    __syncthreads();
    if (tid < 32) {
        float v = red[tid];
        #pragma unroll
        for (int o = 16; o > 0; o >>= 1) v += __shfl_xor_sync(0xffffffffu, v, o);
        if (tid == 0) s_sum = v;
    }
    __syncthreads();
    float inv = 1.f / s_sum;
    for (int i = tid; i < n; i += 1024) g_wts[i] = expf(g_scoreb[i] - m0) * inv;
}

// ---------------- pooled ----------------
#define PBLK 120
__global__ __launch_bounds__(256) void k_pooled() {
    const int total = NB * L_TOK;
    int per = (total + PBLK - 1) / PBLK;
    int g0 = blockIdx.x * per;
    int g1 = g0 + per; if (g1 > total) g1 = total;
    int tid = threadIdx.x;
    float a0 = 0.f, a1 = 0.f;
    for (int g = g0; g < g1; g++) {
        float w = g_wts[g];
        float2 v = *(const float2*)&g_hn[(long long)g * DM + 2 * tid];
        a0 = fmaf(w, v.x, a0);
        a1 = fmaf(w, v.y, a1);
    }
    atomicAdd(&g_pooled[2 * tid], a0);
    atomicAdd(&g_pooled[2 * tid + 1], a1);
}

// ---------------- final classifier ----------------
__global__ void k_final(const float* __restrict__ cls_w, const float* __restrict__ cls_b,
                        float* __restrict__ out, int out_size) {
    int tid = threadIdx.x;
    int cls = tid >> 5, lane = tid & 31;
    float acc = 0.f;
    for (int d = lane; d < DM; d += 32) acc += g_pooled[d] * cls_w[cls * DM + d];
    #pragma unroll
    for (int o = 16; o > 0; o >>= 1) acc += __shfl_xor_sync(0xffffffffu, acc, o);
    __shared__ float lg[2];
    if (lane == 0) lg[cls] = acc;
    __syncthreads();
    if (tid == 0) {
        float l0 = lg[0] + cls_b[0], l1 = lg[1] + cls_b[1];
        float m = fmaxf(l0, l1);
        float e0 = expf(l0 - m), e1 = expf(l1 - m);
        float s = e0 + e1;
        out[0] = l0;
        out[1] = l1;
        if (out_size >= 4) { out[2] = e0 / s; out[3] = e1 / s; }
    }
}

// ---------------- launch ----------------
extern "C" void kernel_launch(void* const* d_in, const int* in_sizes, int n_in,
                              void* d_out, int out_size) {
    const float* x        = (const float*)d_in[0];
    const float* fc1_w    = (const float*)d_in[1];
    const float* fc1_b    = (const float*)d_in[2];
    const float* in_proj_w= (const float*)d_in[3];
    const float* conv_w   = (const float*)d_in[4];
    const float* conv_b   = (const float*)d_in[5];
    const float* dt_bias  = (const float*)d_in[6];
    const float* A_log    = (const float*)d_in[7];
    const float* Dh       = (const float*)d_in[8];
    const float* norm_w   = (const float*)d_in[9];
    const float* out_proj_w=(const float*)d_in[10];
    const float* ln_w     = (const float*)d_in[11];
    const float* ln_b     = (const float*)d_in[12];
    const float* attn_w1  = (const float*)d_in[13];
    const float* attn_b1  = (const float*)d_in[14];
    const float* attn_w2  = (const float*)d_in[15];
    const float* attn_b2  = (const float*)d_in[16];
    const float* cls_w    = (const float*)d_in[17];
    const float* cls_b    = (const float*)d_in[18];
    float* out = (float*)d_out;

    void *p_hcur, *p_zx, *p_s1;
    void *p_xF, *p_fc1wF, *p_ipw4, *p_opw4, *p_aw1F, *p_hcurB, *p_yB, *p_hnF;
    cudaGetSymbolAddress(&p_hcur,  g_hcur);
    cudaGetSymbolAddress(&p_zx,    g_zx);
    cudaGetSymbolAddress(&p_s1,    g_s1);
    cudaGetSymbolAddress(&p_xF,    g_xF);
    cudaGetSymbolAddress(&p_fc1wF, g_fc1wF);
    cudaGetSymbolAddress(&p_ipw4,  g_ipw4);
    cudaGetSymbolAddress(&p_opw4,  g_opw4);
    cudaGetSymbolAddress(&p_aw1F,  g_aw1F);
    cudaGetSymbolAddress(&p_hcurB, g_hcurB);
    cudaGetSymbolAddress(&p_yB,    g_yB);
    cudaGetSymbolAddress(&p_hnF,   g_hnF);

    cudaFuncSetAttribute(tgemm3, cudaFuncAttributeMaxDynamicSharedMemorySize, TG3_SMEM);
    cudaFuncSetAttribute(tgemm2, cudaFuncAttributeMaxDynamicSharedMemorySize, TG2_SMEM);
    cudaFuncSetAttribute(k_intra_mma, cudaFuncAttributeMaxDynamicSharedMemorySize, SMEM_INTRA_MMA);

    // 1: merged splits (x, fc1_w, in_proj_w — all fragment layout)
    {
        long long tot = NX4 + NF4 + NW4;
        k_split_all<<<(int)((tot + 255) / 256), 256>>>(x, fc1_w, in_proj_w);
    }
    // 2: fc1 (tgemm3, op=2, aux -> hcurB)
    {
        dim3 grid((DM + 127) / 128, (L_TOK + 127) / 128, 1);
        tgemm3<<<grid, 256, TG3_SMEM>>>((const uint4*)p_xF, (const uint4*)p_fc1wF, fc1_b,
                                        (float*)p_hcur, (unsigned*)p_hcurB,
                                        L_TOK, DM, 512, 2);
    }
    // 3: branch prep + pad zero
    {
        long long tot = (long long)L_TOK * 128 + (long long)NB * (LP - L_TOK) * 128;
        k_prep2<<<(int)((tot + 255) / 256), 256>>>();
    }

    for (int j = 0; j < 2; j++) {
        // 4 (j=0): in_proj <- ncu capture window
        {
            dim3 g1((DPROJ + 127) / 128, (LP + 127) / 128, NB);
            tgemm2<<<g1, 256, TG2_SMEM>>>((const uint2*)p_hcurB, (long long)LP * 128,
                                          (const uint4*)p_ipw4, (long long)DPROJ * 128,
                                          (float*)p_zx, (long long)LP * DPROJ, nullptr,
                                          LP, DPROJ, 256, 0, j);
        }
        k_convfused<<<dim3(NC, NB), 256>>>(conv_w, conv_b, dt_bias, A_log, j);
        {
            long long tot = 2LL * NB * LP * 16;
            k_splitBC<<<(int)((tot + 255) / 256), 256>>>();
        }
        k_intra_mma<<<dim3(NC, NH, NB), 256, SMEM_INTRA_MMA>>>();
        k_rec<<<dim3(NB * NH, 4), 256>>>();
        k_inter_mma<<<dim3(NC, NH, NB), 256>>>(Dh, j);
        k_gate<<<dim3(LP, NB), 256>>>(norm_w, j);
        if (j == 0) {
            long long nu4 = (long long)6 * DM * 256;
            k_splitW<<<(int)((nu4 + 255) / 256), 256>>>(out_proj_w, (uint4*)p_opw4, nu4, 1024);
        }
        {
            dim3 g2((DM + 127) / 128, (LP + 127) / 128, NB);
            tgemm2<<<g2, 256, TG2_SMEM>>>((const uint2*)p_yB, (long long)LP * 256,
                                          (const uint4*)p_opw4, (long long)DM * 256,
                                          (float*)p_hcur, (long long)LP * DM,
                                          (j == 0) ? (unsigned*)p_hcurB : nullptr,
                                          LP, DM, 512, 1, j);
        }
    }

    // final head
    k_ln<<<NB * L_TOK, 256>>>(ln_w, ln_b);
    {
        long long nu4 = 128LL * 128;
        k_splitW<<<(int)((nu4 + 255) / 256), 256>>>(attn_w1, (uint4*)p_aw1F, nu4, 512);
    }
    {
        dim3 ga(1, (NB * L_TOK + 127) / 128, 1);
        tgemm3<<<ga, 256, TG3_SMEM>>>((const uint4*)p_hnF, (const uint4*)p_aw1F, attn_b1,
                                      (float*)p_s1, nullptr,
                                      NB * L_TOK, 128, 256, 3);
    }
    k_score<<<NB * L_TOK, 128>>>(attn_w2, attn_b2);
    k_softmax<<<1, 1024>>>();
    k_pooled<<<PBLK, 256>>>();
    k_final<<<1, 64>>>(cls_w, cls_b, out, out_size);
}